// round 2
// baseline (speedup 1.0000x reference)
#include <cuda_runtime.h>
#include <cstddef>

// ---------------- scratch (no allocs allowed) ----------------
#define O_CAP 100000
static __device__ float g_pooled[(size_t)O_CAP * 128];
static __device__ float g_counts[O_CAP];

#define KC   32     // K-chunk staged in smem
#define PADX 36     // Xs row stride (pad vs 32)
#define PADH 132    // Hs row stride (pad vs 128)

// ================= Kernel A: triple MLP + scatter =================
// block = 128 triples, 256 threads, 8x8 microtile per thread
__global__ __launch_bounds__(256, 2)
void triple_kernel(const float* __restrict__ obj, const float* __restrict__ predi,
                   const int* __restrict__ edges,
                   const float* __restrict__ w1a, const float* __restrict__ b1a,
                   const float* __restrict__ w1b, const float* __restrict__ b1b,
                   float* __restrict__ outP, float* __restrict__ pooled,
                   float* __restrict__ counts, int T)
{
    extern __shared__ float sm[];
    float* Xs = sm;                      // 128 * PADX
    float* Ws = Xs + 128 * PADX;         // KC * 128
    float* Hs = Ws + KC * 128;           // 128 * PADH
    int*   sIdx = (int*)(Hs + 128 * PADH);
    int*   oIdx = sIdx + 128;

    const int tid = threadIdx.x;
    const int tx = tid & 15;             // 16 col groups
    const int ty = tid >> 4;             // 16 row groups
    const int t0 = blockIdx.x * 128;

    if (tid < 128) {
        int t = t0 + tid;
        int s = 0, o = 0;
        if (t < T) {
            s = edges[2 * t];
            o = edges[2 * t + 1];
            atomicAdd(&counts[s], 1.0f);
            atomicAdd(&counts[o], 1.0f);
        }
        sIdx[tid] = s; oIdx[tid] = o;
    }
    __syncthreads();

    float acc[8][8];
#pragma unroll
    for (int i = 0; i < 8; i++)
#pragma unroll
        for (int j = 0; j < 8; j++) acc[i][j] = 0.f;

    // ---------------- GEMM1: X[128,384] @ w1a[384,128] ----------------
    for (int kc = 0; kc < 384; kc += KC) {
        const int seg = kc >> 7;         // 0: obj[s], 1: predi, 2: obj[o]
        const int segoff = kc & 127;
        // stage Xs[128][32] (gathered): 128 rows x 8 float4
#pragma unroll
        for (int p = 0; p < 4; p++) {
            int idx = p * 256 + tid;     // 0..1023
            int r   = idx >> 3;
            int c4  = idx & 7;
            int t   = t0 + r;
            float4 v = make_float4(0.f, 0.f, 0.f, 0.f);
            if (t < T) {
                const float* src;
                if (seg == 0)      src = obj + (size_t)sIdx[r] * 128;
                else if (seg == 1) src = predi + (size_t)t * 128;
                else               src = obj + (size_t)oIdx[r] * 128;
                v = *(const float4*)(src + segoff + c4 * 4);
            }
            *(float4*)(Xs + r * PADX + c4 * 4) = v;
        }
        // stage Ws[32][128]
#pragma unroll
        for (int p = 0; p < 4; p++) {
            int idx = p * 256 + tid;
            int k = idx >> 5, j4 = idx & 31;
            *(float4*)(Ws + k * 128 + j4 * 4) =
                *(const float4*)(w1a + (size_t)(kc + k) * 128 + j4 * 4);
        }
        __syncthreads();
#pragma unroll
        for (int k = 0; k < KC; k++) {
            float4 b0 = *(float4*)(Ws + k * 128 + tx * 4);
            float4 b1 = *(float4*)(Ws + k * 128 + 64 + tx * 4);
            float bb[8] = {b0.x, b0.y, b0.z, b0.w, b1.x, b1.y, b1.z, b1.w};
            float a[8];
#pragma unroll
            for (int i = 0; i < 4; i++) {
                a[i]     = Xs[(ty * 4 + i) * PADX + k];
                a[4 + i] = Xs[(64 + ty * 4 + i) * PADX + k];
            }
#pragma unroll
            for (int i = 0; i < 8; i++)
#pragma unroll
                for (int j = 0; j < 8; j++) acc[i][j] += a[i] * bb[j];
        }
        __syncthreads();
    }

    // bias + relu -> Hs
    {
        float4 q0 = *(const float4*)(b1a + tx * 4);
        float4 q1 = *(const float4*)(b1a + 64 + tx * 4);
        float bb[8] = {q0.x, q0.y, q0.z, q0.w, q1.x, q1.y, q1.z, q1.w};
#pragma unroll
        for (int i = 0; i < 8; i++) {
            int rr = (i < 4) ? (ty * 4 + i) : (64 + ty * 4 + i - 4);
            float4 h0, h1;
            h0.x = fmaxf(acc[i][0] + bb[0], 0.f);
            h0.y = fmaxf(acc[i][1] + bb[1], 0.f);
            h0.z = fmaxf(acc[i][2] + bb[2], 0.f);
            h0.w = fmaxf(acc[i][3] + bb[3], 0.f);
            h1.x = fmaxf(acc[i][4] + bb[4], 0.f);
            h1.y = fmaxf(acc[i][5] + bb[5], 0.f);
            h1.z = fmaxf(acc[i][6] + bb[6], 0.f);
            h1.w = fmaxf(acc[i][7] + bb[7], 0.f);
            *(float4*)(Hs + rr * PADH + tx * 4)      = h0;
            *(float4*)(Hs + rr * PADH + 64 + tx * 4) = h1;
        }
    }
    __syncthreads();

    // ---------------- GEMM2: H[128,128] @ w1b[128,384], 3 N-chunks ----------------
    for (int nc = 0; nc < 3; nc++) {
#pragma unroll
        for (int i = 0; i < 8; i++)
#pragma unroll
            for (int j = 0; j < 8; j++) acc[i][j] = 0.f;

        for (int kc = 0; kc < 128; kc += KC) {
#pragma unroll
            for (int p = 0; p < 4; p++) {
                int idx = p * 256 + tid;
                int k = idx >> 5, j4 = idx & 31;
                *(float4*)(Ws + k * 128 + j4 * 4) =
                    *(const float4*)(w1b + (size_t)(kc + k) * 384 + nc * 128 + j4 * 4);
            }
            __syncthreads();
#pragma unroll
            for (int k = 0; k < KC; k++) {
                float4 b0 = *(float4*)(Ws + k * 128 + tx * 4);
                float4 b1 = *(float4*)(Ws + k * 128 + 64 + tx * 4);
                float bb[8] = {b0.x, b0.y, b0.z, b0.w, b1.x, b1.y, b1.z, b1.w};
                float a[8];
#pragma unroll
                for (int i = 0; i < 4; i++) {
                    a[i]     = Hs[(ty * 4 + i) * PADH + kc + k];
                    a[4 + i] = Hs[(64 + ty * 4 + i) * PADH + kc + k];
                }
#pragma unroll
                for (int i = 0; i < 8; i++)
#pragma unroll
                    for (int j = 0; j < 8; j++) acc[i][j] += a[i] * bb[j];
            }
            __syncthreads();
        }

        float4 q0 = *(const float4*)(b1b + nc * 128 + tx * 4);
        float4 q1 = *(const float4*)(b1b + nc * 128 + 64 + tx * 4);
        float bb[8] = {q0.x, q0.y, q0.z, q0.w, q1.x, q1.y, q1.z, q1.w};

        if (nc == 1) {
            // new_p -> out
#pragma unroll
            for (int i = 0; i < 8; i++) {
                int rr = (i < 4) ? (ty * 4 + i) : (64 + ty * 4 + i - 4);
                int t = t0 + rr;
                if (t < T) {
                    float4 v0, v1;
                    v0.x = fmaxf(acc[i][0] + bb[0], 0.f);
                    v0.y = fmaxf(acc[i][1] + bb[1], 0.f);
                    v0.z = fmaxf(acc[i][2] + bb[2], 0.f);
                    v0.w = fmaxf(acc[i][3] + bb[3], 0.f);
                    v1.x = fmaxf(acc[i][4] + bb[4], 0.f);
                    v1.y = fmaxf(acc[i][5] + bb[5], 0.f);
                    v1.z = fmaxf(acc[i][6] + bb[6], 0.f);
                    v1.w = fmaxf(acc[i][7] + bb[7], 0.f);
                    *(float4*)(outP + (size_t)t * 128 + tx * 4)      = v0;
                    *(float4*)(outP + (size_t)t * 128 + 64 + tx * 4) = v1;
                }
            }
        } else {
            const int* ridx = (nc == 0) ? sIdx : oIdx;
#pragma unroll
            for (int i = 0; i < 8; i++) {
                int rr = (i < 4) ? (ty * 4 + i) : (64 + ty * 4 + i - 4);
                int t = t0 + rr;
                if (t < T) {
                    float* dst = pooled + (size_t)ridx[rr] * 128;
#pragma unroll
                    for (int j = 0; j < 8; j++) {
                        int jj = (j < 4) ? (tx * 4 + j) : (64 + tx * 4 + j - 4);
                        atomicAdd(dst + jj, fmaxf(acc[i][j] + bb[j], 0.f));
                    }
                }
            }
        }
    }
}

// ================= Kernel B: pooled/count -> object MLP =================
__global__ __launch_bounds__(256, 2)
void obj_kernel(const float* __restrict__ w2a, const float* __restrict__ b2a,
                const float* __restrict__ w2b, const float* __restrict__ b2b,
                const float* __restrict__ pooled, const float* __restrict__ counts,
                float* __restrict__ outO, int O)
{
    extern __shared__ float sm[];
    float* Xs   = sm;                    // 128 * PADH
    float* Ws   = Xs + 128 * PADH;       // KC * 128
    float* invc = Ws + KC * 128;         // 128

    const int tid = threadIdx.x;
    const int tx = tid & 15;
    const int ty = tid >> 4;
    const int o0 = blockIdx.x * 128;

    if (tid < 128) {
        int o = o0 + tid;
        float c = (o < O) ? counts[o] : 1.f;
        c = fminf(fmaxf(c, 1.f), 1000.f);
        invc[tid] = 1.f / c;
    }
    __syncthreads();

    // Xs = pooled * invc : 128 rows x 32 float4  (FIXED: full 128-wide tile)
#pragma unroll
    for (int p = 0; p < 16; p++) {
        int idx = p * 256 + tid;         // 0..4095
        int r = idx >> 5, c4 = idx & 31;
        int o = o0 + r;
        float4 v = make_float4(0.f, 0.f, 0.f, 0.f);
        if (o < O) v = *(const float4*)(pooled + (size_t)o * 128 + c4 * 4);
        float s = invc[r];
        v.x *= s; v.y *= s; v.z *= s; v.w *= s;
        *(float4*)(Xs + r * PADH + c4 * 4) = v;
    }
    __syncthreads();

    float acc[8][8];
    for (int layer = 0; layer < 2; layer++) {
        const float* W = (layer == 0) ? w2a : w2b;
        const float* B = (layer == 0) ? b2a : b2b;
#pragma unroll
        for (int i = 0; i < 8; i++)
#pragma unroll
            for (int j = 0; j < 8; j++) acc[i][j] = 0.f;

        for (int kc = 0; kc < 128; kc += KC) {
#pragma unroll
            for (int p = 0; p < 4; p++) {
                int idx = p * 256 + tid;
                int k = idx >> 5, j4 = idx & 31;
                *(float4*)(Ws + k * 128 + j4 * 4) =
                    *(const float4*)(W + (size_t)(kc + k) * 128 + j4 * 4);
            }
            __syncthreads();
#pragma unroll
            for (int k = 0; k < KC; k++) {
                float4 b0 = *(float4*)(Ws + k * 128 + tx * 4);
                float4 b1 = *(float4*)(Ws + k * 128 + 64 + tx * 4);
                float bb[8] = {b0.x, b0.y, b0.z, b0.w, b1.x, b1.y, b1.z, b1.w};
                float a[8];
#pragma unroll
                for (int i = 0; i < 4; i++) {
                    a[i]     = Xs[(ty * 4 + i) * PADH + kc + k];
                    a[4 + i] = Xs[(64 + ty * 4 + i) * PADH + kc + k];
                }
#pragma unroll
                for (int i = 0; i < 8; i++)
#pragma unroll
                    for (int j = 0; j < 8; j++) acc[i][j] += a[i] * bb[j];
            }
            __syncthreads();
        }

        float4 q0 = *(const float4*)(B + tx * 4);
        float4 q1 = *(const float4*)(B + 64 + tx * 4);
        float bb[8] = {q0.x, q0.y, q0.z, q0.w, q1.x, q1.y, q1.z, q1.w};

        if (layer == 0) {
            // h -> Xs (all reads of Xs completed by trailing sync above)
#pragma unroll
            for (int i = 0; i < 8; i++) {
                int rr = (i < 4) ? (ty * 4 + i) : (64 + ty * 4 + i - 4);
                float4 h0, h1;
                h0.x = fmaxf(acc[i][0] + bb[0], 0.f);
                h0.y = fmaxf(acc[i][1] + bb[1], 0.f);
                h0.z = fmaxf(acc[i][2] + bb[2], 0.f);
                h0.w = fmaxf(acc[i][3] + bb[3], 0.f);
                h1.x = fmaxf(acc[i][4] + bb[4], 0.f);
                h1.y = fmaxf(acc[i][5] + bb[5], 0.f);
                h1.z = fmaxf(acc[i][6] + bb[6], 0.f);
                h1.w = fmaxf(acc[i][7] + bb[7], 0.f);
                *(float4*)(Xs + rr * PADH + tx * 4)      = h0;
                *(float4*)(Xs + rr * PADH + 64 + tx * 4) = h1;
            }
            __syncthreads();
        } else {
#pragma unroll
            for (int i = 0; i < 8; i++) {
                int rr = (i < 4) ? (ty * 4 + i) : (64 + ty * 4 + i - 4);
                int o = o0 + rr;
                if (o < O) {
                    float4 v0, v1;
                    v0.x = fmaxf(acc[i][0] + bb[0], 0.f);
                    v0.y = fmaxf(acc[i][1] + bb[1], 0.f);
                    v0.z = fmaxf(acc[i][2] + bb[2], 0.f);
                    v0.w = fmaxf(acc[i][3] + bb[3], 0.f);
                    v1.x = fmaxf(acc[i][4] + bb[4], 0.f);
                    v1.y = fmaxf(acc[i][5] + bb[5], 0.f);
                    v1.z = fmaxf(acc[i][6] + bb[6], 0.f);
                    v1.w = fmaxf(acc[i][7] + bb[7], 0.f);
                    *(float4*)(outO + (size_t)o * 128 + tx * 4)      = v0;
                    *(float4*)(outO + (size_t)o * 128 + 64 + tx * 4) = v1;
                }
            }
        }
    }
}

// ================= launch =================
extern "C" void kernel_launch(void* const* d_in, const int* in_sizes, int n_in,
                              void* d_out, int out_size)
{
    const float* obj   = (const float*)d_in[0];
    const float* predi = (const float*)d_in[1];
    const int*   edges = (const int*)d_in[2];
    const float* w1a   = (const float*)d_in[3];
    const float* b1a   = (const float*)d_in[4];
    const float* w1b   = (const float*)d_in[5];
    const float* b1b   = (const float*)d_in[6];
    const float* w2a   = (const float*)d_in[7];
    const float* b2a   = (const float*)d_in[8];
    const float* w2b   = (const float*)d_in[9];
    const float* b2b   = (const float*)d_in[10];

    const int O = in_sizes[0] / 128;
    const int T = in_sizes[1] / 128;

    float* outO = (float*)d_out;
    float* outP = outO + (size_t)O * 128;

    float* pooled = nullptr;
    float* counts = nullptr;
    cudaGetSymbolAddress((void**)&pooled, g_pooled);
    cudaGetSymbolAddress((void**)&counts, g_counts);

    cudaMemsetAsync(pooled, 0, (size_t)O * 128 * sizeof(float));
    cudaMemsetAsync(counts, 0, (size_t)O * sizeof(float));

    const size_t smA = (size_t)(128 * PADX + KC * 128 + 128 * PADH) * sizeof(float)
                     + 256 * sizeof(int);
    const size_t smB = (size_t)(128 * PADH + KC * 128 + 128) * sizeof(float);

    cudaFuncSetAttribute(triple_kernel, cudaFuncAttributeMaxDynamicSharedMemorySize, (int)smA);
    cudaFuncSetAttribute(obj_kernel,    cudaFuncAttributeMaxDynamicSharedMemorySize, (int)smB);

    triple_kernel<<<(T + 127) / 128, 256, smA>>>(obj, predi, edges,
                                                 w1a, b1a, w1b, b1b,
                                                 outP, pooled, counts, T);
    obj_kernel<<<(O + 127) / 128, 256, smB>>>(w2a, b2a, w2b, b2b,
                                              pooled, counts, outO, O);
}

// round 3
// speedup vs baseline: 2.7175x; 2.7175x over previous
#include <cuda_runtime.h>
#include <cstddef>

// ---------------- scratch (no allocs allowed) ----------------
#define O_CAP 100000
static __device__ float g_pooled[(size_t)O_CAP * 128];
static __device__ float g_counts[O_CAP];

#define PADA 36     // A-tile row stride (32-wide k chunk + 4)
#define PADW 136    // W-tile row stride (128-wide j + 8)
#define PADH 132    // H / Xs full-K row stride (128 + 4)

// ---------------- helpers ----------------
__device__ __forceinline__ unsigned f2tf(float x) {
    unsigned u;
    asm("cvt.rna.tf32.f32 %0, %1;" : "=r"(u) : "f"(x));
    return u;
}

__device__ __forceinline__ void mma_tf32(float c[4], const unsigned a[4], const unsigned b[2]) {
    asm volatile(
        "mma.sync.aligned.m16n8k8.row.col.f32.tf32.tf32.f32 "
        "{%0,%1,%2,%3},{%4,%5,%6,%7},{%8,%9},{%0,%1,%2,%3};\n"
        : "+f"(c[0]), "+f"(c[1]), "+f"(c[2]), "+f"(c[3])
        : "r"(a[0]), "r"(a[1]), "r"(a[2]), "r"(a[3]),
          "r"(b[0]), "r"(b[1]));
}

__device__ __forceinline__ void red_add_v2(float* p, float x, float y) {
    asm volatile("red.global.add.v2.f32 [%0], {%1,%2};" :: "l"(p), "f"(x), "f"(y) : "memory");
}

// ================= Kernel A: triple MLP (tf32 MMA) + scatter =================
// block = 128 triples, 256 threads (8 warps), warp tile 32x64
__global__ __launch_bounds__(256, 2)
void triple_kernel(const float* __restrict__ obj, const float* __restrict__ predi,
                   const int* __restrict__ edges,
                   const float* __restrict__ w1a, const float* __restrict__ b1a,
                   const float* __restrict__ w1b, const float* __restrict__ b1b,
                   float* __restrict__ outP, float* __restrict__ pooled,
                   float* __restrict__ counts, int T)
{
    extern __shared__ float sm[];
    float* Xs = sm;                        // 128 * PADA
    float* Ws = Xs + 128 * PADA;           // 32 * PADW
    float* Hs = Ws + 32 * PADW;            // 128 * PADH
    int*   sIdx = (int*)(Hs + 128 * PADH);
    int*   oIdx = sIdx + 128;

    const unsigned* Xu = (const unsigned*)Xs;
    const unsigned* Wu = (const unsigned*)Ws;
    const unsigned* Hu = (const unsigned*)Hs;

    const int tid  = threadIdx.x;
    const int lane = tid & 31;
    const int g    = lane >> 2;            // 0..7
    const int tg   = lane & 3;             // 0..3
    const int w    = tid >> 5;             // 0..7
    const int R0   = (w >> 1) * 32;        // warp row base
    const int C0   = (w & 1) * 64;         // warp col base
    const int t0   = blockIdx.x * 128;

    if (tid < 128) {
        int t = t0 + tid;
        int s = 0, o = 0;
        if (t < T) {
            s = edges[2 * t];
            o = edges[2 * t + 1];
            atomicAdd(&counts[s], 1.0f);
            atomicAdd(&counts[o], 1.0f);
        }
        sIdx[tid] = s; oIdx[tid] = o;
    }
    __syncthreads();

    float acc[2][8][4];
#pragma unroll
    for (int mi = 0; mi < 2; mi++)
#pragma unroll
        for (int ni = 0; ni < 8; ni++)
#pragma unroll
            for (int q = 0; q < 4; q++) acc[mi][ni][q] = 0.f;

    // ---------------- GEMM1: X[128,384] @ w1a[384,128] ----------------
    for (int kc = 0; kc < 384; kc += 32) {
        const int seg = kc >> 7;            // 0: obj[s], 1: predi, 2: obj[o]
        const int segoff = kc & 127;
        // stage Xs[128][32] gathered + cvt tf32
#pragma unroll
        for (int p = 0; p < 4; p++) {
            int idx = p * 256 + tid;        // 0..1023
            int r = idx >> 3, c4 = idx & 7;
            int t = t0 + r;
            float4 v = make_float4(0.f, 0.f, 0.f, 0.f);
            if (t < T) {
                const float* src;
                if (seg == 0)      src = obj + (size_t)sIdx[r] * 128;
                else if (seg == 1) src = predi + (size_t)t * 128;
                else               src = obj + (size_t)oIdx[r] * 128;
                v = *(const float4*)(src + segoff + c4 * 4);
            }
            uint4 u; u.x = f2tf(v.x); u.y = f2tf(v.y); u.z = f2tf(v.z); u.w = f2tf(v.w);
            *(uint4*)(Xs + r * PADA + c4 * 4) = u;
        }
        // stage Ws[32][128] + cvt tf32
#pragma unroll
        for (int p = 0; p < 4; p++) {
            int idx = p * 256 + tid;
            int k = idx >> 5, j4 = idx & 31;
            float4 v = *(const float4*)(w1a + (size_t)(kc + k) * 128 + j4 * 4);
            uint4 u; u.x = f2tf(v.x); u.y = f2tf(v.y); u.z = f2tf(v.z); u.w = f2tf(v.w);
            *(uint4*)(Ws + k * PADW + j4 * 4) = u;
        }
        __syncthreads();
#pragma unroll
        for (int ks = 0; ks < 4; ks++) {
            const int k0 = ks * 8;
            unsigned a[2][4], b[8][2];
#pragma unroll
            for (int mi = 0; mi < 2; mi++) {
                int r = R0 + mi * 16 + g;
                a[mi][0] = Xu[r * PADA + k0 + tg];
                a[mi][1] = Xu[(r + 8) * PADA + k0 + tg];
                a[mi][2] = Xu[r * PADA + k0 + tg + 4];
                a[mi][3] = Xu[(r + 8) * PADA + k0 + tg + 4];
            }
#pragma unroll
            for (int ni = 0; ni < 8; ni++) {
                int c = C0 + ni * 8 + g;
                b[ni][0] = Wu[(k0 + tg) * PADW + c];
                b[ni][1] = Wu[(k0 + tg + 4) * PADW + c];
            }
#pragma unroll
            for (int mi = 0; mi < 2; mi++)
#pragma unroll
                for (int ni = 0; ni < 8; ni++)
                    mma_tf32(acc[mi][ni], a[mi], b[ni]);
        }
        __syncthreads();
    }

    // bias + relu -> Hs (tf32)
#pragma unroll
    for (int mi = 0; mi < 2; mi++)
#pragma unroll
        for (int ni = 0; ni < 8; ni++) {
            int r = R0 + mi * 16 + g;
            int c = C0 + ni * 8 + 2 * tg;
            float bx = b1a[c], by = b1a[c + 1];
            float h00 = fmaxf(acc[mi][ni][0] + bx, 0.f);
            float h01 = fmaxf(acc[mi][ni][1] + by, 0.f);
            float h10 = fmaxf(acc[mi][ni][2] + bx, 0.f);
            float h11 = fmaxf(acc[mi][ni][3] + by, 0.f);
            uint2 u0 = make_uint2(f2tf(h00), f2tf(h01));
            uint2 u1 = make_uint2(f2tf(h10), f2tf(h11));
            *(uint2*)(Hs + r * PADH + c)       = u0;
            *(uint2*)(Hs + (r + 8) * PADH + c) = u1;
        }
    __syncthreads();

    // ---------------- GEMM2: H[128,128] @ w1b[128,384], 3 N-chunks ----------------
    for (int nc = 0; nc < 3; nc++) {
#pragma unroll
        for (int mi = 0; mi < 2; mi++)
#pragma unroll
            for (int ni = 0; ni < 8; ni++)
#pragma unroll
                for (int q = 0; q < 4; q++) acc[mi][ni][q] = 0.f;

        for (int kc = 0; kc < 128; kc += 32) {
#pragma unroll
            for (int p = 0; p < 4; p++) {
                int idx = p * 256 + tid;
                int k = idx >> 5, j4 = idx & 31;
                float4 v = *(const float4*)(w1b + (size_t)(kc + k) * 384 + nc * 128 + j4 * 4);
                uint4 u; u.x = f2tf(v.x); u.y = f2tf(v.y); u.z = f2tf(v.z); u.w = f2tf(v.w);
                *(uint4*)(Ws + k * PADW + j4 * 4) = u;
            }
            __syncthreads();
#pragma unroll
            for (int ks = 0; ks < 4; ks++) {
                const int k0 = kc + ks * 8;
                unsigned a[2][4], b[8][2];
#pragma unroll
                for (int mi = 0; mi < 2; mi++) {
                    int r = R0 + mi * 16 + g;
                    a[mi][0] = Hu[r * PADH + k0 + tg];
                    a[mi][1] = Hu[(r + 8) * PADH + k0 + tg];
                    a[mi][2] = Hu[r * PADH + k0 + tg + 4];
                    a[mi][3] = Hu[(r + 8) * PADH + k0 + tg + 4];
                }
#pragma unroll
                for (int ni = 0; ni < 8; ni++) {
                    int c = C0 + ni * 8 + g;
                    b[ni][0] = Wu[(ks * 8 + tg) * PADW + c];
                    b[ni][1] = Wu[(ks * 8 + tg + 4) * PADW + c];
                }
#pragma unroll
                for (int mi = 0; mi < 2; mi++)
#pragma unroll
                    for (int ni = 0; ni < 8; ni++)
                        mma_tf32(acc[mi][ni], a[mi], b[ni]);
            }
            __syncthreads();
        }

        if (nc == 1) {
            // new_p -> outP
#pragma unroll
            for (int mi = 0; mi < 2; mi++)
#pragma unroll
                for (int ni = 0; ni < 8; ni++) {
                    int r = R0 + mi * 16 + g;
                    int c = C0 + ni * 8 + 2 * tg;
                    float bx = b1b[128 + c], by = b1b[128 + c + 1];
                    int ta = t0 + r, tb = t0 + r + 8;
                    if (ta < T) {
                        float2 v = make_float2(fmaxf(acc[mi][ni][0] + bx, 0.f),
                                               fmaxf(acc[mi][ni][1] + by, 0.f));
                        *(float2*)(outP + (size_t)ta * 128 + c) = v;
                    }
                    if (tb < T) {
                        float2 v = make_float2(fmaxf(acc[mi][ni][2] + bx, 0.f),
                                               fmaxf(acc[mi][ni][3] + by, 0.f));
                        *(float2*)(outP + (size_t)tb * 128 + c) = v;
                    }
                }
        } else {
            const int* ridx = (nc == 0) ? sIdx : oIdx;
            const int boff = (nc == 0) ? 0 : 256;
#pragma unroll
            for (int mi = 0; mi < 2; mi++)
#pragma unroll
                for (int ni = 0; ni < 8; ni++) {
                    int r = R0 + mi * 16 + g;
                    int c = C0 + ni * 8 + 2 * tg;
                    float bx = b1b[boff + c], by = b1b[boff + c + 1];
                    int ta = t0 + r, tb = t0 + r + 8;
                    if (ta < T) {
                        red_add_v2(pooled + (size_t)ridx[r] * 128 + c,
                                   fmaxf(acc[mi][ni][0] + bx, 0.f),
                                   fmaxf(acc[mi][ni][1] + by, 0.f));
                    }
                    if (tb < T) {
                        red_add_v2(pooled + (size_t)ridx[r + 8] * 128 + c,
                                   fmaxf(acc[mi][ni][2] + bx, 0.f),
                                   fmaxf(acc[mi][ni][3] + by, 0.f));
                    }
                }
        }
    }
}

// ================= Kernel B: pooled/count -> object MLP (tf32 MMA) =================
__global__ __launch_bounds__(256, 2)
void obj_kernel(const float* __restrict__ w2a, const float* __restrict__ b2a,
                const float* __restrict__ w2b, const float* __restrict__ b2b,
                const float* __restrict__ pooled, const float* __restrict__ counts,
                float* __restrict__ outO, int O)
{
    extern __shared__ float sm[];
    float* Xs   = sm;                      // 128 * PADH (tf32)
    float* Ws   = Xs + 128 * PADH;         // 32 * PADW
    float* invc = Ws + 32 * PADW;          // 128

    const unsigned* Xu = (const unsigned*)Xs;
    const unsigned* Wu = (const unsigned*)Ws;

    const int tid  = threadIdx.x;
    const int lane = tid & 31;
    const int g    = lane >> 2;
    const int tg   = lane & 3;
    const int w    = tid >> 5;
    const int R0   = (w >> 1) * 32;
    const int C0   = (w & 1) * 64;
    const int o0   = blockIdx.x * 128;

    if (tid < 128) {
        int o = o0 + tid;
        float c = (o < O) ? counts[o] : 1.f;
        c = fminf(fmaxf(c, 1.f), 1000.f);
        invc[tid] = 1.f / c;
    }
    __syncthreads();

    // Xs = tf32(pooled * invc) : 128 rows x 32 float4
#pragma unroll
    for (int p = 0; p < 16; p++) {
        int idx = p * 256 + tid;
        int r = idx >> 5, c4 = idx & 31;
        int o = o0 + r;
        float4 v = make_float4(0.f, 0.f, 0.f, 0.f);
        if (o < O) v = *(const float4*)(pooled + (size_t)o * 128 + c4 * 4);
        float s = invc[r];
        uint4 u; u.x = f2tf(v.x * s); u.y = f2tf(v.y * s); u.z = f2tf(v.z * s); u.w = f2tf(v.w * s);
        *(uint4*)(Xs + r * PADH + c4 * 4) = u;
    }
    __syncthreads();

    float acc[2][8][4];
    for (int layer = 0; layer < 2; layer++) {
        const float* W = (layer == 0) ? w2a : w2b;
        const float* B = (layer == 0) ? b2a : b2b;
#pragma unroll
        for (int mi = 0; mi < 2; mi++)
#pragma unroll
            for (int ni = 0; ni < 8; ni++)
#pragma unroll
                for (int q = 0; q < 4; q++) acc[mi][ni][q] = 0.f;

        for (int kc = 0; kc < 128; kc += 32) {
#pragma unroll
            for (int p = 0; p < 4; p++) {
                int idx = p * 256 + tid;
                int k = idx >> 5, j4 = idx & 31;
                float4 v = *(const float4*)(W + (size_t)(kc + k) * 128 + j4 * 4);
                uint4 u; u.x = f2tf(v.x); u.y = f2tf(v.y); u.z = f2tf(v.z); u.w = f2tf(v.w);
                *(uint4*)(Ws + k * PADW + j4 * 4) = u;
            }
            __syncthreads();
#pragma unroll
            for (int ks = 0; ks < 4; ks++) {
                const int k0 = kc + ks * 8;
                unsigned a[2][4], b[8][2];
#pragma unroll
                for (int mi = 0; mi < 2; mi++) {
                    int r = R0 + mi * 16 + g;
                    a[mi][0] = Xu[r * PADH + k0 + tg];
                    a[mi][1] = Xu[(r + 8) * PADH + k0 + tg];
                    a[mi][2] = Xu[r * PADH + k0 + tg + 4];
                    a[mi][3] = Xu[(r + 8) * PADH + k0 + tg + 4];
                }
#pragma unroll
                for (int ni = 0; ni < 8; ni++) {
                    int c = C0 + ni * 8 + g;
                    b[ni][0] = Wu[(ks * 8 + tg) * PADW + c];
                    b[ni][1] = Wu[(ks * 8 + tg + 4) * PADW + c];
                }
#pragma unroll
                for (int mi = 0; mi < 2; mi++)
#pragma unroll
                    for (int ni = 0; ni < 8; ni++)
                        mma_tf32(acc[mi][ni], a[mi], b[ni]);
            }
            __syncthreads();
        }

        if (layer == 0) {
            // relu -> back into Xs (tf32)
#pragma unroll
            for (int mi = 0; mi < 2; mi++)
#pragma unroll
                for (int ni = 0; ni < 8; ni++) {
                    int r = R0 + mi * 16 + g;
                    int c = C0 + ni * 8 + 2 * tg;
                    float bx = B[c], by = B[c + 1];
                    uint2 u0 = make_uint2(f2tf(fmaxf(acc[mi][ni][0] + bx, 0.f)),
                                          f2tf(fmaxf(acc[mi][ni][1] + by, 0.f)));
                    uint2 u1 = make_uint2(f2tf(fmaxf(acc[mi][ni][2] + bx, 0.f)),
                                          f2tf(fmaxf(acc[mi][ni][3] + by, 0.f)));
                    *(uint2*)(Xs + r * PADH + c)       = u0;
                    *(uint2*)(Xs + (r + 8) * PADH + c) = u1;
                }
            __syncthreads();
        } else {
#pragma unroll
            for (int mi = 0; mi < 2; mi++)
#pragma unroll
                for (int ni = 0; ni < 8; ni++) {
                    int r = R0 + mi * 16 + g;
                    int c = C0 + ni * 8 + 2 * tg;
                    float bx = B[c], by = B[c + 1];
                    int oa = o0 + r, ob = o0 + r + 8;
                    if (oa < O) {
                        float2 v = make_float2(fmaxf(acc[mi][ni][0] + bx, 0.f),
                                               fmaxf(acc[mi][ni][1] + by, 0.f));
                        *(float2*)(outO + (size_t)oa * 128 + c) = v;
                    }
                    if (ob < O) {
                        float2 v = make_float2(fmaxf(acc[mi][ni][2] + bx, 0.f),
                                               fmaxf(acc[mi][ni][3] + by, 0.f));
                        *(float2*)(outO + (size_t)ob * 128 + c) = v;
                    }
                }
        }
    }
}

// ================= launch =================
extern "C" void kernel_launch(void* const* d_in, const int* in_sizes, int n_in,
                              void* d_out, int out_size)
{
    const float* obj   = (const float*)d_in[0];
    const float* predi = (const float*)d_in[1];
    const int*   edges = (const int*)d_in[2];
    const float* w1a   = (const float*)d_in[3];
    const float* b1a   = (const float*)d_in[4];
    const float* w1b   = (const float*)d_in[5];
    const float* b1b   = (const float*)d_in[6];
    const float* w2a   = (const float*)d_in[7];
    const float* b2a   = (const float*)d_in[8];
    const float* w2b   = (const float*)d_in[9];
    const float* b2b   = (const float*)d_in[10];

    const int O = in_sizes[0] / 128;
    const int T = in_sizes[1] / 128;

    float* outO = (float*)d_out;
    float* outP = outO + (size_t)O * 128;

    float* pooled = nullptr;
    float* counts = nullptr;
    cudaGetSymbolAddress((void**)&pooled, g_pooled);
    cudaGetSymbolAddress((void**)&counts, g_counts);

    cudaMemsetAsync(pooled, 0, (size_t)O * 128 * sizeof(float));
    cudaMemsetAsync(counts, 0, (size_t)O * sizeof(float));

    const size_t smA = (size_t)(128 * PADA + 32 * PADW + 128 * PADH) * sizeof(float)
                     + 256 * sizeof(int);
    const size_t smB = (size_t)(128 * PADH + 32 * PADW + 128) * sizeof(float);

    cudaFuncSetAttribute(triple_kernel, cudaFuncAttributeMaxDynamicSharedMemorySize, (int)smA);
    cudaFuncSetAttribute(obj_kernel,    cudaFuncAttributeMaxDynamicSharedMemorySize, (int)smB);

    triple_kernel<<<(T + 127) / 128, 256, smA>>>(obj, predi, edges,
                                                 w1a, b1a, w1b, b1b,
                                                 outP, pooled, counts, T);
    obj_kernel<<<(O + 127) / 128, 256, smB>>>(w2a, b2a, w2b, b2b,
                                              pooled, counts, outO, O);
}

// round 4
// speedup vs baseline: 3.1654x; 1.1648x over previous
#include <cuda_runtime.h>
#include <cstddef>

// ---------------- scratch (no allocs allowed) ----------------
#define O_CAP 100000
static __device__ float g_pooled[(size_t)O_CAP * 128];
static __device__ float g_counts[O_CAP];
// proj[o][0:128] = obj[o] @ w1a[0:128,:], proj[o][128:256] = obj[o] @ w1a[256:384,:]
static __device__ float g_proj[(size_t)O_CAP * 256];

#define PADW 136    // W-tile row stride (128 + 8) -> conflict-free B reads
#define PADH 132    // A-tile row stride (128 + 4) -> conflict-free A reads

// ---------------- helpers ----------------
__device__ __forceinline__ unsigned f2tf(float x) {
    unsigned u;
    asm("cvt.rna.tf32.f32 %0, %1;" : "=r"(u) : "f"(x));
    return u;
}

__device__ __forceinline__ void mma_tf32(float c[4], const unsigned a[4], const unsigned b[2]) {
    asm volatile(
        "mma.sync.aligned.m16n8k8.row.col.f32.tf32.tf32.f32 "
        "{%0,%1,%2,%3},{%4,%5,%6,%7},{%8,%9},{%0,%1,%2,%3};\n"
        : "+f"(c[0]), "+f"(c[1]), "+f"(c[2]), "+f"(c[3])
        : "r"(a[0]), "r"(a[1]), "r"(a[2]), "r"(a[3]),
          "r"(b[0]), "r"(b[1]));
}

__device__ __forceinline__ void red_add_v2(float* p, float x, float y) {
    asm volatile("red.global.add.v2.f32 [%0], {%1,%2};" :: "l"(p), "f"(x), "f"(y) : "memory");
}

// ================= Kernel P: proj = obj @ {w1a_top, w1a_bot} =================
__global__ __launch_bounds__(256, 2)
void proj_kernel(const float* __restrict__ obj, const float* __restrict__ w1a,
                 float* __restrict__ proj, int O)
{
    extern __shared__ float sm[];
    float* Xs = sm;                         // 128 * PADH
    float* Ws = Xs + 128 * PADH;            // 2 * 32 * PADW

    const unsigned* Xu = (const unsigned*)Xs;

    const int tid  = threadIdx.x;
    const int lane = tid & 31;
    const int g    = lane >> 2;
    const int tg   = lane & 3;
    const int w    = tid >> 5;
    const int R0   = (w >> 1) * 32;
    const int C0   = (w & 1) * 64;
    const int o0   = blockIdx.x * 128;

    // stage A = tf32(obj tile), full K=128
#pragma unroll
    for (int p = 0; p < 16; p++) {
        int idx = p * 256 + tid;
        int r = idx >> 5, c4 = idx & 31;
        int o = o0 + r;
        float4 v = make_float4(0.f, 0.f, 0.f, 0.f);
        if (o < O) v = *(const float4*)(obj + (size_t)o * 128 + c4 * 4);
        uint4 u; u.x = f2tf(v.x); u.y = f2tf(v.y); u.z = f2tf(v.z); u.w = f2tf(v.w);
        *(uint4*)(Xs + r * PADH + c4 * 4) = u;
    }

    auto stageW = [&](float* dst, const float* src) {
#pragma unroll
        for (int p = 0; p < 4; p++) {
            int idx = p * 256 + tid;
            int k = idx >> 5, j4 = idx & 31;
            float4 v = *(const float4*)(src + (size_t)k * 128 + j4 * 4);
            uint4 u; u.x = f2tf(v.x); u.y = f2tf(v.y); u.z = f2tf(v.z); u.w = f2tf(v.w);
            *(uint4*)(dst + k * PADW + j4 * 4) = u;
        }
    };

    // chunks 0..7: m = ch>>2 (0: rows 0..127, 1: rows 256..383), kc = (ch&3)*32
    stageW(Ws, w1a);                         // chunk 0: m=0, kc=0
    __syncthreads();

    float acc[2][8][4];
    for (int ch = 0; ch < 8; ch++) {
        const int kc = (ch & 3) * 32;
        if (ch < 7) {
            int m2 = (ch + 1) >> 2, kc2 = ((ch + 1) & 3) * 32;
            stageW(Ws + ((ch + 1) & 1) * 32 * PADW,
                   w1a + (size_t)(m2 * 256 + kc2) * 128);
        }
        if ((ch & 3) == 0) {
#pragma unroll
            for (int mi = 0; mi < 2; mi++)
#pragma unroll
                for (int ni = 0; ni < 8; ni++)
#pragma unroll
                    for (int q = 0; q < 4; q++) acc[mi][ni][q] = 0.f;
        }
        const unsigned* Wu = (const unsigned*)(Ws + (ch & 1) * 32 * PADW);
#pragma unroll
        for (int ks = 0; ks < 4; ks++) {
            const int k0 = kc + ks * 8;
            unsigned a[2][4], b[8][2];
#pragma unroll
            for (int mi = 0; mi < 2; mi++) {
                int r = R0 + mi * 16 + g;
                a[mi][0] = Xu[r * PADH + k0 + tg];
                a[mi][1] = Xu[(r + 8) * PADH + k0 + tg];
                a[mi][2] = Xu[r * PADH + k0 + tg + 4];
                a[mi][3] = Xu[(r + 8) * PADH + k0 + tg + 4];
            }
#pragma unroll
            for (int ni = 0; ni < 8; ni++) {
                int c = C0 + ni * 8 + g;
                b[ni][0] = Wu[(ks * 8 + tg) * PADW + c];
                b[ni][1] = Wu[(ks * 8 + tg + 4) * PADW + c];
            }
#pragma unroll
            for (int mi = 0; mi < 2; mi++)
#pragma unroll
                for (int ni = 0; ni < 8; ni++)
                    mma_tf32(acc[mi][ni], a[mi], b[ni]);
        }
        if ((ch & 3) == 3) {
            const int m = ch >> 2;
#pragma unroll
            for (int mi = 0; mi < 2; mi++) {
                int ra = R0 + mi * 16 + g;
                int oa = o0 + ra, ob = oa + 8;
#pragma unroll
                for (int ni = 0; ni < 8; ni++) {
                    int c = C0 + ni * 8 + 2 * tg;
                    if (oa < O)
                        *(float2*)(proj + (size_t)oa * 256 + m * 128 + c) =
                            make_float2(acc[mi][ni][0], acc[mi][ni][1]);
                    if (ob < O)
                        *(float2*)(proj + (size_t)ob * 256 + m * 128 + c) =
                            make_float2(acc[mi][ni][2], acc[mi][ni][3]);
                }
            }
        }
        __syncthreads();
    }
}

// ================= Kernel A: triple MLP (tf32 MMA) + scatter =================
// GEMM1: predi[128,128] @ w1a_mid[128,128]; epilogue adds gathered proj rows.
__global__ __launch_bounds__(256, 2)
void triple_kernel(const float* __restrict__ predi, const int* __restrict__ edges,
                   const float* __restrict__ w1a, const float* __restrict__ b1a,
                   const float* __restrict__ w1b, const float* __restrict__ b1b,
                   const float* __restrict__ proj,
                   float* __restrict__ outP, float* __restrict__ pooled,
                   float* __restrict__ counts, int T)
{
    extern __shared__ float sm[];
    float* XH = sm;                          // 128 * PADH : A for GEMM1, then H for GEMM2
    float* Ws = XH + 128 * PADH;             // 2 * 32 * PADW
    int*   sIdx = (int*)(Ws + 2 * 32 * PADW);
    int*   oIdx = sIdx + 128;

    const unsigned* Xu = (const unsigned*)XH;

    const int tid  = threadIdx.x;
    const int lane = tid & 31;
    const int g    = lane >> 2;
    const int tg   = lane & 3;
    const int w    = tid >> 5;
    const int R0   = (w >> 1) * 32;
    const int C0   = (w & 1) * 64;
    const int t0   = blockIdx.x * 128;

    if (tid < 128) {
        int t = t0 + tid;
        int s = 0, o = 0;
        if (t < T) {
            s = edges[2 * t];
            o = edges[2 * t + 1];
            atomicAdd(&counts[s], 1.0f);
            atomicAdd(&counts[o], 1.0f);
        }
        sIdx[tid] = s; oIdx[tid] = o;
    }

    // stage A = tf32(predi tile), coalesced, full K=128
#pragma unroll
    for (int p = 0; p < 16; p++) {
        int idx = p * 256 + tid;
        int r = idx >> 5, c4 = idx & 31;
        int t = t0 + r;
        float4 v = make_float4(0.f, 0.f, 0.f, 0.f);
        if (t < T) v = *(const float4*)(predi + (size_t)t * 128 + c4 * 4);
        uint4 u; u.x = f2tf(v.x); u.y = f2tf(v.y); u.z = f2tf(v.z); u.w = f2tf(v.w);
        *(uint4*)(XH + r * PADH + c4 * 4) = u;
    }

    auto stageW = [&](float* dst, const float* src, int ld) {
#pragma unroll
        for (int p = 0; p < 4; p++) {
            int idx = p * 256 + tid;
            int k = idx >> 5, j4 = idx & 31;
            float4 v = *(const float4*)(src + (size_t)k * ld + j4 * 4);
            uint4 u; u.x = f2tf(v.x); u.y = f2tf(v.y); u.z = f2tf(v.z); u.w = f2tf(v.w);
            *(uint4*)(dst + k * PADW + j4 * 4) = u;
        }
    };

    const float* w1a_mid = w1a + 128 * 128;  // rows 128..255

    float acc[2][8][4];
#pragma unroll
    for (int mi = 0; mi < 2; mi++)
#pragma unroll
        for (int ni = 0; ni < 8; ni++)
#pragma unroll
            for (int q = 0; q < 4; q++) acc[mi][ni][q] = 0.f;

    // ---------------- GEMM1: 4 chunks, double-buffered W ----------------
    stageW(Ws, w1a_mid, 128);
    __syncthreads();
    for (int ch = 0; ch < 4; ch++) {
        if (ch < 3)
            stageW(Ws + ((ch + 1) & 1) * 32 * PADW, w1a_mid + (size_t)(ch + 1) * 32 * 128, 128);
        const unsigned* Wu = (const unsigned*)(Ws + (ch & 1) * 32 * PADW);
#pragma unroll
        for (int ks = 0; ks < 4; ks++) {
            const int k0 = ch * 32 + ks * 8;
            unsigned a[2][4], b[8][2];
#pragma unroll
            for (int mi = 0; mi < 2; mi++) {
                int r = R0 + mi * 16 + g;
                a[mi][0] = Xu[r * PADH + k0 + tg];
                a[mi][1] = Xu[(r + 8) * PADH + k0 + tg];
                a[mi][2] = Xu[r * PADH + k0 + tg + 4];
                a[mi][3] = Xu[(r + 8) * PADH + k0 + tg + 4];
            }
#pragma unroll
            for (int ni = 0; ni < 8; ni++) {
                int c = C0 + ni * 8 + g;
                b[ni][0] = Wu[(ks * 8 + tg) * PADW + c];
                b[ni][1] = Wu[(ks * 8 + tg + 4) * PADW + c];
            }
#pragma unroll
            for (int mi = 0; mi < 2; mi++)
#pragma unroll
                for (int ni = 0; ni < 8; ni++)
                    mma_tf32(acc[mi][ni], a[mi], b[ni]);
        }
        __syncthreads();
    }

    // epilogue: h = relu(acc + b1a + proj_s + proj_o) -> XH (tf32)
#pragma unroll
    for (int mi = 0; mi < 2; mi++) {
        int ra = R0 + mi * 16 + g;
        int rb = ra + 8;
        const float* psA = proj + (size_t)sIdx[ra] * 256;
        const float* poA = proj + (size_t)oIdx[ra] * 256 + 128;
        const float* psB = proj + (size_t)sIdx[rb] * 256;
        const float* poB = proj + (size_t)oIdx[rb] * 256 + 128;
#pragma unroll
        for (int ni = 0; ni < 8; ni++) {
            int c = C0 + ni * 8 + 2 * tg;
            float bx = b1a[c], by = b1a[c + 1];
            float2 sa = *(const float2*)(psA + c);
            float2 oa = *(const float2*)(poA + c);
            float2 sb = *(const float2*)(psB + c);
            float2 ob = *(const float2*)(poB + c);
            uint2 u0 = make_uint2(
                f2tf(fmaxf(acc[mi][ni][0] + bx + sa.x + oa.x, 0.f)),
                f2tf(fmaxf(acc[mi][ni][1] + by + sa.y + oa.y, 0.f)));
            uint2 u1 = make_uint2(
                f2tf(fmaxf(acc[mi][ni][2] + bx + sb.x + ob.x, 0.f)),
                f2tf(fmaxf(acc[mi][ni][3] + by + sb.y + ob.y, 0.f)));
            *(uint2*)(XH + ra * PADH + c) = u0;
            *(uint2*)(XH + rb * PADH + c) = u1;
        }
    }

    // ---------------- GEMM2: 12 chunks (3 nc x 4 kc), double-buffered ----------------
    stageW(Ws, w1b, 384);                    // chunk 0: nc=0, kc=0
    __syncthreads();
    for (int i = 0; i < 12; i++) {
        const int nc = i >> 2;
        const int kc = (i & 3) * 32;
        if (i < 11) {
            int nc2 = (i + 1) >> 2, kc2 = ((i + 1) & 3) * 32;
            stageW(Ws + ((i + 1) & 1) * 32 * PADW,
                   w1b + (size_t)kc2 * 384 + nc2 * 128, 384);
        }
        if ((i & 3) == 0) {
#pragma unroll
            for (int mi = 0; mi < 2; mi++)
#pragma unroll
                for (int ni = 0; ni < 8; ni++)
#pragma unroll
                    for (int q = 0; q < 4; q++) acc[mi][ni][q] = 0.f;
        }
        const unsigned* Wu = (const unsigned*)(Ws + (i & 1) * 32 * PADW);
#pragma unroll
        for (int ks = 0; ks < 4; ks++) {
            const int k0 = kc + ks * 8;
            unsigned a[2][4], b[8][2];
#pragma unroll
            for (int mi = 0; mi < 2; mi++) {
                int r = R0 + mi * 16 + g;
                a[mi][0] = Xu[r * PADH + k0 + tg];
                a[mi][1] = Xu[(r + 8) * PADH + k0 + tg];
                a[mi][2] = Xu[r * PADH + k0 + tg + 4];
                a[mi][3] = Xu[(r + 8) * PADH + k0 + tg + 4];
            }
#pragma unroll
            for (int ni = 0; ni < 8; ni++) {
                int c = C0 + ni * 8 + g;
                b[ni][0] = Wu[(ks * 8 + tg) * PADW + c];
                b[ni][1] = Wu[(ks * 8 + tg + 4) * PADW + c];
            }
#pragma unroll
            for (int mi = 0; mi < 2; mi++)
#pragma unroll
                for (int ni = 0; ni < 8; ni++)
                    mma_tf32(acc[mi][ni], a[mi], b[ni]);
        }
        if ((i & 3) == 3) {
            if (nc == 1) {
#pragma unroll
                for (int mi = 0; mi < 2; mi++)
#pragma unroll
                    for (int ni = 0; ni < 8; ni++) {
                        int r = R0 + mi * 16 + g;
                        int c = C0 + ni * 8 + 2 * tg;
                        float bx = b1b[128 + c], by = b1b[128 + c + 1];
                        int ta = t0 + r, tb = ta + 8;
                        if (ta < T)
                            *(float2*)(outP + (size_t)ta * 128 + c) =
                                make_float2(fmaxf(acc[mi][ni][0] + bx, 0.f),
                                            fmaxf(acc[mi][ni][1] + by, 0.f));
                        if (tb < T)
                            *(float2*)(outP + (size_t)tb * 128 + c) =
                                make_float2(fmaxf(acc[mi][ni][2] + bx, 0.f),
                                            fmaxf(acc[mi][ni][3] + by, 0.f));
                    }
            } else {
                const int* ridx = (nc == 0) ? sIdx : oIdx;
                const int boff = nc * 128;
#pragma unroll
                for (int mi = 0; mi < 2; mi++)
#pragma unroll
                    for (int ni = 0; ni < 8; ni++) {
                        int r = R0 + mi * 16 + g;
                        int c = C0 + ni * 8 + 2 * tg;
                        float bx = b1b[boff + c], by = b1b[boff + c + 1];
                        int ta = t0 + r, tb = ta + 8;
                        if (ta < T)
                            red_add_v2(pooled + (size_t)ridx[r] * 128 + c,
                                       fmaxf(acc[mi][ni][0] + bx, 0.f),
                                       fmaxf(acc[mi][ni][1] + by, 0.f));
                        if (tb < T)
                            red_add_v2(pooled + (size_t)ridx[r + 8] * 128 + c,
                                       fmaxf(acc[mi][ni][2] + bx, 0.f),
                                       fmaxf(acc[mi][ni][3] + by, 0.f));
                    }
            }
        }
        __syncthreads();
    }
}

// ================= Kernel B: pooled/count -> object MLP (tf32 MMA) =================
__global__ __launch_bounds__(256, 2)
void obj_kernel(const float* __restrict__ w2a, const float* __restrict__ b2a,
                const float* __restrict__ w2b, const float* __restrict__ b2b,
                const float* __restrict__ pooled, const float* __restrict__ counts,
                float* __restrict__ outO, int O)
{
    extern __shared__ float sm[];
    float* Xs   = sm;                      // 128 * PADH (tf32)
    float* Ws   = Xs + 128 * PADH;         // 32 * PADW
    float* invc = Ws + 32 * PADW;          // 128

    const unsigned* Xu = (const unsigned*)Xs;
    const unsigned* Wu = (const unsigned*)Ws;

    const int tid  = threadIdx.x;
    const int lane = tid & 31;
    const int g    = lane >> 2;
    const int tg   = lane & 3;
    const int w    = tid >> 5;
    const int R0   = (w >> 1) * 32;
    const int C0   = (w & 1) * 64;
    const int o0   = blockIdx.x * 128;

    if (tid < 128) {
        int o = o0 + tid;
        float c = (o < O) ? counts[o] : 1.f;
        c = fminf(fmaxf(c, 1.f), 1000.f);
        invc[tid] = 1.f / c;
    }
    __syncthreads();

#pragma unroll
    for (int p = 0; p < 16; p++) {
        int idx = p * 256 + tid;
        int r = idx >> 5, c4 = idx & 31;
        int o = o0 + r;
        float4 v = make_float4(0.f, 0.f, 0.f, 0.f);
        if (o < O) v = *(const float4*)(pooled + (size_t)o * 128 + c4 * 4);
        float s = invc[r];
        uint4 u; u.x = f2tf(v.x * s); u.y = f2tf(v.y * s); u.z = f2tf(v.z * s); u.w = f2tf(v.w * s);
        *(uint4*)(Xs + r * PADH + c4 * 4) = u;
    }
    __syncthreads();

    float acc[2][8][4];
    for (int layer = 0; layer < 2; layer++) {
        const float* W = (layer == 0) ? w2a : w2b;
        const float* B = (layer == 0) ? b2a : b2b;
#pragma unroll
        for (int mi = 0; mi < 2; mi++)
#pragma unroll
            for (int ni = 0; ni < 8; ni++)
#pragma unroll
                for (int q = 0; q < 4; q++) acc[mi][ni][q] = 0.f;

        for (int kc = 0; kc < 128; kc += 32) {
#pragma unroll
            for (int p = 0; p < 4; p++) {
                int idx = p * 256 + tid;
                int k = idx >> 5, j4 = idx & 31;
                float4 v = *(const float4*)(W + (size_t)(kc + k) * 128 + j4 * 4);
                uint4 u; u.x = f2tf(v.x); u.y = f2tf(v.y); u.z = f2tf(v.z); u.w = f2tf(v.w);
                *(uint4*)(Ws + k * PADW + j4 * 4) = u;
            }
            __syncthreads();
#pragma unroll
            for (int ks = 0; ks < 4; ks++) {
                const int k0 = kc + ks * 8;
                unsigned a[2][4], b[8][2];
#pragma unroll
                for (int mi = 0; mi < 2; mi++) {
                    int r = R0 + mi * 16 + g;
                    a[mi][0] = Xu[r * PADH + k0 + tg];
                    a[mi][1] = Xu[(r + 8) * PADH + k0 + tg];
                    a[mi][2] = Xu[r * PADH + k0 + tg + 4];
                    a[mi][3] = Xu[(r + 8) * PADH + k0 + tg + 4];
                }
#pragma unroll
                for (int ni = 0; ni < 8; ni++) {
                    int c = C0 + ni * 8 + g;
                    b[ni][0] = Wu[(ks * 8 + tg) * PADW + c];
                    b[ni][1] = Wu[(ks * 8 + tg + 4) * PADW + c];
                }
#pragma unroll
                for (int mi = 0; mi < 2; mi++)
#pragma unroll
                    for (int ni = 0; ni < 8; ni++)
                        mma_tf32(acc[mi][ni], a[mi], b[ni]);
            }
            __syncthreads();
        }

        if (layer == 0) {
#pragma unroll
            for (int mi = 0; mi < 2; mi++)
#pragma unroll
                for (int ni = 0; ni < 8; ni++) {
                    int r = R0 + mi * 16 + g;
                    int c = C0 + ni * 8 + 2 * tg;
                    float bx = B[c], by = B[c + 1];
                    uint2 u0 = make_uint2(f2tf(fmaxf(acc[mi][ni][0] + bx, 0.f)),
                                          f2tf(fmaxf(acc[mi][ni][1] + by, 0.f)));
                    uint2 u1 = make_uint2(f2tf(fmaxf(acc[mi][ni][2] + bx, 0.f)),
                                          f2tf(fmaxf(acc[mi][ni][3] + by, 0.f)));
                    *(uint2*)(Xs + r * PADH + c)       = u0;
                    *(uint2*)(Xs + (r + 8) * PADH + c) = u1;
                }
            __syncthreads();
        } else {
#pragma unroll
            for (int mi = 0; mi < 2; mi++)
#pragma unroll
                for (int ni = 0; ni < 8; ni++) {
                    int r = R0 + mi * 16 + g;
                    int c = C0 + ni * 8 + 2 * tg;
                    float bx = B[c], by = B[c + 1];
                    int oa = o0 + r, ob = o0 + r + 8;
                    if (oa < O)
                        *(float2*)(outO + (size_t)oa * 128 + c) =
                            make_float2(fmaxf(acc[mi][ni][0] + bx, 0.f),
                                        fmaxf(acc[mi][ni][1] + by, 0.f));
                    if (ob < O)
                        *(float2*)(outO + (size_t)ob * 128 + c) =
                            make_float2(fmaxf(acc[mi][ni][2] + bx, 0.f),
                                        fmaxf(acc[mi][ni][3] + by, 0.f));
                }
        }
    }
}

// ================= launch =================
extern "C" void kernel_launch(void* const* d_in, const int* in_sizes, int n_in,
                              void* d_out, int out_size)
{
    const float* obj   = (const float*)d_in[0];
    const float* predi = (const float*)d_in[1];
    const int*   edges = (const int*)d_in[2];
    const float* w1a   = (const float*)d_in[3];
    const float* b1a   = (const float*)d_in[4];
    const float* w1b   = (const float*)d_in[5];
    const float* b1b   = (const float*)d_in[6];
    const float* w2a   = (const float*)d_in[7];
    const float* b2a   = (const float*)d_in[8];
    const float* w2b   = (const float*)d_in[9];
    const float* b2b   = (const float*)d_in[10];

    const int O = in_sizes[0] / 128;
    const int T = in_sizes[1] / 128;

    float* outO = (float*)d_out;
    float* outP = outO + (size_t)O * 128;

    float* pooled = nullptr;
    float* counts = nullptr;
    float* proj   = nullptr;
    cudaGetSymbolAddress((void**)&pooled, g_pooled);
    cudaGetSymbolAddress((void**)&counts, g_counts);
    cudaGetSymbolAddress((void**)&proj,   g_proj);

    cudaMemsetAsync(pooled, 0, (size_t)O * 128 * sizeof(float));
    cudaMemsetAsync(counts, 0, (size_t)O * sizeof(float));

    const size_t smP = (size_t)(128 * PADH + 2 * 32 * PADW) * sizeof(float);
    const size_t smA = smP + 256 * sizeof(int);
    const size_t smB = (size_t)(128 * PADH + 32 * PADW + 128) * sizeof(float);

    cudaFuncSetAttribute(proj_kernel,   cudaFuncAttributeMaxDynamicSharedMemorySize, (int)smP);
    cudaFuncSetAttribute(triple_kernel, cudaFuncAttributeMaxDynamicSharedMemorySize, (int)smA);
    cudaFuncSetAttribute(obj_kernel,    cudaFuncAttributeMaxDynamicSharedMemorySize, (int)smB);

    proj_kernel<<<(O + 127) / 128, 256, smP>>>(obj, w1a, proj, O);
    triple_kernel<<<(T + 127) / 128, 256, smA>>>(predi, edges,
                                                 w1a, b1a, w1b, b1b, proj,
                                                 outP, pooled, counts, T);
    obj_kernel<<<(O + 127) / 128, 256, smB>>>(w2a, b2a, w2b, b2b,
                                              pooled, counts, outO, O);
}

// round 6
// speedup vs baseline: 3.3079x; 1.0450x over previous
#include <cuda_runtime.h>
#include <cstdint>
#include <cstddef>

// ---------------- scratch (no allocs allowed) ----------------
#define O_CAP 100000
static __device__ float g_pooled[(size_t)O_CAP * 128];
static __device__ float g_counts[O_CAP];
static __device__ float g_proj[(size_t)O_CAP * 256];

#define PADW 136    // W-tile row stride (conflict-free B frag reads)
#define PADH 132    // A/H row stride (conflict-free A frag reads)

// ---------------- helpers ----------------
__device__ __forceinline__ unsigned f2tf(float x) {
    unsigned u;
    asm("cvt.rna.tf32.f32 %0, %1;" : "=r"(u) : "f"(x));
    return u;
}
__device__ __forceinline__ void mma_tf32(float c[4], const unsigned a[4], const unsigned b[2]) {
    asm volatile(
        "mma.sync.aligned.m16n8k8.row.col.f32.tf32.tf32.f32 "
        "{%0,%1,%2,%3},{%4,%5,%6,%7},{%8,%9},{%0,%1,%2,%3};\n"
        : "+f"(c[0]), "+f"(c[1]), "+f"(c[2]), "+f"(c[3])
        : "r"(a[0]), "r"(a[1]), "r"(a[2]), "r"(a[3]), "r"(b[0]), "r"(b[1]));
}
__device__ __forceinline__ void red_add_v2(float* p, float x, float y) {
    asm volatile("red.global.add.v2.f32 [%0], {%1,%2};" :: "l"(p), "f"(x), "f"(y) : "memory");
}

// ================= Kernel A: triple MLP, 128 threads, warp tile m64n64 =================
__global__ __launch_bounds__(128, 2)
void triple_kernel(const float* __restrict__ predi, const int* __restrict__ edges,
                   const float* __restrict__ w1a, const float* __restrict__ b1a,
                   const float* __restrict__ w1b, const float* __restrict__ b1b,
                   const float* __restrict__ proj,
                   float* __restrict__ outP, float* __restrict__ pooled,
                   float* __restrict__ counts, int T)
{
    extern __shared__ float sm[];
    float* XH = sm;                          // 128 * PADH (A for GEMM1, then H)
    float* Ws = XH + 128 * PADH;             // 2 * 32 * PADW
    int*   sIdx = (int*)(Ws + 2 * 32 * PADW);
    int*   oIdx = sIdx + 128;

    const unsigned* Xu = (const unsigned*)XH;

    const int tid  = threadIdx.x;            // 0..127
    const int lane = tid & 31;
    const int g    = lane >> 2;               // 0..7
    const int tg   = lane & 3;                // 0..3
    const int w    = tid >> 5;                // 0..3
    const int R0   = (w >> 1) * 64;           // warp row base (m64)
    const int C0   = (w & 1) * 64;            // warp col base (n64)
    const int t0   = blockIdx.x * 128;

    {
        int t = t0 + tid;
        int s = 0, o = 0;
        if (t < T) {
            s = edges[2 * t];
            o = edges[2 * t + 1];
            atomicAdd(&counts[s], 1.0f);
            atomicAdd(&counts[o], 1.0f);
        }
        sIdx[tid] = s; oIdx[tid] = o;
    }

    // stage A = tf32(predi tile), full K=128: 4096 float4 / 128 thr = 32 iters
#pragma unroll
    for (int p = 0; p < 32; p++) {
        int idx = p * 128 + tid;
        int r = idx >> 5, c4 = idx & 31;
        int t = t0 + r;
        float4 v = make_float4(0.f, 0.f, 0.f, 0.f);
        if (t < T) v = *(const float4*)(predi + (size_t)t * 128 + c4 * 4);
        uint4 u; u.x = f2tf(v.x); u.y = f2tf(v.y); u.z = f2tf(v.z); u.w = f2tf(v.w);
        *(uint4*)(XH + r * PADH + c4 * 4) = u;
    }

    auto stageW = [&](int buf, const float* src, int ld) {
        float* dst = Ws + buf * 32 * PADW;
#pragma unroll
        for (int p = 0; p < 8; p++) {
            int idx = p * 128 + tid;
            int k = idx >> 5, j4 = idx & 31;
            float4 v = *(const float4*)(src + (size_t)k * ld + j4 * 4);
            uint4 u; u.x = f2tf(v.x); u.y = f2tf(v.y); u.z = f2tf(v.z); u.w = f2tf(v.w);
            *(uint4*)(dst + k * PADW + j4 * 4) = u;
        }
    };

    const float* w1a_mid = w1a + 128 * 128;

    float acc[4][8][4];
#pragma unroll
    for (int mi = 0; mi < 4; mi++)
#pragma unroll
        for (int ni = 0; ni < 8; ni++)
#pragma unroll
            for (int q = 0; q < 4; q++) acc[mi][ni][q] = 0.f;

    // ---------------- GEMM1: predi @ w1a_mid, 4 K-chunks, dbl-buffered W ----------------
    stageW(0, w1a_mid, 128);
    __syncthreads();
    for (int ch = 0; ch < 4; ch++) {
        if (ch < 3) stageW((ch + 1) & 1, w1a_mid + (size_t)(ch + 1) * 32 * 128, 128);
        const unsigned* Wu = (const unsigned*)(Ws + (ch & 1) * 32 * PADW);
#pragma unroll
        for (int ks = 0; ks < 4; ks++) {
            const int k0 = ch * 32 + ks * 8;
            unsigned a[4][4], b[8][2];
#pragma unroll
            for (int mi = 0; mi < 4; mi++) {
                int r = R0 + mi * 16 + g;
                a[mi][0] = Xu[r * PADH + k0 + tg];
                a[mi][1] = Xu[(r + 8) * PADH + k0 + tg];
                a[mi][2] = Xu[r * PADH + k0 + tg + 4];
                a[mi][3] = Xu[(r + 8) * PADH + k0 + tg + 4];
            }
#pragma unroll
            for (int ni = 0; ni < 8; ni++) {
                int c = C0 + ni * 8 + g;
                b[ni][0] = Wu[(ks * 8 + tg) * PADW + c];
                b[ni][1] = Wu[(ks * 8 + tg + 4) * PADW + c];
            }
#pragma unroll
            for (int mi = 0; mi < 4; mi++)
#pragma unroll
                for (int ni = 0; ni < 8; ni++)
                    mma_tf32(acc[mi][ni], a[mi], b[ni]);
        }
        __syncthreads();
    }

    // epilogue: H = tf32(relu(acc + b1a + proj_s + proj_o)) -> XH
#pragma unroll
    for (int mi = 0; mi < 4; mi++) {
        int ra = R0 + mi * 16 + g;
        int rb = ra + 8;
        const float* psA = proj + (size_t)sIdx[ra] * 256;
        const float* poA = proj + (size_t)oIdx[ra] * 256 + 128;
        const float* psB = proj + (size_t)sIdx[rb] * 256;
        const float* poB = proj + (size_t)oIdx[rb] * 256 + 128;
#pragma unroll
        for (int ni = 0; ni < 8; ni++) {
            int c = C0 + ni * 8 + 2 * tg;
            float bx = b1a[c], by = b1a[c + 1];
            float2 sa = *(const float2*)(psA + c);
            float2 oa = *(const float2*)(poA + c);
            float2 sb = *(const float2*)(psB + c);
            float2 ob = *(const float2*)(poB + c);
            uint2 u0 = make_uint2(
                f2tf(fmaxf(acc[mi][ni][0] + bx + sa.x + oa.x, 0.f)),
                f2tf(fmaxf(acc[mi][ni][1] + by + sa.y + oa.y, 0.f)));
            uint2 u1 = make_uint2(
                f2tf(fmaxf(acc[mi][ni][2] + bx + sb.x + ob.x, 0.f)),
                f2tf(fmaxf(acc[mi][ni][3] + by + sb.y + ob.y, 0.f)));
            *(uint2*)(XH + ra * PADH + c) = u0;
            *(uint2*)(XH + rb * PADH + c) = u1;
        }
    }

    // ---------------- GEMM2: H @ w1b, 12 chunks (3 nc x 4 kc), dbl-buffered ----------------
    __syncthreads();          // H fully written before any warp reads it
    stageW(0, w1b, 384);
    __syncthreads();
    for (int i = 0; i < 12; i++) {
        const int nc = i >> 2;
        const int kc = (i & 3) * 32;
        if (i < 11) {
            int nc2 = (i + 1) >> 2, kc2 = ((i + 1) & 3) * 32;
            stageW((i + 1) & 1, w1b + (size_t)kc2 * 384 + nc2 * 128, 384);
        }
        if ((i & 3) == 0) {
#pragma unroll
            for (int mi = 0; mi < 4; mi++)
#pragma unroll
                for (int ni = 0; ni < 8; ni++)
#pragma unroll
                    for (int q = 0; q < 4; q++) acc[mi][ni][q] = 0.f;
        }
        const unsigned* Wu = (const unsigned*)(Ws + (i & 1) * 32 * PADW);
#pragma unroll
        for (int ks = 0; ks < 4; ks++) {
            const int k0 = kc + ks * 8;
            unsigned a[4][4], b[8][2];
#pragma unroll
            for (int mi = 0; mi < 4; mi++) {
                int r = R0 + mi * 16 + g;
                a[mi][0] = Xu[r * PADH + k0 + tg];
                a[mi][1] = Xu[(r + 8) * PADH + k0 + tg];
                a[mi][2] = Xu[r * PADH + k0 + tg + 4];
                a[mi][3] = Xu[(r + 8) * PADH + k0 + tg + 4];
            }
#pragma unroll
            for (int ni = 0; ni < 8; ni++) {
                int c = C0 + ni * 8 + g;
                b[ni][0] = Wu[(ks * 8 + tg) * PADW + c];
                b[ni][1] = Wu[(ks * 8 + tg + 4) * PADW + c];
            }
#pragma unroll
            for (int mi = 0; mi < 4; mi++)
#pragma unroll
                for (int ni = 0; ni < 8; ni++)
                    mma_tf32(acc[mi][ni], a[mi], b[ni]);
        }
        if ((i & 3) == 3) {
            if (nc == 1) {
#pragma unroll
                for (int mi = 0; mi < 4; mi++)
#pragma unroll
                    for (int ni = 0; ni < 8; ni++) {
                        int r = R0 + mi * 16 + g;
                        int c = C0 + ni * 8 + 2 * tg;
                        float bx = b1b[128 + c], by = b1b[128 + c + 1];
                        int ta = t0 + r, tb = ta + 8;
                        if (ta < T)
                            *(float2*)(outP + (size_t)ta * 128 + c) =
                                make_float2(fmaxf(acc[mi][ni][0] + bx, 0.f),
                                            fmaxf(acc[mi][ni][1] + by, 0.f));
                        if (tb < T)
                            *(float2*)(outP + (size_t)tb * 128 + c) =
                                make_float2(fmaxf(acc[mi][ni][2] + bx, 0.f),
                                            fmaxf(acc[mi][ni][3] + by, 0.f));
                    }
            } else {
                const int* ridx = (nc == 0) ? sIdx : oIdx;
                const int boff = nc * 128;
#pragma unroll
                for (int mi = 0; mi < 4; mi++)
#pragma unroll
                    for (int ni = 0; ni < 8; ni++) {
                        int r = R0 + mi * 16 + g;
                        int c = C0 + ni * 8 + 2 * tg;
                        float bx = b1b[boff + c], by = b1b[boff + c + 1];
                        int ta = t0 + r, tb = ta + 8;
                        if (ta < T)
                            red_add_v2(pooled + (size_t)ridx[r] * 128 + c,
                                       fmaxf(acc[mi][ni][0] + bx, 0.f),
                                       fmaxf(acc[mi][ni][1] + by, 0.f));
                        if (tb < T)
                            red_add_v2(pooled + (size_t)ridx[r + 8] * 128 + c,
                                       fmaxf(acc[mi][ni][2] + bx, 0.f),
                                       fmaxf(acc[mi][ni][3] + by, 0.f));
                    }
            }
        }
        __syncthreads();
    }
}

// ================= Kernel P: proj = obj @ {w1a_top, w1a_bot} (unchanged) =================
__global__ __launch_bounds__(256, 2)
void proj_kernel(const float* __restrict__ obj, const float* __restrict__ w1a,
                 float* __restrict__ proj, int O)
{
    extern __shared__ float sm[];
    float* Xs = sm;
    float* Ws = Xs + 128 * PADH;
    const unsigned* Xu = (const unsigned*)Xs;

    const int tid = threadIdx.x;
    const int lane = tid & 31;
    const int g = lane >> 2, tg = lane & 3;
    const int w = tid >> 5;
    const int R0 = (w >> 1) * 32, C0 = (w & 1) * 64;
    const int o0 = blockIdx.x * 128;

#pragma unroll
    for (int p = 0; p < 16; p++) {
        int idx = p * 256 + tid;
        int r = idx >> 5, c4 = idx & 31;
        int o = o0 + r;
        float4 v = make_float4(0.f, 0.f, 0.f, 0.f);
        if (o < O) v = *(const float4*)(obj + (size_t)o * 128 + c4 * 4);
        uint4 u; u.x = f2tf(v.x); u.y = f2tf(v.y); u.z = f2tf(v.z); u.w = f2tf(v.w);
        *(uint4*)(Xs + r * PADH + c4 * 4) = u;
    }

    auto stageW = [&](float* dst, const float* src) {
#pragma unroll
        for (int p = 0; p < 4; p++) {
            int idx = p * 256 + tid;
            int k = idx >> 5, j4 = idx & 31;
            float4 v = *(const float4*)(src + (size_t)k * 128 + j4 * 4);
            uint4 u; u.x = f2tf(v.x); u.y = f2tf(v.y); u.z = f2tf(v.z); u.w = f2tf(v.w);
            *(uint4*)(dst + k * PADW + j4 * 4) = u;
        }
    };

    stageW(Ws, w1a);
    __syncthreads();

    float acc[2][8][4];
    for (int ch = 0; ch < 8; ch++) {
        const int kc = (ch & 3) * 32;
        if (ch < 7) {
            int m2 = (ch + 1) >> 2, kc2 = ((ch + 1) & 3) * 32;
            stageW(Ws + ((ch + 1) & 1) * 32 * PADW, w1a + (size_t)(m2 * 256 + kc2) * 128);
        }
        if ((ch & 3) == 0) {
#pragma unroll
            for (int mi = 0; mi < 2; mi++)
#pragma unroll
                for (int ni = 0; ni < 8; ni++)
#pragma unroll
                    for (int q = 0; q < 4; q++) acc[mi][ni][q] = 0.f;
        }
        const unsigned* Wu = (const unsigned*)(Ws + (ch & 1) * 32 * PADW);
#pragma unroll
        for (int ks = 0; ks < 4; ks++) {
            const int k0 = kc + ks * 8;
            unsigned a[2][4], b[8][2];
#pragma unroll
            for (int mi = 0; mi < 2; mi++) {
                int r = R0 + mi * 16 + g;
                a[mi][0] = Xu[r * PADH + k0 + tg];
                a[mi][1] = Xu[(r + 8) * PADH + k0 + tg];
                a[mi][2] = Xu[r * PADH + k0 + tg + 4];
                a[mi][3] = Xu[(r + 8) * PADH + k0 + tg + 4];
            }
#pragma unroll
            for (int ni = 0; ni < 8; ni++) {
                int c = C0 + ni * 8 + g;
                b[ni][0] = Wu[(ks * 8 + tg) * PADW + c];
                b[ni][1] = Wu[(ks * 8 + tg + 4) * PADW + c];
            }
#pragma unroll
            for (int mi = 0; mi < 2; mi++)
#pragma unroll
                for (int ni = 0; ni < 8; ni++)
                    mma_tf32(acc[mi][ni], a[mi], b[ni]);
        }
        if ((ch & 3) == 3) {
            const int m = ch >> 2;
#pragma unroll
            for (int mi = 0; mi < 2; mi++) {
                int ra = R0 + mi * 16 + g;
                int oa = o0 + ra, ob = oa + 8;
#pragma unroll
                for (int ni = 0; ni < 8; ni++) {
                    int c = C0 + ni * 8 + 2 * tg;
                    if (oa < O)
                        *(float2*)(proj + (size_t)oa * 256 + m * 128 + c) =
                            make_float2(acc[mi][ni][0], acc[mi][ni][1]);
                    if (ob < O)
                        *(float2*)(proj + (size_t)ob * 256 + m * 128 + c) =
                            make_float2(acc[mi][ni][2], acc[mi][ni][3]);
                }
            }
        }
        __syncthreads();
    }
}

// ================= Kernel B: object MLP (unchanged) =================
__global__ __launch_bounds__(256, 2)
void obj_kernel(const float* __restrict__ w2a, const float* __restrict__ b2a,
                const float* __restrict__ w2b, const float* __restrict__ b2b,
                const float* __restrict__ pooled, const float* __restrict__ counts,
                float* __restrict__ outO, int O)
{
    extern __shared__ float sm[];
    float* Xs = sm;
    float* Ws = Xs + 128 * PADH;
    float* invc = Ws + 32 * PADW;

    const unsigned* Xu = (const unsigned*)Xs;
    const unsigned* Wu = (const unsigned*)Ws;

    const int tid = threadIdx.x;
    const int lane = tid & 31;
    const int g = lane >> 2, tg = lane & 3;
    const int w = tid >> 5;
    const int R0 = (w >> 1) * 32, C0 = (w & 1) * 64;
    const int o0 = blockIdx.x * 128;

    if (tid < 128) {
        int o = o0 + tid;
        float c = (o < O) ? counts[o] : 1.f;
        c = fminf(fmaxf(c, 1.f), 1000.f);
        invc[tid] = 1.f / c;
    }
    __syncthreads();

#pragma unroll
    for (int p = 0; p < 16; p++) {
        int idx = p * 256 + tid;
        int r = idx >> 5, c4 = idx & 31;
        int o = o0 + r;
        float4 v = make_float4(0.f, 0.f, 0.f, 0.f);
        if (o < O) v = *(const float4*)(pooled + (size_t)o * 128 + c4 * 4);
        float s = invc[r];
        uint4 u; u.x = f2tf(v.x * s); u.y = f2tf(v.y * s); u.z = f2tf(v.z * s); u.w = f2tf(v.w * s);
        *(uint4*)(Xs + r * PADH + c4 * 4) = u;
    }
    __syncthreads();

    float acc[2][8][4];
    for (int layer = 0; layer < 2; layer++) {
        const float* W = (layer == 0) ? w2a : w2b;
        const float* B = (layer == 0) ? b2a : b2b;
#pragma unroll
        for (int mi = 0; mi < 2; mi++)
#pragma unroll
            for (int ni = 0; ni < 8; ni++)
#pragma unroll
                for (int q = 0; q < 4; q++) acc[mi][ni][q] = 0.f;

        for (int kc = 0; kc < 128; kc += 32) {
#pragma unroll
            for (int p = 0; p < 4; p++) {
                int idx = p * 256 + tid;
                int k = idx >> 5, j4 = idx & 31;
                float4 v = *(const float4*)(W + (size_t)(kc + k) * 128 + j4 * 4);
                uint4 u; u.x = f2tf(v.x); u.y = f2tf(v.y); u.z = f2tf(v.z); u.w = f2tf(v.w);
                *(uint4*)(Ws + k * PADW + j4 * 4) = u;
            }
            __syncthreads();
#pragma unroll
            for (int ks = 0; ks < 4; ks++) {
                const int k0 = kc + ks * 8;
                unsigned a[2][4], b[8][2];
#pragma unroll
                for (int mi = 0; mi < 2; mi++) {
                    int r = R0 + mi * 16 + g;
                    a[mi][0] = Xu[r * PADH + k0 + tg];
                    a[mi][1] = Xu[(r + 8) * PADH + k0 + tg];
                    a[mi][2] = Xu[r * PADH + k0 + tg + 4];
                    a[mi][3] = Xu[(r + 8) * PADH + k0 + tg + 4];
                }
#pragma unroll
                for (int ni = 0; ni < 8; ni++) {
                    int c = C0 + ni * 8 + g;
                    b[ni][0] = Wu[(ks * 8 + tg) * PADW + c];
                    b[ni][1] = Wu[(ks * 8 + tg + 4) * PADW + c];
                }
#pragma unroll
                for (int mi = 0; mi < 2; mi++)
#pragma unroll
                    for (int ni = 0; ni < 8; ni++)
                        mma_tf32(acc[mi][ni], a[mi], b[ni]);
            }
            __syncthreads();
        }

        if (layer == 0) {
#pragma unroll
            for (int mi = 0; mi < 2; mi++)
#pragma unroll
                for (int ni = 0; ni < 8; ni++) {
                    int r = R0 + mi * 16 + g;
                    int c = C0 + ni * 8 + 2 * tg;
                    float bx = B[c], by = B[c + 1];
                    uint2 u0 = make_uint2(f2tf(fmaxf(acc[mi][ni][0] + bx, 0.f)),
                                          f2tf(fmaxf(acc[mi][ni][1] + by, 0.f)));
                    uint2 u1 = make_uint2(f2tf(fmaxf(acc[mi][ni][2] + bx, 0.f)),
                                          f2tf(fmaxf(acc[mi][ni][3] + by, 0.f)));
                    *(uint2*)(Xs + r * PADH + c) = u0;
                    *(uint2*)(Xs + (r + 8) * PADH + c) = u1;
                }
            __syncthreads();
        } else {
#pragma unroll
            for (int mi = 0; mi < 2; mi++)
#pragma unroll
                for (int ni = 0; ni < 8; ni++) {
                    int r = R0 + mi * 16 + g;
                    int c = C0 + ni * 8 + 2 * tg;
                    float bx = B[c], by = B[c + 1];
                    int oa = o0 + r, ob = o0 + r + 8;
                    if (oa < O)
                        *(float2*)(outO + (size_t)oa * 128 + c) =
                            make_float2(fmaxf(acc[mi][ni][0] + bx, 0.f),
                                        fmaxf(acc[mi][ni][1] + by, 0.f));
                    if (ob < O)
                        *(float2*)(outO + (size_t)ob * 128 + c) =
                            make_float2(fmaxf(acc[mi][ni][2] + bx, 0.f),
                                        fmaxf(acc[mi][ni][3] + by, 0.f));
                }
        }
    }
}

// ================= launch =================
extern "C" void kernel_launch(void* const* d_in, const int* in_sizes, int n_in,
                              void* d_out, int out_size)
{
    const float* obj   = (const float*)d_in[0];
    const float* predi = (const float*)d_in[1];
    const int*   edges = (const int*)d_in[2];
    const float* w1a   = (const float*)d_in[3];
    const float* b1a   = (const float*)d_in[4];
    const float* w1b   = (const float*)d_in[5];
    const float* b1b   = (const float*)d_in[6];
    const float* w2a   = (const float*)d_in[7];
    const float* b2a   = (const float*)d_in[8];
    const float* w2b   = (const float*)d_in[9];
    const float* b2b   = (const float*)d_in[10];

    const int O = in_sizes[0] / 128;
    const int T = in_sizes[1] / 128;

    float* outO = (float*)d_out;
    float* outP = outO + (size_t)O * 128;

    float *pooled = nullptr, *counts = nullptr, *proj = nullptr;
    cudaGetSymbolAddress((void**)&pooled, g_pooled);
    cudaGetSymbolAddress((void**)&counts, g_counts);
    cudaGetSymbolAddress((void**)&proj,   g_proj);

    cudaMemsetAsync(pooled, 0, (size_t)O * 128 * sizeof(float));
    cudaMemsetAsync(counts, 0, (size_t)O * sizeof(float));

    const size_t smP = (size_t)(128 * PADH + 2 * 32 * PADW) * sizeof(float);
    const size_t smA = smP + 256 * sizeof(int);
    const size_t smB = (size_t)(128 * PADH + 32 * PADW + 128) * sizeof(float);

    cudaFuncSetAttribute(proj_kernel,   cudaFuncAttributeMaxDynamicSharedMemorySize, (int)smP);
    cudaFuncSetAttribute(triple_kernel, cudaFuncAttributeMaxDynamicSharedMemorySize, (int)smA);
    cudaFuncSetAttribute(obj_kernel,    cudaFuncAttributeMaxDynamicSharedMemorySize, (int)smB);

    proj_kernel<<<(O + 127) / 128, 256, smP>>>(obj, w1a, proj, O);
    triple_kernel<<<(T + 127) / 128, 128, smA>>>(predi, edges,
                                                 w1a, b1a, w1b, b1b, proj,
                                                 outP, pooled, counts, T);
    obj_kernel<<<(O + 127) / 128, 256, smB>>>(w2a, b2a, w2b, b2b,
                                              pooled, counts, outO, O);
}

// round 7
// speedup vs baseline: 3.9648x; 1.1986x over previous
#include <cuda_runtime.h>
#include <cuda_fp16.h>
#include <cstdint>
#include <cstddef>

// ---------------- scratch (no allocs allowed) ----------------
#define O_CAP 100000
static __device__ float g_pooled[(size_t)O_CAP * 128];
static __device__ float g_counts[O_CAP];
static __device__ float g_proj[(size_t)O_CAP * 256];
// 8 pre-transposed half tiles [n=128][k=128]:
// 0,1,2: w1a k-rows [0:128),[128:256),[256:384);  3,4,5: w1b nc 0..2;  6: w2a; 7: w2b
static __device__ __half g_wt[8 * 128 * 128];

#define PADK 68   // 32-bit words per row (64 data + 4 pad) -> bank = 4r+tg, conflict-free

// ---------------- helpers ----------------
__device__ __forceinline__ unsigned pk2(float x, float y) {
    __half2 h = __floats2half2_rn(x, y);
    return *reinterpret_cast<unsigned*>(&h);
}
__device__ __forceinline__ void mma_f16(float c[4], const unsigned a[4], const unsigned b[2]) {
    asm volatile(
        "mma.sync.aligned.m16n8k16.row.col.f32.f16.f16.f32 "
        "{%0,%1,%2,%3},{%4,%5,%6,%7},{%8,%9},{%0,%1,%2,%3};\n"
        : "+f"(c[0]), "+f"(c[1]), "+f"(c[2]), "+f"(c[3])
        : "r"(a[0]), "r"(a[1]), "r"(a[2]), "r"(a[3]), "r"(b[0]), "r"(b[1]));
}
__device__ __forceinline__ void red_add_v4(float* p, float a, float b, float c, float d) {
    asm volatile("red.global.add.v4.f32 [%0], {%1,%2,%3,%4};"
                 :: "l"(p), "f"(a), "f"(b), "f"(c), "f"(d) : "memory");
}

// ================= prep: transpose+convert weights to half [n][k] =================
__global__ void prep_kernel(const float* __restrict__ w1a, const float* __restrict__ w1b,
                            const float* __restrict__ w2a, const float* __restrict__ w2b,
                            __half* __restrict__ wt)
{
    const int t = blockIdx.x;           // 0..7
    const int tid = threadIdx.x;
    for (int p = 0; p < 64; p++) {
        int idx = p * 256 + tid;        // 0..16383
        int n = idx >> 7, k = idx & 127;
        float v;
        if (t < 3)       v = w1a[(size_t)(t * 128 + k) * 128 + n];
        else if (t < 6)  v = w1b[(size_t)k * 384 + (t - 3) * 128 + n];
        else if (t == 6) v = w2a[(size_t)k * 128 + n];
        else             v = w2b[(size_t)k * 128 + n];
        wt[((size_t)t * 128 + n) * 128 + k] = __float2half_rn(v);
    }
}

// ---------------- shared mainloop: 8 ksteps of m16n8k16 over full K=128 ----------------
#define MMA_KLOOP(As, Wu, acc, R0, C0, g, tg)                                   \
    do {                                                                        \
        _Pragma("unroll")                                                       \
        for (int ks = 0; ks < 8; ks++) {                                        \
            const int kw = ks * 8;                                              \
            unsigned a[2][4], b[8][2];                                          \
            _Pragma("unroll")                                                   \
            for (int mi = 0; mi < 2; mi++) {                                    \
                int r = (R0) + mi * 16 + (g);                                   \
                a[mi][0] = (As)[r * PADK + kw + (tg)];                          \
                a[mi][1] = (As)[(r + 8) * PADK + kw + (tg)];                    \
                a[mi][2] = (As)[r * PADK + kw + 4 + (tg)];                      \
                a[mi][3] = (As)[(r + 8) * PADK + kw + 4 + (tg)];                \
            }                                                                   \
            _Pragma("unroll")                                                   \
            for (int ni = 0; ni < 8; ni++) {                                    \
                int c = (C0) + ni * 8 + (g);                                    \
                b[ni][0] = (Wu)[c * PADK + kw + (tg)];                          \
                b[ni][1] = (Wu)[c * PADK + kw + 4 + (tg)];                      \
            }                                                                   \
            _Pragma("unroll")                                                   \
            for (int mi = 0; mi < 2; mi++)                                      \
                _Pragma("unroll")                                               \
                for (int ni = 0; ni < 8; ni++)                                  \
                    mma_f16(acc[mi][ni], a[mi], b[ni]);                         \
        }                                                                       \
    } while (0)

#define ZERO_ACC(acc)                                                           \
    do {                                                                        \
        _Pragma("unroll")                                                       \
        for (int mi = 0; mi < 2; mi++)                                          \
            _Pragma("unroll")                                                   \
            for (int ni = 0; ni < 8; ni++)                                      \
                _Pragma("unroll")                                               \
                for (int q = 0; q < 4; q++) acc[mi][ni][q] = 0.f;               \
    } while (0)

// ================= Kernel A: triple MLP (fp16 MMA) + scatter =================
__global__ __launch_bounds__(256, 2)
void triple_kernel(const float* __restrict__ predi, const int* __restrict__ edges,
                   const __half* __restrict__ wt,
                   const float* __restrict__ b1a, const float* __restrict__ b1b,
                   const float* __restrict__ proj,
                   float* __restrict__ outP, float* __restrict__ pooled,
                   float* __restrict__ counts, int T)
{
    extern __shared__ unsigned smu[];
    unsigned* As = smu;                    // 128*PADK
    unsigned* Wb = smu + 128 * PADK;       // 2 * 128*PADK
    int* sIdx = (int*)(smu + 3 * 128 * PADK);
    int* oIdx = sIdx + 128;

    const int tid  = threadIdx.x;
    const int lane = tid & 31;
    const int g    = lane >> 2;
    const int tg   = lane & 3;
    const int w    = tid >> 5;
    const int R0   = (w >> 1) * 32;
    const int C0   = (w & 1) * 64;
    const int t0   = blockIdx.x * 128;

    if (tid < 128) {
        int t = t0 + tid;
        int s = 0, o = 0;
        if (t < T) {
            s = edges[2 * t];
            o = edges[2 * t + 1];
            atomicAdd(&counts[s], 1.0f);
            atomicAdd(&counts[o], 1.0f);
        }
        sIdx[tid] = s; oIdx[tid] = o;
    }

    // stage A = half(predi tile)
#pragma unroll
    for (int p = 0; p < 16; p++) {
        int idx = p * 256 + tid;
        int r = idx >> 5, c4 = idx & 31;
        int t = t0 + r;
        float4 v = make_float4(0.f, 0.f, 0.f, 0.f);
        if (t < T) v = *(const float4*)(predi + (size_t)t * 128 + c4 * 4);
        *(uint2*)(As + r * PADK + c4 * 2) = make_uint2(pk2(v.x, v.y), pk2(v.z, v.w));
    }

    auto stageW = [&](int buf, const __half* src) {
        unsigned* d = Wb + buf * 128 * PADK;
        const uint4* s = (const uint4*)src;
#pragma unroll
        for (int p = 0; p < 8; p++) {
            int idx = p * 256 + tid;       // 0..2047
            int n = idx >> 4, c = idx & 15;
            *(uint4*)(d + n * PADK + c * 4) = s[idx];
        }
    };

    stageW(0, wt + 1 * 16384);             // GEMM1 W = w1a_mid^T
    __syncthreads();
    stageW(1, wt + 3 * 16384);             // prefetch GEMM2 nc0 during GEMM1 mma

    float acc[2][8][4];
    ZERO_ACC(acc);
    MMA_KLOOP(As, Wb, acc, R0, C0, g, tg);
    __syncthreads();                       // everyone done reading As before H overwrite

    // GEMM1 epilogue: H = half(relu(acc + b1a + proj_s + proj_o)) -> As
#pragma unroll
    for (int mi = 0; mi < 2; mi++) {
        int ra = R0 + mi * 16 + g;
        int rb = ra + 8;
        const float* psA = proj + (size_t)sIdx[ra] * 256;
        const float* poA = proj + (size_t)oIdx[ra] * 256 + 128;
        const float* psB = proj + (size_t)sIdx[rb] * 256;
        const float* poB = proj + (size_t)oIdx[rb] * 256 + 128;
#pragma unroll
        for (int ni = 0; ni < 8; ni++) {
            int c = C0 + ni * 8 + 2 * tg;
            float2 bv = *(const float2*)(b1a + c);
            float2 sa = *(const float2*)(psA + c);
            float2 oa = *(const float2*)(poA + c);
            float2 sb = *(const float2*)(psB + c);
            float2 ob = *(const float2*)(poB + c);
            As[ra * PADK + (c >> 1)] = pk2(fmaxf(acc[mi][ni][0] + bv.x + sa.x + oa.x, 0.f),
                                           fmaxf(acc[mi][ni][1] + bv.y + sa.y + oa.y, 0.f));
            As[rb * PADK + (c >> 1)] = pk2(fmaxf(acc[mi][ni][2] + bv.x + sb.x + ob.x, 0.f),
                                           fmaxf(acc[mi][ni][3] + bv.y + sb.y + ob.y, 0.f));
        }
    }
    __syncthreads();

    // GEMM2: 3 N-chunks, double-buffered W
    for (int nc = 0; nc < 3; nc++) {
        if (nc < 2) stageW(nc & 1, wt + (size_t)(4 + nc) * 16384);
        ZERO_ACC(acc);
        const unsigned* Wu = Wb + ((nc & 1) ^ 1) * 128 * PADK;
        MMA_KLOOP(As, Wu, acc, R0, C0, g, tg);

        const int boff = nc * 128;
#pragma unroll
        for (int mi = 0; mi < 2; mi++) {
            int ra = R0 + mi * 16 + g;
            int rb = ra + 8;
            int ta = t0 + ra, tb = t0 + rb;
            float* dA;
            float* dB;
            if (nc == 1) { dA = outP + (size_t)ta * 128; dB = outP + (size_t)tb * 128; }
            else {
                const int* ridx = nc ? oIdx : sIdx;
                dA = pooled + (size_t)ridx[ra] * 128;
                dB = pooled + (size_t)ridx[rb] * 128;
            }
#pragma unroll
            for (int ni = 0; ni < 8; ni++) {
                int cb = C0 + ni * 8;
                float2 bv = *(const float2*)(b1b + boff + cb + 2 * tg);
                float p0 = fmaxf(acc[mi][ni][0] + bv.x, 0.f);
                float p1 = fmaxf(acc[mi][ni][1] + bv.y, 0.f);
                float q0 = fmaxf(acc[mi][ni][2] + bv.x, 0.f);
                float q1 = fmaxf(acc[mi][ni][3] + bv.y, 0.f);
                float pp0 = __shfl_xor_sync(0xFFFFFFFF, p0, 1);
                float pp1 = __shfl_xor_sync(0xFFFFFFFF, p1, 1);
                float qq0 = __shfl_xor_sync(0xFFFFFFFF, q0, 1);
                float qq1 = __shfl_xor_sync(0xFFFFFFFF, q1, 1);
                if (nc == 1) {
                    if (!(tg & 1)) {
                        if (ta < T) *(float4*)(dA + cb + 2 * tg) = make_float4(p0, p1, pp0, pp1);
                    } else {
                        if (tb < T) *(float4*)(dB + cb + 2 * (tg - 1)) = make_float4(qq0, qq1, q0, q1);
                    }
                } else {
                    if (!(tg & 1)) {
                        if (ta < T) red_add_v4(dA + cb + 2 * tg, p0, p1, pp0, pp1);
                    } else {
                        if (tb < T) red_add_v4(dB + cb + 2 * (tg - 1), qq0, qq1, q0, q1);
                    }
                }
            }
        }
        __syncthreads();
    }
}

// ================= Kernel P: proj = obj @ {w1a_top^T, w1a_bot^T} =================
__global__ __launch_bounds__(256, 2)
void proj_kernel(const float* __restrict__ obj, const __half* __restrict__ wt,
                 float* __restrict__ proj, int O)
{
    extern __shared__ unsigned smu[];
    unsigned* As = smu;
    unsigned* Wb = smu + 128 * PADK;

    const int tid  = threadIdx.x;
    const int lane = tid & 31;
    const int g    = lane >> 2;
    const int tg   = lane & 3;
    const int w    = tid >> 5;
    const int R0   = (w >> 1) * 32;
    const int C0   = (w & 1) * 64;
    const int o0   = blockIdx.x * 128;

#pragma unroll
    for (int p = 0; p < 16; p++) {
        int idx = p * 256 + tid;
        int r = idx >> 5, c4 = idx & 31;
        int o = o0 + r;
        float4 v = make_float4(0.f, 0.f, 0.f, 0.f);
        if (o < O) v = *(const float4*)(obj + (size_t)o * 128 + c4 * 4);
        *(uint2*)(As + r * PADK + c4 * 2) = make_uint2(pk2(v.x, v.y), pk2(v.z, v.w));
    }

    auto stageW = [&](int buf, const __half* src) {
        unsigned* d = Wb + buf * 128 * PADK;
        const uint4* s = (const uint4*)src;
#pragma unroll
        for (int p = 0; p < 8; p++) {
            int idx = p * 256 + tid;
            int n = idx >> 4, c = idx & 15;
            *(uint4*)(d + n * PADK + c * 4) = s[idx];
        }
    };

    stageW(0, wt);                         // tile 0 = w1a_top^T
    __syncthreads();
    stageW(1, wt + 2 * 16384);             // tile 2 = w1a_bot^T

    float acc[2][8][4];
    for (int m = 0; m < 2; m++) {
        ZERO_ACC(acc);
        const unsigned* Wu = Wb + m * 128 * PADK;
        MMA_KLOOP(As, Wu, acc, R0, C0, g, tg);
#pragma unroll
        for (int mi = 0; mi < 2; mi++) {
            int ra = R0 + mi * 16 + g;
            int rb = ra + 8;
            int oa = o0 + ra, ob = o0 + rb;
#pragma unroll
            for (int ni = 0; ni < 8; ni++) {
                int cb = C0 + ni * 8;
                float p0 = acc[mi][ni][0], p1 = acc[mi][ni][1];
                float q0 = acc[mi][ni][2], q1 = acc[mi][ni][3];
                float pp0 = __shfl_xor_sync(0xFFFFFFFF, p0, 1);
                float pp1 = __shfl_xor_sync(0xFFFFFFFF, p1, 1);
                float qq0 = __shfl_xor_sync(0xFFFFFFFF, q0, 1);
                float qq1 = __shfl_xor_sync(0xFFFFFFFF, q1, 1);
                if (!(tg & 1)) {
                    if (oa < O)
                        *(float4*)(proj + (size_t)oa * 256 + m * 128 + cb + 2 * tg) =
                            make_float4(p0, p1, pp0, pp1);
                } else {
                    if (ob < O)
                        *(float4*)(proj + (size_t)ob * 256 + m * 128 + cb + 2 * (tg - 1)) =
                            make_float4(qq0, qq1, q0, q1);
                }
            }
        }
        __syncthreads();
    }
}

// ================= Kernel B: object MLP (fp16 MMA) =================
__global__ __launch_bounds__(256, 2)
void obj_kernel(const __half* __restrict__ wt,
                const float* __restrict__ b2a, const float* __restrict__ b2b,
                const float* __restrict__ pooled, const float* __restrict__ counts,
                float* __restrict__ outO, int O)
{
    extern __shared__ unsigned smu[];
    unsigned* As = smu;
    unsigned* Wu = smu + 128 * PADK;
    float* invc = (float*)(smu + 2 * 128 * PADK);

    const int tid  = threadIdx.x;
    const int lane = tid & 31;
    const int g    = lane >> 2;
    const int tg   = lane & 3;
    const int w    = tid >> 5;
    const int R0   = (w >> 1) * 32;
    const int C0   = (w & 1) * 64;
    const int o0   = blockIdx.x * 128;

    if (tid < 128) {
        int o = o0 + tid;
        float c = (o < O) ? counts[o] : 1.f;
        c = fminf(fmaxf(c, 1.f), 1000.f);
        invc[tid] = 1.f / c;
    }

    auto stageW = [&](const __half* src) {
        const uint4* s = (const uint4*)src;
#pragma unroll
        for (int p = 0; p < 8; p++) {
            int idx = p * 256 + tid;
            int n = idx >> 4, c = idx & 15;
            *(uint4*)(Wu + n * PADK + c * 4) = s[idx];
        }
    };

    stageW(wt + 6 * 16384);                // w2a^T
    __syncthreads();

#pragma unroll
    for (int p = 0; p < 16; p++) {
        int idx = p * 256 + tid;
        int r = idx >> 5, c4 = idx & 31;
        int o = o0 + r;
        float4 v = make_float4(0.f, 0.f, 0.f, 0.f);
        if (o < O) v = *(const float4*)(pooled + (size_t)o * 128 + c4 * 4);
        float s = invc[r];
        *(uint2*)(As + r * PADK + c4 * 2) =
            make_uint2(pk2(v.x * s, v.y * s), pk2(v.z * s, v.w * s));
    }
    __syncthreads();

    float acc[2][8][4];
    // layer 0
    ZERO_ACC(acc);
    MMA_KLOOP(As, Wu, acc, R0, C0, g, tg);
    __syncthreads();                       // all reads of As/Wu done

    // epilogue -> As (half), stage w2b^T
#pragma unroll
    for (int mi = 0; mi < 2; mi++) {
        int ra = R0 + mi * 16 + g;
        int rb = ra + 8;
#pragma unroll
        for (int ni = 0; ni < 8; ni++) {
            int c = C0 + ni * 8 + 2 * tg;
            float2 bv = *(const float2*)(b2a + c);
            As[ra * PADK + (c >> 1)] = pk2(fmaxf(acc[mi][ni][0] + bv.x, 0.f),
                                           fmaxf(acc[mi][ni][1] + bv.y, 0.f));
            As[rb * PADK + (c >> 1)] = pk2(fmaxf(acc[mi][ni][2] + bv.x, 0.f),
                                           fmaxf(acc[mi][ni][3] + bv.y, 0.f));
        }
    }
    stageW(wt + 7 * 16384);
    __syncthreads();

    // layer 1
    ZERO_ACC(acc);
    MMA_KLOOP(As, Wu, acc, R0, C0, g, tg);
#pragma unroll
    for (int mi = 0; mi < 2; mi++) {
        int ra = R0 + mi * 16 + g;
        int rb = ra + 8;
        int oa = o0 + ra, ob = o0 + rb;
#pragma unroll
        for (int ni = 0; ni < 8; ni++) {
            int cb = C0 + ni * 8;
            float2 bv = *(const float2*)(b2b + cb + 2 * tg);
            float p0 = fmaxf(acc[mi][ni][0] + bv.x, 0.f);
            float p1 = fmaxf(acc[mi][ni][1] + bv.y, 0.f);
            float q0 = fmaxf(acc[mi][ni][2] + bv.x, 0.f);
            float q1 = fmaxf(acc[mi][ni][3] + bv.y, 0.f);
            float pp0 = __shfl_xor_sync(0xFFFFFFFF, p0, 1);
            float pp1 = __shfl_xor_sync(0xFFFFFFFF, p1, 1);
            float qq0 = __shfl_xor_sync(0xFFFFFFFF, q0, 1);
            float qq1 = __shfl_xor_sync(0xFFFFFFFF, q1, 1);
            if (!(tg & 1)) {
                if (oa < O)
                    *(float4*)(outO + (size_t)oa * 128 + cb + 2 * tg) =
                        make_float4(p0, p1, pp0, pp1);
            } else {
                if (ob < O)
                    *(float4*)(outO + (size_t)ob * 128 + cb + 2 * (tg - 1)) =
                        make_float4(qq0, qq1, q0, q1);
            }
        }
    }
}

// ================= launch =================
extern "C" void kernel_launch(void* const* d_in, const int* in_sizes, int n_in,
                              void* d_out, int out_size)
{
    const float* obj   = (const float*)d_in[0];
    const float* predi = (const float*)d_in[1];
    const int*   edges = (const int*)d_in[2];
    const float* w1a   = (const float*)d_in[3];
    const float* b1a   = (const float*)d_in[4];
    const float* w1b   = (const float*)d_in[5];
    const float* b1b   = (const float*)d_in[6];
    const float* w2a   = (const float*)d_in[7];
    const float* b2a   = (const float*)d_in[8];
    const float* w2b   = (const float*)d_in[9];
    const float* b2b   = (const float*)d_in[10];

    const int O = in_sizes[0] / 128;
    const int T = in_sizes[1] / 128;

    float* outO = (float*)d_out;
    float* outP = outO + (size_t)O * 128;

    float *pooled = nullptr, *counts = nullptr, *proj = nullptr;
    __half* wt = nullptr;
    cudaGetSymbolAddress((void**)&pooled, g_pooled);
    cudaGetSymbolAddress((void**)&counts, g_counts);
    cudaGetSymbolAddress((void**)&proj,   g_proj);
    cudaGetSymbolAddress((void**)&wt,     g_wt);

    cudaMemsetAsync(pooled, 0, (size_t)O * 128 * sizeof(float));
    cudaMemsetAsync(counts, 0, (size_t)O * sizeof(float));

    const size_t smT = (size_t)(3 * 128 * PADK) * 4 + 1024;
    const size_t smP = (size_t)(3 * 128 * PADK) * 4;
    const size_t smB = (size_t)(2 * 128 * PADK) * 4 + 512;

    cudaFuncSetAttribute(proj_kernel,   cudaFuncAttributeMaxDynamicSharedMemorySize, (int)smP);
    cudaFuncSetAttribute(triple_kernel, cudaFuncAttributeMaxDynamicSharedMemorySize, (int)smT);
    cudaFuncSetAttribute(obj_kernel,    cudaFuncAttributeMaxDynamicSharedMemorySize, (int)smB);

    prep_kernel<<<8, 256>>>(w1a, w1b, w2a, w2b, wt);
    proj_kernel<<<(O + 127) / 128, 256, smP>>>(obj, wt, proj, O);
    triple_kernel<<<(T + 127) / 128, 256, smT>>>(predi, edges, wt, b1a, b1b, proj,
                                                 outP, pooled, counts, T);
    obj_kernel<<<(O + 127) / 128, 256, smB>>>(wt, b2a, b2b, pooled, counts, outO, O);
}

// round 9
// speedup vs baseline: 4.4919x; 1.1329x over previous
#include <cuda_runtime.h>
#include <cuda_fp16.h>
#include <cstdint>
#include <cstddef>

// ---------------- scratch (no allocs allowed) ----------------
#define O_CAP 100000
static __device__ float g_pooled[(size_t)O_CAP * 128];
static __device__ float g_counts[O_CAP];
static __device__ float g_proj[(size_t)O_CAP * 256];
// 8 pre-transposed half tiles [n=128][k=128]:
// 0,1,2: w1a k-rows [0:128),[128:256),[256:384);  3,4,5: w1b nc 0..2;  6: w2a; 7: w2b
static __device__ __half g_wt[8 * 128 * 128];

#define PADK  68   // As row stride (words): 64 data + 4 pad -> conflict-free
#define PADW2 36   // half-K W row stride (words): 32 data + 4 pad -> conflict-free
#define MT    64   // triples per block in triple_kernel

// ---------------- helpers ----------------
__device__ __forceinline__ unsigned pk2(float x, float y) {
    __half2 h = __floats2half2_rn(x, y);
    return *reinterpret_cast<unsigned*>(&h);
}
__device__ __forceinline__ void mma_f16(float c[4], const unsigned a[4], const unsigned b[2]) {
    asm volatile(
        "mma.sync.aligned.m16n8k16.row.col.f32.f16.f16.f32 "
        "{%0,%1,%2,%3},{%4,%5,%6,%7},{%8,%9},{%0,%1,%2,%3};\n"
        : "+f"(c[0]), "+f"(c[1]), "+f"(c[2]), "+f"(c[3])
        : "r"(a[0]), "r"(a[1]), "r"(a[2]), "r"(a[3]), "r"(b[0]), "r"(b[1]));
}
__device__ __forceinline__ void red_add_v4(float* p, float a, float b, float c, float d) {
    asm volatile("red.global.add.v4.f32 [%0], {%1,%2,%3,%4};"
                 :: "l"(p), "f"(a), "f"(b), "f"(c), "f"(d) : "memory");
}
__device__ __forceinline__ void cp16(void* dst, const void* src) {
    unsigned d = (unsigned)__cvta_generic_to_shared(dst);
    asm volatile("cp.async.cg.shared.global [%0], [%1], 16;" :: "r"(d), "l"(src) : "memory");
}
#define CP_COMMIT() asm volatile("cp.async.commit_group;" ::: "memory")
#define CP_WAIT0()  asm volatile("cp.async.wait_group 0;" ::: "memory")

// ================= prep: transpose+convert weights to half [n][k] =================
__global__ void prep_kernel(const float* __restrict__ w1a, const float* __restrict__ w1b,
                            const float* __restrict__ w2a, const float* __restrict__ w2b,
                            __half* __restrict__ wt)
{
    const int t = blockIdx.x;           // 0..7
    const int tid = threadIdx.x;
    for (int p = 0; p < 64; p++) {
        int idx = p * 256 + tid;        // 0..16383
        int n = idx >> 7, k = idx & 127;
        float v;
        if (t < 3)       v = w1a[(size_t)(t * 128 + k) * 128 + n];
        else if (t < 6)  v = w1b[(size_t)k * 384 + (t - 3) * 128 + n];
        else if (t == 6) v = w2a[(size_t)k * 128 + n];
        else             v = w2b[(size_t)k * 128 + n];
        wt[((size_t)t * 128 + n) * 128 + k] = __float2half_rn(v);
    }
}

// ================= Kernel A: triple MLP, 64-row tiles, m32n32 warps, cp.async W =================
__global__ __launch_bounds__(256, 3)
void triple_kernel(const float* __restrict__ predi, const int* __restrict__ edges,
                   const __half* __restrict__ wt,
                   const float* __restrict__ b1a, const float* __restrict__ b1b,
                   const float* __restrict__ proj,
                   float* __restrict__ outP, float* __restrict__ pooled,
                   float* __restrict__ counts, int T)
{
    extern __shared__ unsigned smu[];
    unsigned* As = smu;                            // MT*PADK
    unsigned* Wb = smu + MT * PADK;                // 2 * 128*PADW2
    int* sIdx = (int*)(smu + MT * PADK + 2 * 128 * PADW2);
    int* oIdx = sIdx + MT;

    const int tid  = threadIdx.x;
    const int lane = tid & 31;
    const int g    = lane >> 2;
    const int tg   = lane & 3;
    const int w    = tid >> 5;
    const int R0   = (w >> 2) * 32;                // 2 row groups x 32 = 64 rows
    const int C0   = (w & 3) * 32;                 // 4 col groups x 32 = 128 cols
    const int t0   = blockIdx.x * MT;

    // cp.async stage: one half-K chunk [128n][32 words] of a tile
    auto stageW = [&](int buf, const __half* tile, int half) {
        unsigned* dstBase = Wb + buf * 128 * PADW2;
#pragma unroll
        for (int p = 0; p < 4; p++) {
            int idx = p * 256 + tid;               // 0..1023
            int n = idx >> 3, c8 = idx & 7;
            cp16(dstBase + n * PADW2 + c8 * 4, tile + n * 128 + half * 64 + c8 * 8);
        }
        CP_COMMIT();
    };

    // chunk schedule: tiles {1,1,3,3,4,4,5,5}, half = i&1
    stageW(0, wt + 1 * 16384, 0);

    if (tid < MT) {
        int t = t0 + tid;
        int s = 0, o = 0;
        if (t < T) {
            s = edges[2 * t];
            o = edges[2 * t + 1];
            atomicAdd(&counts[s], 1.0f);
            atomicAdd(&counts[o], 1.0f);
        }
        sIdx[tid] = s; oIdx[tid] = o;
    }

    // stage A = half(predi tile): MT rows x 32 float4 = 2048 items
#pragma unroll
    for (int p = 0; p < 8; p++) {
        int idx = p * 256 + tid;
        int r = idx >> 5, c4 = idx & 31;
        int t = t0 + r;
        float4 v = make_float4(0.f, 0.f, 0.f, 0.f);
        if (t < T) v = *(const float4*)(predi + (size_t)t * 128 + c4 * 4);
        *(uint2*)(As + r * PADK + c4 * 2) = make_uint2(pk2(v.x, v.y), pk2(v.z, v.w));
    }
    CP_WAIT0();
    __syncthreads();

    float acc[2][4][4];
#pragma unroll
    for (int mi = 0; mi < 2; mi++)
#pragma unroll
        for (int ni = 0; ni < 4; ni++)
#pragma unroll
            for (int q = 0; q < 4; q++) acc[mi][ni][q] = 0.f;

    for (int i = 0; i < 8; i++) {
        if (i < 7) {
            int tile2 = (i + 1) < 2 ? 1 : 3 + ((i - 1) >> 1);
            stageW((i + 1) & 1, wt + (size_t)tile2 * 16384, (i + 1) & 1);
        }
        const unsigned* Wu = Wb + (i & 1) * 128 * PADW2;
        const int kwA0 = (i & 1) * 32;
#pragma unroll
        for (int ks = 0; ks < 4; ks++) {
            const int kwA = kwA0 + ks * 8;
            const int kwB = ks * 8;
            unsigned a[2][4], b[4][2];
#pragma unroll
            for (int mi = 0; mi < 2; mi++) {
                int r = R0 + mi * 16 + g;
                a[mi][0] = As[r * PADK + kwA + tg];
                a[mi][1] = As[(r + 8) * PADK + kwA + tg];
                a[mi][2] = As[r * PADK + kwA + 4 + tg];
                a[mi][3] = As[(r + 8) * PADK + kwA + 4 + tg];
            }
#pragma unroll
            for (int ni = 0; ni < 4; ni++) {
                int c = C0 + ni * 8 + g;
                b[ni][0] = Wu[c * PADW2 + kwB + tg];
                b[ni][1] = Wu[c * PADW2 + kwB + 4 + tg];
            }
#pragma unroll
            for (int mi = 0; mi < 2; mi++)
#pragma unroll
                for (int ni = 0; ni < 4; ni++)
                    mma_f16(acc[mi][ni], a[mi], b[ni]);
        }
        CP_WAIT0();
        __syncthreads();

        if (i == 1) {
            // GEMM1 epilogue: H = half(relu(acc + b1a + proj_s + proj_o)) -> As
#pragma unroll
            for (int mi = 0; mi < 2; mi++) {
                int ra = R0 + mi * 16 + g;
                int rb = ra + 8;
                const float* psA = proj + (size_t)sIdx[ra] * 256;
                const float* poA = proj + (size_t)oIdx[ra] * 256 + 128;
                const float* psB = proj + (size_t)sIdx[rb] * 256;
                const float* poB = proj + (size_t)oIdx[rb] * 256 + 128;
#pragma unroll
                for (int ni = 0; ni < 4; ni++) {
                    int c = C0 + ni * 8 + 2 * tg;
                    float2 bv = *(const float2*)(b1a + c);
                    float2 sa = *(const float2*)(psA + c);
                    float2 oa = *(const float2*)(poA + c);
                    float2 sb = *(const float2*)(psB + c);
                    float2 ob = *(const float2*)(poB + c);
                    As[ra * PADK + (c >> 1)] =
                        pk2(fmaxf(acc[mi][ni][0] + bv.x + sa.x + oa.x, 0.f),
                            fmaxf(acc[mi][ni][1] + bv.y + sa.y + oa.y, 0.f));
                    As[rb * PADK + (c >> 1)] =
                        pk2(fmaxf(acc[mi][ni][2] + bv.x + sb.x + ob.x, 0.f),
                            fmaxf(acc[mi][ni][3] + bv.y + sb.y + ob.y, 0.f));
                }
            }
            __syncthreads();
#pragma unroll
            for (int mi = 0; mi < 2; mi++)
#pragma unroll
                for (int ni = 0; ni < 4; ni++)
#pragma unroll
                    for (int q = 0; q < 4; q++) acc[mi][ni][q] = 0.f;
        } else if (i >= 3 && (i & 1)) {
            // GEMM2 epilogue for nc = (i-2)>>1
            const int nc = (i - 2) >> 1;
            const int boff = nc * 128;
#pragma unroll
            for (int mi = 0; mi < 2; mi++) {
                int ra = R0 + mi * 16 + g;
                int rb = ra + 8;
                int ta = t0 + ra, tb = t0 + rb;
                float* dA;
                float* dB;
                if (nc == 1) { dA = outP + (size_t)ta * 128; dB = outP + (size_t)tb * 128; }
                else {
                    const int* ridx = nc ? oIdx : sIdx;
                    dA = pooled + (size_t)ridx[ra] * 128;
                    dB = pooled + (size_t)ridx[rb] * 128;
                }
#pragma unroll
                for (int ni = 0; ni < 4; ni++) {
                    int cb = C0 + ni * 8;
                    float2 bv = *(const float2*)(b1b + boff + cb + 2 * tg);
                    float p0 = fmaxf(acc[mi][ni][0] + bv.x, 0.f);
                    float p1 = fmaxf(acc[mi][ni][1] + bv.y, 0.f);
                    float q0 = fmaxf(acc[mi][ni][2] + bv.x, 0.f);
                    float q1 = fmaxf(acc[mi][ni][3] + bv.y, 0.f);
                    float pp0 = __shfl_xor_sync(0xFFFFFFFF, p0, 1);
                    float pp1 = __shfl_xor_sync(0xFFFFFFFF, p1, 1);
                    float qq0 = __shfl_xor_sync(0xFFFFFFFF, q0, 1);
                    float qq1 = __shfl_xor_sync(0xFFFFFFFF, q1, 1);
                    if (nc == 1) {
                        if (!(tg & 1)) {
                            if (ta < T) *(float4*)(dA + cb + 2 * tg) = make_float4(p0, p1, pp0, pp1);
                        } else {
                            if (tb < T) *(float4*)(dB + cb + 2 * (tg - 1)) = make_float4(qq0, qq1, q0, q1);
                        }
                    } else {
                        if (!(tg & 1)) {
                            if (ta < T) red_add_v4(dA + cb + 2 * tg, p0, p1, pp0, pp1);
                        } else {
                            if (tb < T) red_add_v4(dB + cb + 2 * (tg - 1), qq0, qq1, q0, q1);
                        }
                    }
                }
            }
            if (i < 7) {
#pragma unroll
                for (int mi = 0; mi < 2; mi++)
#pragma unroll
                    for (int ni = 0; ni < 4; ni++)
#pragma unroll
                        for (int q = 0; q < 4; q++) acc[mi][ni][q] = 0.f;
            }
        }
    }
}

// ---------------- shared m32n64 mainloop for proj/obj ----------------
#define MMA_KLOOP(As, Wu, acc, R0, C0, g, tg)                                   \
    do {                                                                        \
        _Pragma("unroll")                                                       \
        for (int ks = 0; ks < 8; ks++) {                                        \
            const int kw = ks * 8;                                              \
            unsigned a[2][4], b[8][2];                                          \
            _Pragma("unroll")                                                   \
            for (int mi = 0; mi < 2; mi++) {                                    \
                int r = (R0) + mi * 16 + (g);                                   \
                a[mi][0] = (As)[r * PADK + kw + (tg)];                          \
                a[mi][1] = (As)[(r + 8) * PADK + kw + (tg)];                    \
                a[mi][2] = (As)[r * PADK + kw + 4 + (tg)];                      \
                a[mi][3] = (As)[(r + 8) * PADK + kw + 4 + (tg)];                \
            }                                                                   \
            _Pragma("unroll")                                                   \
            for (int ni = 0; ni < 8; ni++) {                                    \
                int c = (C0) + ni * 8 + (g);                                    \
                b[ni][0] = (Wu)[c * PADK + kw + (tg)];                          \
                b[ni][1] = (Wu)[c * PADK + kw + 4 + (tg)];                      \
            }                                                                   \
            _Pragma("unroll")                                                   \
            for (int mi = 0; mi < 2; mi++)                                      \
                _Pragma("unroll")                                               \
                for (int ni = 0; ni < 8; ni++)                                  \
                    mma_f16(acc[mi][ni], a[mi], b[ni]);                         \
        }                                                                       \
    } while (0)

#define ZERO_ACC8(acc)                                                          \
    do {                                                                        \
        _Pragma("unroll")                                                       \
        for (int mi = 0; mi < 2; mi++)                                          \
            _Pragma("unroll")                                                   \
            for (int ni = 0; ni < 8; ni++)                                      \
                _Pragma("unroll")                                               \
                for (int q = 0; q < 4; q++) acc[mi][ni][q] = 0.f;               \
    } while (0)

// ================= Kernel P: proj = obj @ {w1a_top^T, w1a_bot^T} =================
__global__ __launch_bounds__(256, 2)
void proj_kernel(const float* __restrict__ obj, const __half* __restrict__ wt,
                 float* __restrict__ proj, int O)
{
    extern __shared__ unsigned smu[];
    unsigned* As = smu;
    unsigned* Wb = smu + 128 * PADK;

    const int tid  = threadIdx.x;
    const int lane = tid & 31;
    const int g    = lane >> 2;
    const int tg   = lane & 3;
    const int w    = tid >> 5;
    const int R0   = (w >> 1) * 32;
    const int C0   = (w & 1) * 64;
    const int o0   = blockIdx.x * 128;

#pragma unroll
    for (int p = 0; p < 16; p++) {
        int idx = p * 256 + tid;
        int r = idx >> 5, c4 = idx & 31;
        int o = o0 + r;
        float4 v = make_float4(0.f, 0.f, 0.f, 0.f);
        if (o < O) v = *(const float4*)(obj + (size_t)o * 128 + c4 * 4);
        *(uint2*)(As + r * PADK + c4 * 2) = make_uint2(pk2(v.x, v.y), pk2(v.z, v.w));
    }

    auto stageW = [&](int buf, const __half* src) {
        unsigned* d = Wb + buf * 128 * PADK;
        const uint4* s = (const uint4*)src;
#pragma unroll
        for (int p = 0; p < 8; p++) {
            int idx = p * 256 + tid;
            int n = idx >> 4, c = idx & 15;
            *(uint4*)(d + n * PADK + c * 4) = s[idx];
        }
    };

    stageW(0, wt);                         // tile 0 = w1a_top^T
    __syncthreads();
    stageW(1, wt + 2 * 16384);             // tile 2 = w1a_bot^T

    float acc[2][8][4];
    for (int m = 0; m < 2; m++) {
        ZERO_ACC8(acc);
        const unsigned* Wu = Wb + m * 128 * PADK;
        MMA_KLOOP(As, Wu, acc, R0, C0, g, tg);
#pragma unroll
        for (int mi = 0; mi < 2; mi++) {
            int ra = R0 + mi * 16 + g;
            int rb = ra + 8;
            int oa = o0 + ra, ob = o0 + rb;
#pragma unroll
            for (int ni = 0; ni < 8; ni++) {
                int cb = C0 + ni * 8;
                float p0 = acc[mi][ni][0], p1 = acc[mi][ni][1];
                float q0 = acc[mi][ni][2], q1 = acc[mi][ni][3];
                float pp0 = __shfl_xor_sync(0xFFFFFFFF, p0, 1);
                float pp1 = __shfl_xor_sync(0xFFFFFFFF, p1, 1);
                float qq0 = __shfl_xor_sync(0xFFFFFFFF, q0, 1);
                float qq1 = __shfl_xor_sync(0xFFFFFFFF, q1, 1);
                if (!(tg & 1)) {
                    if (oa < O)
                        *(float4*)(proj + (size_t)oa * 256 + m * 128 + cb + 2 * tg) =
                            make_float4(p0, p1, pp0, pp1);
                } else {
                    if (ob < O)
                        *(float4*)(proj + (size_t)ob * 256 + m * 128 + cb + 2 * (tg - 1)) =
                            make_float4(qq0, qq1, q0, q1);
                }
            }
        }
        __syncthreads();
    }
}

// ================= Kernel B: object MLP (fp16 MMA) =================
__global__ __launch_bounds__(256, 2)
void obj_kernel(const __half* __restrict__ wt,
                const float* __restrict__ b2a, const float* __restrict__ b2b,
                const float* __restrict__ pooled, const float* __restrict__ counts,
                float* __restrict__ outO, int O)
{
    extern __shared__ unsigned smu[];
    unsigned* As = smu;
    unsigned* Wu = smu + 128 * PADK;
    float* invc = (float*)(smu + 2 * 128 * PADK);

    const int tid  = threadIdx.x;
    const int lane = tid & 31;
    const int g    = lane >> 2;
    const int tg   = lane & 3;
    const int w    = tid >> 5;
    const int R0   = (w >> 1) * 32;
    const int C0   = (w & 1) * 64;
    const int o0   = blockIdx.x * 128;

    if (tid < 128) {
        int o = o0 + tid;
        float c = (o < O) ? counts[o] : 1.f;
        c = fminf(fmaxf(c, 1.f), 1000.f);
        invc[tid] = 1.f / c;
    }

    auto stageW = [&](const __half* src) {
        const uint4* s = (const uint4*)src;
#pragma unroll
        for (int p = 0; p < 8; p++) {
            int idx = p * 256 + tid;
            int n = idx >> 4, c = idx & 15;
            *(uint4*)(Wu + n * PADK + c * 4) = s[idx];
        }
    };

    stageW(wt + 6 * 16384);                // w2a^T
    __syncthreads();

#pragma unroll
    for (int p = 0; p < 16; p++) {
        int idx = p * 256 + tid;
        int r = idx >> 5, c4 = idx & 31;
        int o = o0 + r;
        float4 v = make_float4(0.f, 0.f, 0.f, 0.f);
        if (o < O) v = *(const float4*)(pooled + (size_t)o * 128 + c4 * 4);
        float s = invc[r];
        *(uint2*)(As + r * PADK + c4 * 2) =
            make_uint2(pk2(v.x * s, v.y * s), pk2(v.z * s, v.w * s));
    }
    __syncthreads();

    float acc[2][8][4];
    ZERO_ACC8(acc);
    MMA_KLOOP(As, Wu, acc, R0, C0, g, tg);
    __syncthreads();

#pragma unroll
    for (int mi = 0; mi < 2; mi++) {
        int ra = R0 + mi * 16 + g;
        int rb = ra + 8;
#pragma unroll
        for (int ni = 0; ni < 8; ni++) {
            int c = C0 + ni * 8 + 2 * tg;
            float2 bv = *(const float2*)(b2a + c);
            As[ra * PADK + (c >> 1)] = pk2(fmaxf(acc[mi][ni][0] + bv.x, 0.f),
                                           fmaxf(acc[mi][ni][1] + bv.y, 0.f));
            As[rb * PADK + (c >> 1)] = pk2(fmaxf(acc[mi][ni][2] + bv.x, 0.f),
                                           fmaxf(acc[mi][ni][3] + bv.y, 0.f));
        }
    }
    stageW(wt + 7 * 16384);
    __syncthreads();

    ZERO_ACC8(acc);
    MMA_KLOOP(As, Wu, acc, R0, C0, g, tg);
#pragma unroll
    for (int mi = 0; mi < 2; mi++) {
        int ra = R0 + mi * 16 + g;
        int rb = ra + 8;
        int oa = o0 + ra, ob = o0 + rb;
#pragma unroll
        for (int ni = 0; ni < 8; ni++) {
            int cb = C0 + ni * 8;
            float2 bv = *(const float2*)(b2b + cb + 2 * tg);
            float p0 = fmaxf(acc[mi][ni][0] + bv.x, 0.f);
            float p1 = fmaxf(acc[mi][ni][1] + bv.y, 0.f);
            float q0 = fmaxf(acc[mi][ni][2] + bv.x, 0.f);
            float q1 = fmaxf(acc[mi][ni][3] + bv.y, 0.f);
            float pp0 = __shfl_xor_sync(0xFFFFFFFF, p0, 1);
            float pp1 = __shfl_xor_sync(0xFFFFFFFF, p1, 1);
            float qq0 = __shfl_xor_sync(0xFFFFFFFF, q0, 1);
            float qq1 = __shfl_xor_sync(0xFFFFFFFF, q1, 1);
            if (!(tg & 1)) {
                if (oa < O)
                    *(float4*)(outO + (size_t)oa * 128 + cb + 2 * tg) =
                        make_float4(p0, p1, pp0, pp1);
            } else {
                if (ob < O)
                    *(float4*)(outO + (size_t)ob * 128 + cb + 2 * (tg - 1)) =
                        make_float4(qq0, qq1, q0, q1);
            }
        }
    }
}

// ================= launch =================
extern "C" void kernel_launch(void* const* d_in, const int* in_sizes, int n_in,
                              void* d_out, int out_size)
{
    const float* obj   = (const float*)d_in[0];
    const float* predi = (const float*)d_in[1];
    const int*   edges = (const int*)d_in[2];
    const float* w1a   = (const float*)d_in[3];
    const float* b1a   = (const float*)d_in[4];
    const float* w1b   = (const float*)d_in[5];
    const float* b1b   = (const float*)d_in[6];
    const float* w2a   = (const float*)d_in[7];
    const float* b2a   = (const float*)d_in[8];
    const float* w2b   = (const float*)d_in[9];
    const float* b2b   = (const float*)d_in[10];

    const int O = in_sizes[0] / 128;
    const int T = in_sizes[1] / 128;

    float* outO = (float*)d_out;
    float* outP = outO + (size_t)O * 128;

    float *pooled = nullptr, *counts = nullptr, *proj = nullptr;
    __half* wt = nullptr;
    cudaGetSymbolAddress((void**)&pooled, g_pooled);
    cudaGetSymbolAddress((void**)&counts, g_counts);
    cudaGetSymbolAddress((void**)&proj,   g_proj);
    cudaGetSymbolAddress((void**)&wt,     g_wt);

    cudaMemsetAsync(pooled, 0, (size_t)O * 128 * sizeof(float));
    cudaMemsetAsync(counts, 0, (size_t)O * sizeof(float));

    const size_t smT = (size_t)(MT * PADK + 2 * 128 * PADW2) * 4 + MT * 2 * 4 + 256;
    const size_t smP = (size_t)(3 * 128 * PADK) * 4;
    const size_t smB = (size_t)(2 * 128 * PADK) * 4 + 512;

    cudaFuncSetAttribute(proj_kernel,   cudaFuncAttributeMaxDynamicSharedMemorySize, (int)smP);
    cudaFuncSetAttribute(triple_kernel, cudaFuncAttributeMaxDynamicSharedMemorySize, (int)smT);
    cudaFuncSetAttribute(obj_kernel,    cudaFuncAttributeMaxDynamicSharedMemorySize, (int)smB);

    prep_kernel<<<8, 256>>>(w1a, w1b, w2a, w2b, wt);
    proj_kernel<<<(O + 127) / 128, 256, smP>>>(obj, wt, proj, O);
    triple_kernel<<<(T + MT - 1) / MT, 256, smT>>>(predi, edges, wt, b1a, b1b, proj,
                                                   outP, pooled, counts, T);
    obj_kernel<<<(O + 127) / 128, 256, smB>>>(wt, b2a, b2b, pooled, counts, outO, O);
}

// round 10
// speedup vs baseline: 4.6555x; 1.0364x over previous
#include <cuda_runtime.h>
#include <cuda_fp16.h>
#include <cstdint>
#include <cstddef>

// ---------------- scratch (no allocs allowed) ----------------
#define O_CAP 100000
static __device__ float g_pooled[(size_t)O_CAP * 128];
static __device__ float g_counts[O_CAP];
static __device__ __half g_proj[(size_t)O_CAP * 256];   // half: 50MB -> L2-resident
// 8 pre-transposed half tiles [n=128][k=128]:
// 0,1,2: w1a k-rows [0:128),[128:256),[256:384);  3,4,5: w1b nc 0..2;  6: w2a; 7: w2b
static __device__ __half g_wt[8 * 128 * 128];

#define PADK  68   // As row stride (words): 64 data + 4 pad -> conflict-free
#define PADW2 36   // half-K W row stride (words): 32 data + 4 pad -> conflict-free
#define MT    64   // triples per block in triple_kernel

// ---------------- helpers ----------------
__device__ __forceinline__ unsigned pk2(float x, float y) {
    __half2 h = __floats2half2_rn(x, y);
    return *reinterpret_cast<unsigned*>(&h);
}
__device__ __forceinline__ void mma_f16(float c[4], const unsigned a[4], const unsigned b[2]) {
    asm volatile(
        "mma.sync.aligned.m16n8k16.row.col.f32.f16.f16.f32 "
        "{%0,%1,%2,%3},{%4,%5,%6,%7},{%8,%9},{%0,%1,%2,%3};\n"
        : "+f"(c[0]), "+f"(c[1]), "+f"(c[2]), "+f"(c[3])
        : "r"(a[0]), "r"(a[1]), "r"(a[2]), "r"(a[3]), "r"(b[0]), "r"(b[1]));
}
__device__ __forceinline__ void red_add_v4(float* p, float a, float b, float c, float d) {
    asm volatile("red.global.add.v4.f32 [%0], {%1,%2,%3,%4};"
                 :: "l"(p), "f"(a), "f"(b), "f"(c), "f"(d) : "memory");
}
__device__ __forceinline__ void cp16(void* dst, const void* src) {
    unsigned d = (unsigned)__cvta_generic_to_shared(dst);
    asm volatile("cp.async.cg.shared.global [%0], [%1], 16;" :: "r"(d), "l"(src) : "memory");
}
#define CP_COMMIT() asm volatile("cp.async.commit_group;" ::: "memory")
#define CP_WAIT0()  asm volatile("cp.async.wait_group 0;" ::: "memory")

// ================= prep: transpose+convert weights to half [n][k] =================
__global__ void prep_kernel(const float* __restrict__ w1a, const float* __restrict__ w1b,
                            const float* __restrict__ w2a, const float* __restrict__ w2b,
                            __half* __restrict__ wt)
{
    const int t = blockIdx.x;           // 0..7
    const int tid = threadIdx.x;
    for (int p = 0; p < 64; p++) {
        int idx = p * 256 + tid;        // 0..16383
        int n = idx >> 7, k = idx & 127;
        float v;
        if (t < 3)       v = w1a[(size_t)(t * 128 + k) * 128 + n];
        else if (t < 6)  v = w1b[(size_t)k * 384 + (t - 3) * 128 + n];
        else if (t == 6) v = w2a[(size_t)k * 128 + n];
        else             v = w2b[(size_t)k * 128 + n];
        wt[((size_t)t * 128 + n) * 128 + k] = __float2half_rn(v);
    }
}

// ================= Kernel A: triple MLP, 64-row tiles, m32n32 warps, cp.async W =================
__global__ __launch_bounds__(256, 3)
void triple_kernel(const float* __restrict__ predi, const int* __restrict__ edges,
                   const __half* __restrict__ wt,
                   const float* __restrict__ b1a, const float* __restrict__ b1b,
                   const __half* __restrict__ proj,
                   float* __restrict__ outP, float* __restrict__ pooled,
                   float* __restrict__ counts, int T)
{
    extern __shared__ unsigned smu[];
    unsigned* As = smu;                            // MT*PADK
    unsigned* Wb = smu + MT * PADK;                // 2 * 128*PADW2
    int* sIdx = (int*)(smu + MT * PADK + 2 * 128 * PADW2);
    int* oIdx = sIdx + MT;

    const int tid  = threadIdx.x;
    const int lane = tid & 31;
    const int g    = lane >> 2;
    const int tg   = lane & 3;
    const int w    = tid >> 5;
    const int R0   = (w >> 2) * 32;                // 2 row groups x 32 = 64 rows
    const int C0   = (w & 3) * 32;                 // 4 col groups x 32 = 128 cols
    const int t0   = blockIdx.x * MT;

    // cp.async stage: one half-K chunk [128n][32 words] of a tile
    auto stageW = [&](int buf, const __half* tile, int half) {
        unsigned* dstBase = Wb + buf * 128 * PADW2;
#pragma unroll
        for (int p = 0; p < 4; p++) {
            int idx = p * 256 + tid;               // 0..1023
            int n = idx >> 3, c8 = idx & 7;
            cp16(dstBase + n * PADW2 + c8 * 4, tile + n * 128 + half * 64 + c8 * 8);
        }
        CP_COMMIT();
    };

    // chunk schedule: tiles {1,1,3,3,4,4,5,5}, half = i&1
    stageW(0, wt + 1 * 16384, 0);

    if (tid < MT) {
        int t = t0 + tid;
        int s = 0, o = 0;
        if (t < T) {
            s = edges[2 * t];
            o = edges[2 * t + 1];
            atomicAdd(&counts[s], 1.0f);
            atomicAdd(&counts[o], 1.0f);
        }
        sIdx[tid] = s; oIdx[tid] = o;
    }

    // stage A = half(predi tile): MT rows x 32 float4 = 2048 items
#pragma unroll
    for (int p = 0; p < 8; p++) {
        int idx = p * 256 + tid;
        int r = idx >> 5, c4 = idx & 31;
        int t = t0 + r;
        float4 v = make_float4(0.f, 0.f, 0.f, 0.f);
        if (t < T) v = *(const float4*)(predi + (size_t)t * 128 + c4 * 4);
        *(uint2*)(As + r * PADK + c4 * 2) = make_uint2(pk2(v.x, v.y), pk2(v.z, v.w));
    }
    CP_WAIT0();
    __syncthreads();

    float acc[2][4][4];
#pragma unroll
    for (int mi = 0; mi < 2; mi++)
#pragma unroll
        for (int ni = 0; ni < 4; ni++)
#pragma unroll
            for (int q = 0; q < 4; q++) acc[mi][ni][q] = 0.f;

    for (int i = 0; i < 8; i++) {
        if (i < 7) {
            int tile2 = (i + 1) < 2 ? 1 : 3 + ((i - 1) >> 1);
            stageW((i + 1) & 1, wt + (size_t)tile2 * 16384, (i + 1) & 1);
        }
        const unsigned* Wu = Wb + (i & 1) * 128 * PADW2;
        const int kwA0 = (i & 1) * 32;
#pragma unroll
        for (int ks = 0; ks < 4; ks++) {
            const int kwA = kwA0 + ks * 8;
            const int kwB = ks * 8;
            unsigned a[2][4], b[4][2];
#pragma unroll
            for (int mi = 0; mi < 2; mi++) {
                int r = R0 + mi * 16 + g;
                a[mi][0] = As[r * PADK + kwA + tg];
                a[mi][1] = As[(r + 8) * PADK + kwA + tg];
                a[mi][2] = As[r * PADK + kwA + 4 + tg];
                a[mi][3] = As[(r + 8) * PADK + kwA + 4 + tg];
            }
#pragma unroll
            for (int ni = 0; ni < 4; ni++) {
                int c = C0 + ni * 8 + g;
                b[ni][0] = Wu[c * PADW2 + kwB + tg];
                b[ni][1] = Wu[c * PADW2 + kwB + 4 + tg];
            }
#pragma unroll
            for (int mi = 0; mi < 2; mi++)
#pragma unroll
                for (int ni = 0; ni < 4; ni++)
                    mma_f16(acc[mi][ni], a[mi], b[ni]);
        }
        CP_WAIT0();
        __syncthreads();

        if (i == 1) {
            // GEMM1 epilogue: H = half(relu(acc + b1a + proj_s + proj_o)) -> As
#pragma unroll
            for (int mi = 0; mi < 2; mi++) {
                int ra = R0 + mi * 16 + g;
                int rb = ra + 8;
                const __half* psA = proj + (size_t)sIdx[ra] * 256;
                const __half* poA = proj + (size_t)oIdx[ra] * 256 + 128;
                const __half* psB = proj + (size_t)sIdx[rb] * 256;
                const __half* poB = proj + (size_t)oIdx[rb] * 256 + 128;
#pragma unroll
                for (int ni = 0; ni < 4; ni++) {
                    int c = C0 + ni * 8 + 2 * tg;
                    float2 bv = *(const float2*)(b1a + c);
                    float2 sa = __half22float2(*(const __half2*)(psA + c));
                    float2 oa = __half22float2(*(const __half2*)(poA + c));
                    float2 sb = __half22float2(*(const __half2*)(psB + c));
                    float2 ob = __half22float2(*(const __half2*)(poB + c));
                    As[ra * PADK + (c >> 1)] =
                        pk2(fmaxf(acc[mi][ni][0] + bv.x + sa.x + oa.x, 0.f),
                            fmaxf(acc[mi][ni][1] + bv.y + sa.y + oa.y, 0.f));
                    As[rb * PADK + (c >> 1)] =
                        pk2(fmaxf(acc[mi][ni][2] + bv.x + sb.x + ob.x, 0.f),
                            fmaxf(acc[mi][ni][3] + bv.y + sb.y + ob.y, 0.f));
                }
            }
            __syncthreads();
#pragma unroll
            for (int mi = 0; mi < 2; mi++)
#pragma unroll
                for (int ni = 0; ni < 4; ni++)
#pragma unroll
                    for (int q = 0; q < 4; q++) acc[mi][ni][q] = 0.f;
        } else if (i >= 3 && (i & 1)) {
            // GEMM2 epilogue for nc = (i-2)>>1
            const int nc = (i - 2) >> 1;
            const int boff = nc * 128;
#pragma unroll
            for (int mi = 0; mi < 2; mi++) {
                int ra = R0 + mi * 16 + g;
                int rb = ra + 8;
                int ta = t0 + ra, tb = t0 + rb;
                float* dA;
                float* dB;
                if (nc == 1) { dA = outP + (size_t)ta * 128; dB = outP + (size_t)tb * 128; }
                else {
                    const int* ridx = nc ? oIdx : sIdx;
                    dA = pooled + (size_t)ridx[ra] * 128;
                    dB = pooled + (size_t)ridx[rb] * 128;
                }
#pragma unroll
                for (int ni = 0; ni < 4; ni++) {
                    int cb = C0 + ni * 8;
                    float2 bv = *(const float2*)(b1b + boff + cb + 2 * tg);
                    float p0 = fmaxf(acc[mi][ni][0] + bv.x, 0.f);
                    float p1 = fmaxf(acc[mi][ni][1] + bv.y, 0.f);
                    float q0 = fmaxf(acc[mi][ni][2] + bv.x, 0.f);
                    float q1 = fmaxf(acc[mi][ni][3] + bv.y, 0.f);
                    float pp0 = __shfl_xor_sync(0xFFFFFFFF, p0, 1);
                    float pp1 = __shfl_xor_sync(0xFFFFFFFF, p1, 1);
                    float qq0 = __shfl_xor_sync(0xFFFFFFFF, q0, 1);
                    float qq1 = __shfl_xor_sync(0xFFFFFFFF, q1, 1);
                    if (nc == 1) {
                        if (!(tg & 1)) {
                            if (ta < T) *(float4*)(dA + cb + 2 * tg) = make_float4(p0, p1, pp0, pp1);
                        } else {
                            if (tb < T) *(float4*)(dB + cb + 2 * (tg - 1)) = make_float4(qq0, qq1, q0, q1);
                        }
                    } else {
                        if (!(tg & 1)) {
                            if (ta < T) red_add_v4(dA + cb + 2 * tg, p0, p1, pp0, pp1);
                        } else {
                            if (tb < T) red_add_v4(dB + cb + 2 * (tg - 1), qq0, qq1, q0, q1);
                        }
                    }
                }
            }
            if (i < 7) {
#pragma unroll
                for (int mi = 0; mi < 2; mi++)
#pragma unroll
                    for (int ni = 0; ni < 4; ni++)
#pragma unroll
                        for (int q = 0; q < 4; q++) acc[mi][ni][q] = 0.f;
            }
        }
    }
}

// ---------------- shared m32n64 mainloop for proj/obj ----------------
#define MMA_KLOOP(As, Wu, acc, R0, C0, g, tg)                                   \
    do {                                                                        \
        _Pragma("unroll")                                                       \
        for (int ks = 0; ks < 8; ks++) {                                        \
            const int kw = ks * 8;                                              \
            unsigned a[2][4], b[8][2];                                          \
            _Pragma("unroll")                                                   \
            for (int mi = 0; mi < 2; mi++) {                                    \
                int r = (R0) + mi * 16 + (g);                                   \
                a[mi][0] = (As)[r * PADK + kw + (tg)];                          \
                a[mi][1] = (As)[(r + 8) * PADK + kw + (tg)];                    \
                a[mi][2] = (As)[r * PADK + kw + 4 + (tg)];                      \
                a[mi][3] = (As)[(r + 8) * PADK + kw + 4 + (tg)];                \
            }                                                                   \
            _Pragma("unroll")                                                   \
            for (int ni = 0; ni < 8; ni++) {                                    \
                int c = (C0) + ni * 8 + (g);                                    \
                b[ni][0] = (Wu)[c * PADK + kw + (tg)];                          \
                b[ni][1] = (Wu)[c * PADK + kw + 4 + (tg)];                      \
            }                                                                   \
            _Pragma("unroll")                                                   \
            for (int mi = 0; mi < 2; mi++)                                      \
                _Pragma("unroll")                                               \
                for (int ni = 0; ni < 8; ni++)                                  \
                    mma_f16(acc[mi][ni], a[mi], b[ni]);                         \
        }                                                                       \
    } while (0)

#define ZERO_ACC8(acc)                                                          \
    do {                                                                        \
        _Pragma("unroll")                                                       \
        for (int mi = 0; mi < 2; mi++)                                          \
            _Pragma("unroll")                                                   \
            for (int ni = 0; ni < 8; ni++)                                      \
                _Pragma("unroll")                                               \
                for (int q = 0; q < 4; q++) acc[mi][ni][q] = 0.f;               \
    } while (0)

// ================= Kernel P: proj = half(obj @ {w1a_top^T, w1a_bot^T}) =================
__global__ __launch_bounds__(256, 2)
void proj_kernel(const float* __restrict__ obj, const __half* __restrict__ wt,
                 __half* __restrict__ proj, int O)
{
    extern __shared__ unsigned smu[];
    unsigned* As = smu;
    unsigned* Wb = smu + 128 * PADK;

    const int tid  = threadIdx.x;
    const int lane = tid & 31;
    const int g    = lane >> 2;
    const int tg   = lane & 3;
    const int w    = tid >> 5;
    const int R0   = (w >> 1) * 32;
    const int C0   = (w & 1) * 64;
    const int o0   = blockIdx.x * 128;

#pragma unroll
    for (int p = 0; p < 16; p++) {
        int idx = p * 256 + tid;
        int r = idx >> 5, c4 = idx & 31;
        int o = o0 + r;
        float4 v = make_float4(0.f, 0.f, 0.f, 0.f);
        if (o < O) v = *(const float4*)(obj + (size_t)o * 128 + c4 * 4);
        *(uint2*)(As + r * PADK + c4 * 2) = make_uint2(pk2(v.x, v.y), pk2(v.z, v.w));
    }

    auto stageW = [&](int buf, const __half* src) {
        unsigned* d = Wb + buf * 128 * PADK;
        const uint4* s = (const uint4*)src;
#pragma unroll
        for (int p = 0; p < 8; p++) {
            int idx = p * 256 + tid;
            int n = idx >> 4, c = idx & 15;
            *(uint4*)(d + n * PADK + c * 4) = s[idx];
        }
    };

    stageW(0, wt);                         // tile 0 = w1a_top^T
    __syncthreads();
    stageW(1, wt + 2 * 16384);             // tile 2 = w1a_bot^T

    float acc[2][8][4];
    for (int m = 0; m < 2; m++) {
        ZERO_ACC8(acc);
        const unsigned* Wu = Wb + m * 128 * PADK;
        MMA_KLOOP(As, Wu, acc, R0, C0, g, tg);
#pragma unroll
        for (int mi = 0; mi < 2; mi++) {
            int ra = R0 + mi * 16 + g;
            int rb = ra + 8;
            int oa = o0 + ra, ob = o0 + rb;
#pragma unroll
            for (int ni = 0; ni < 8; ni++) {
                int cb = C0 + ni * 8;
                float p0 = acc[mi][ni][0], p1 = acc[mi][ni][1];
                float q0 = acc[mi][ni][2], q1 = acc[mi][ni][3];
                float pp0 = __shfl_xor_sync(0xFFFFFFFF, p0, 1);
                float pp1 = __shfl_xor_sync(0xFFFFFFFF, p1, 1);
                float qq0 = __shfl_xor_sync(0xFFFFFFFF, q0, 1);
                float qq1 = __shfl_xor_sync(0xFFFFFFFF, q1, 1);
                if (!(tg & 1)) {
                    if (oa < O)
                        *(uint2*)(proj + (size_t)oa * 256 + m * 128 + cb + 2 * tg) =
                            make_uint2(pk2(p0, p1), pk2(pp0, pp1));
                } else {
                    if (ob < O)
                        *(uint2*)(proj + (size_t)ob * 256 + m * 128 + cb + 2 * (tg - 1)) =
                            make_uint2(pk2(qq0, qq1), pk2(q0, q1));
                }
            }
        }
        __syncthreads();
    }
}

// ================= Kernel B: object MLP (fp16 MMA) =================
__global__ __launch_bounds__(256, 2)
void obj_kernel(const __half* __restrict__ wt,
                const float* __restrict__ b2a, const float* __restrict__ b2b,
                const float* __restrict__ pooled, const float* __restrict__ counts,
                float* __restrict__ outO, int O)
{
    extern __shared__ unsigned smu[];
    unsigned* As = smu;
    unsigned* Wu = smu + 128 * PADK;
    float* invc = (float*)(smu + 2 * 128 * PADK);

    const int tid  = threadIdx.x;
    const int lane = tid & 31;
    const int g    = lane >> 2;
    const int tg   = lane & 3;
    const int w    = tid >> 5;
    const int R0   = (w >> 1) * 32;
    const int C0   = (w & 1) * 64;
    const int o0   = blockIdx.x * 128;

    if (tid < 128) {
        int o = o0 + tid;
        float c = (o < O) ? counts[o] : 1.f;
        c = fminf(fmaxf(c, 1.f), 1000.f);
        invc[tid] = 1.f / c;
    }

    auto stageW = [&](const __half* src) {
        const uint4* s = (const uint4*)src;
#pragma unroll
        for (int p = 0; p < 8; p++) {
            int idx = p * 256 + tid;
            int n = idx >> 4, c = idx & 15;
            *(uint4*)(Wu + n * PADK + c * 4) = s[idx];
        }
    };

    stageW(wt + 6 * 16384);                // w2a^T
    __syncthreads();

#pragma unroll
    for (int p = 0; p < 16; p++) {
        int idx = p * 256 + tid;
        int r = idx >> 5, c4 = idx & 31;
        int o = o0 + r;
        float4 v = make_float4(0.f, 0.f, 0.f, 0.f);
        if (o < O) v = *(const float4*)(pooled + (size_t)o * 128 + c4 * 4);
        float s = invc[r];
        *(uint2*)(As + r * PADK + c4 * 2) =
            make_uint2(pk2(v.x * s, v.y * s), pk2(v.z * s, v.w * s));
    }
    __syncthreads();

    float acc[2][8][4];
    ZERO_ACC8(acc);
    MMA_KLOOP(As, Wu, acc, R0, C0, g, tg);
    __syncthreads();

#pragma unroll
    for (int mi = 0; mi < 2; mi++) {
        int ra = R0 + mi * 16 + g;
        int rb = ra + 8;
#pragma unroll
        for (int ni = 0; ni < 8; ni++) {
            int c = C0 + ni * 8 + 2 * tg;
            float2 bv = *(const float2*)(b2a + c);
            As[ra * PADK + (c >> 1)] = pk2(fmaxf(acc[mi][ni][0] + bv.x, 0.f),
                                           fmaxf(acc[mi][ni][1] + bv.y, 0.f));
            As[rb * PADK + (c >> 1)] = pk2(fmaxf(acc[mi][ni][2] + bv.x, 0.f),
                                           fmaxf(acc[mi][ni][3] + bv.y, 0.f));
        }
    }
    stageW(wt + 7 * 16384);
    __syncthreads();

    ZERO_ACC8(acc);
    MMA_KLOOP(As, Wu, acc, R0, C0, g, tg);
#pragma unroll
    for (int mi = 0; mi < 2; mi++) {
        int ra = R0 + mi * 16 + g;
        int rb = ra + 8;
        int oa = o0 + ra, ob = o0 + rb;
#pragma unroll
        for (int ni = 0; ni < 8; ni++) {
            int cb = C0 + ni * 8;
            float2 bv = *(const float2*)(b2b + cb + 2 * tg);
            float p0 = fmaxf(acc[mi][ni][0] + bv.x, 0.f);
            float p1 = fmaxf(acc[mi][ni][1] + bv.y, 0.f);
            float q0 = fmaxf(acc[mi][ni][2] + bv.x, 0.f);
            float q1 = fmaxf(acc[mi][ni][3] + bv.y, 0.f);
            float pp0 = __shfl_xor_sync(0xFFFFFFFF, p0, 1);
            float pp1 = __shfl_xor_sync(0xFFFFFFFF, p1, 1);
            float qq0 = __shfl_xor_sync(0xFFFFFFFF, q0, 1);
            float qq1 = __shfl_xor_sync(0xFFFFFFFF, q1, 1);
            if (!(tg & 1)) {
                if (oa < O)
                    *(float4*)(outO + (size_t)oa * 128 + cb + 2 * tg) =
                        make_float4(p0, p1, pp0, pp1);
            } else {
                if (ob < O)
                    *(float4*)(outO + (size_t)ob * 128 + cb + 2 * (tg - 1)) =
                        make_float4(qq0, qq1, q0, q1);
            }
        }
    }
}

// ================= launch =================
extern "C" void kernel_launch(void* const* d_in, const int* in_sizes, int n_in,
                              void* d_out, int out_size)
{
    const float* obj   = (const float*)d_in[0];
    const float* predi = (const float*)d_in[1];
    const int*   edges = (const int*)d_in[2];
    const float* w1a   = (const float*)d_in[3];
    const float* b1a   = (const float*)d_in[4];
    const float* w1b   = (const float*)d_in[5];
    const float* b1b   = (const float*)d_in[6];
    const float* w2a   = (const float*)d_in[7];
    const float* b2a   = (const float*)d_in[8];
    const float* w2b   = (const float*)d_in[9];
    const float* b2b   = (const float*)d_in[10];

    const int O = in_sizes[0] / 128;
    const int T = in_sizes[1] / 128;

    float* outO = (float*)d_out;
    float* outP = outO + (size_t)O * 128;

    float *pooled = nullptr, *counts = nullptr;
    __half *proj = nullptr, *wt = nullptr;
    cudaGetSymbolAddress((void**)&pooled, g_pooled);
    cudaGetSymbolAddress((void**)&counts, g_counts);
    cudaGetSymbolAddress((void**)&proj,   g_proj);
    cudaGetSymbolAddress((void**)&wt,     g_wt);

    cudaMemsetAsync(pooled, 0, (size_t)O * 128 * sizeof(float));
    cudaMemsetAsync(counts, 0, (size_t)O * sizeof(float));

    const size_t smT = (size_t)(MT * PADK + 2 * 128 * PADW2) * 4 + MT * 2 * 4 + 256;
    const size_t smP = (size_t)(3 * 128 * PADK) * 4;
    const size_t smB = (size_t)(2 * 128 * PADK) * 4 + 512;

    cudaFuncSetAttribute(proj_kernel,   cudaFuncAttributeMaxDynamicSharedMemorySize, (int)smP);
    cudaFuncSetAttribute(triple_kernel, cudaFuncAttributeMaxDynamicSharedMemorySize, (int)smT);
    cudaFuncSetAttribute(obj_kernel,    cudaFuncAttributeMaxDynamicSharedMemorySize, (int)smB);

    prep_kernel<<<8, 256>>>(w1a, w1b, w2a, w2b, wt);
    proj_kernel<<<(O + 127) / 128, 256, smP>>>(obj, wt, proj, O);
    triple_kernel<<<(T + MT - 1) / MT, 256, smT>>>(predi, edges, wt, b1a, b1b, proj,
                                                   outP, pooled, counts, T);
    obj_kernel<<<(O + 127) / 128, 256, smB>>>(wt, b2a, b2b, pooled, counts, outO, O);
}

// round 11
// speedup vs baseline: 4.7854x; 1.0279x over previous
#include <cuda_runtime.h>
#include <cuda_fp16.h>
#include <cstdint>
#include <cstddef>

// ---------------- scratch (no allocs allowed) ----------------
#define O_CAP 100000
static __device__ float g_pooled[(size_t)O_CAP * 128];
static __device__ float g_counts[O_CAP];
static __device__ __half g_proj[(size_t)O_CAP * 256];   // half: 50MB -> L2-resident
// 8 pre-transposed half tiles [n=128][k=128]:
// 0,1,2: w1a k-rows [0:128),[128:256),[256:384);  3,4,5: w1b nc 0..2;  6: w2a; 7: w2b
static __device__ __half g_wt[8 * 128 * 128];

#define PADK  68   // As row stride (words): 64 data + 4 pad -> conflict-free, 272B = 17*16
#define PADW2 36   // half-K W row stride (words): 32 data + 4 pad -> conflict-free, 144B = 9*16
#define MT    64   // triples per block in triple_kernel

// ---------------- helpers ----------------
__device__ __forceinline__ unsigned pk2(float x, float y) {
    __half2 h = __floats2half2_rn(x, y);
    return *reinterpret_cast<unsigned*>(&h);
}
__device__ __forceinline__ void mma_f16(float c[4], const unsigned a[4], const unsigned b[2]) {
    asm volatile(
        "mma.sync.aligned.m16n8k16.row.col.f32.f16.f16.f32 "
        "{%0,%1,%2,%3},{%4,%5,%6,%7},{%8,%9},{%0,%1,%2,%3};\n"
        : "+f"(c[0]), "+f"(c[1]), "+f"(c[2]), "+f"(c[3])
        : "r"(a[0]), "r"(a[1]), "r"(a[2]), "r"(a[3]), "r"(b[0]), "r"(b[1]));
}
__device__ __forceinline__ void ldsm_x4(unsigned r[4], const unsigned* p) {
    unsigned addr = (unsigned)__cvta_generic_to_shared(p);
    asm volatile("ldmatrix.sync.aligned.m8n8.x4.shared.b16 {%0,%1,%2,%3}, [%4];"
                 : "=r"(r[0]), "=r"(r[1]), "=r"(r[2]), "=r"(r[3]) : "r"(addr));
}
__device__ __forceinline__ void red_add_v4(float* p, float a, float b, float c, float d) {
    asm volatile("red.global.add.v4.f32 [%0], {%1,%2,%3,%4};"
                 :: "l"(p), "f"(a), "f"(b), "f"(c), "f"(d) : "memory");
}
__device__ __forceinline__ void cp16(void* dst, const void* src) {
    unsigned d = (unsigned)__cvta_generic_to_shared(dst);
    asm volatile("cp.async.cg.shared.global [%0], [%1], 16;" :: "r"(d), "l"(src) : "memory");
}
#define CP_COMMIT() asm volatile("cp.async.commit_group;" ::: "memory")
#define CP_WAIT0()  asm volatile("cp.async.wait_group 0;" ::: "memory")

// ldmatrix lane decomposition (same for all kernels):
//   sel = lane>>3 selects the 8x8 tile (reg index), rp = lane&7 the row within it.
//   A x4: regs = {rows+0 w+0, rows+8 w+0, rows+0 w+4, rows+8 w+4}  (matches a0..a3)
//   B x4: regs = {ni w+0, ni w+4, ni+1 w+0, ni+1 w+4}              (matches b[ni][0..1],b[ni+1][0..1])

// ================= prep: transpose+convert weights to half [n][k] =================
__global__ void prep_kernel(const float* __restrict__ w1a, const float* __restrict__ w1b,
                            const float* __restrict__ w2a, const float* __restrict__ w2b,
                            __half* __restrict__ wt)
{
    const int t = blockIdx.x;           // 0..7
    const int tid = threadIdx.x;
    for (int p = 0; p < 64; p++) {
        int idx = p * 256 + tid;        // 0..16383
        int n = idx >> 7, k = idx & 127;
        float v;
        if (t < 3)       v = w1a[(size_t)(t * 128 + k) * 128 + n];
        else if (t < 6)  v = w1b[(size_t)k * 384 + (t - 3) * 128 + n];
        else if (t == 6) v = w2a[(size_t)k * 128 + n];
        else             v = w2b[(size_t)k * 128 + n];
        wt[((size_t)t * 128 + n) * 128 + k] = __float2half_rn(v);
    }
}

// ================= Kernel A: triple MLP, 64-row tiles, m32n32 warps, cp.async W =================
__global__ __launch_bounds__(256, 3)
void triple_kernel(const float* __restrict__ predi, const int* __restrict__ edges,
                   const __half* __restrict__ wt,
                   const float* __restrict__ b1a, const float* __restrict__ b1b,
                   const __half* __restrict__ proj,
                   float* __restrict__ outP, float* __restrict__ pooled,
                   float* __restrict__ counts, int T)
{
    extern __shared__ unsigned smu[];
    unsigned* As = smu;                            // MT*PADK
    unsigned* Wb = smu + MT * PADK;                // 2 * 128*PADW2
    int* sIdx = (int*)(smu + MT * PADK + 2 * 128 * PADW2);
    int* oIdx = sIdx + MT;

    const int tid  = threadIdx.x;
    const int lane = tid & 31;
    const int g    = lane >> 2;
    const int tg   = lane & 3;
    const int w    = tid >> 5;
    const int R0   = (w >> 2) * 32;                // 2 row groups x 32 = 64 rows
    const int C0   = (w & 3) * 32;                 // 4 col groups x 32 = 128 cols
    const int t0   = blockIdx.x * MT;

    // ldmatrix lane addressing
    const int rp   = lane & 7;
    const int sel  = lane >> 3;
    const int arow = ((sel & 1) << 3) + rp;
    const int acol = (sel >> 1) << 2;
    const int brow = ((sel >> 1) << 3) + rp;
    const int bcol = (sel & 1) << 2;

    // cp.async stage: one half-K chunk [128n][32 words] of a tile
    auto stageW = [&](int buf, const __half* tile, int half) {
        unsigned* dstBase = Wb + buf * 128 * PADW2;
#pragma unroll
        for (int p = 0; p < 4; p++) {
            int idx = p * 256 + tid;               // 0..1023
            int n = idx >> 3, c8 = idx & 7;
            cp16(dstBase + n * PADW2 + c8 * 4, tile + n * 128 + half * 64 + c8 * 8);
        }
        CP_COMMIT();
    };

    // chunk schedule: tiles {1,1,3,3,4,4,5,5}, half = i&1
    stageW(0, wt + 1 * 16384, 0);

    if (tid < MT) {
        int t = t0 + tid;
        int s = 0, o = 0;
        if (t < T) {
            s = edges[2 * t];
            o = edges[2 * t + 1];
            atomicAdd(&counts[s], 1.0f);
            atomicAdd(&counts[o], 1.0f);
        }
        sIdx[tid] = s; oIdx[tid] = o;
    }

    // stage A = half(predi tile): MT rows x 32 float4 = 2048 items
#pragma unroll
    for (int p = 0; p < 8; p++) {
        int idx = p * 256 + tid;
        int r = idx >> 5, c4 = idx & 31;
        int t = t0 + r;
        float4 v = make_float4(0.f, 0.f, 0.f, 0.f);
        if (t < T) v = *(const float4*)(predi + (size_t)t * 128 + c4 * 4);
        *(uint2*)(As + r * PADK + c4 * 2) = make_uint2(pk2(v.x, v.y), pk2(v.z, v.w));
    }
    CP_WAIT0();
    __syncthreads();

    float acc[2][4][4];
#pragma unroll
    for (int mi = 0; mi < 2; mi++)
#pragma unroll
        for (int ni = 0; ni < 4; ni++)
#pragma unroll
            for (int q = 0; q < 4; q++) acc[mi][ni][q] = 0.f;

    for (int i = 0; i < 8; i++) {
        if (i < 7) {
            int tile2 = (i + 1) < 2 ? 1 : 3 + ((i - 1) >> 1);
            stageW((i + 1) & 1, wt + (size_t)tile2 * 16384, (i + 1) & 1);
        }
        const unsigned* Wu = Wb + (i & 1) * 128 * PADW2;
        const int kwA0 = (i & 1) * 32;
#pragma unroll
        for (int ks = 0; ks < 4; ks++) {
            const int kwA = kwA0 + ks * 8;
            const int kwB = ks * 8;
            unsigned a[2][4], bb[2][4];
#pragma unroll
            for (int mi = 0; mi < 2; mi++)
                ldsm_x4(a[mi], As + (R0 + mi * 16 + arow) * PADK + kwA + acol);
#pragma unroll
            for (int j = 0; j < 2; j++)
                ldsm_x4(bb[j], Wu + (C0 + j * 16 + brow) * PADW2 + kwB + bcol);
#pragma unroll
            for (int mi = 0; mi < 2; mi++)
#pragma unroll
                for (int ni = 0; ni < 4; ni++)
                    mma_f16(acc[mi][ni], a[mi], &bb[ni >> 1][(ni & 1) * 2]);
        }
        CP_WAIT0();
        __syncthreads();

        if (i == 1) {
            // GEMM1 epilogue: H = half(relu(acc + b1a + proj_s + proj_o)) -> As
#pragma unroll
            for (int mi = 0; mi < 2; mi++) {
                int ra = R0 + mi * 16 + g;
                int rb = ra + 8;
                const __half* psA = proj + (size_t)sIdx[ra] * 256;
                const __half* poA = proj + (size_t)oIdx[ra] * 256 + 128;
                const __half* psB = proj + (size_t)sIdx[rb] * 256;
                const __half* poB = proj + (size_t)oIdx[rb] * 256 + 128;
#pragma unroll
                for (int ni = 0; ni < 4; ni++) {
                    int c = C0 + ni * 8 + 2 * tg;
                    float2 bv = *(const float2*)(b1a + c);
                    float2 sa = __half22float2(*(const __half2*)(psA + c));
                    float2 oa = __half22float2(*(const __half2*)(poA + c));
                    float2 sb = __half22float2(*(const __half2*)(psB + c));
                    float2 ob = __half22float2(*(const __half2*)(poB + c));
                    As[ra * PADK + (c >> 1)] =
                        pk2(fmaxf(acc[mi][ni][0] + bv.x + sa.x + oa.x, 0.f),
                            fmaxf(acc[mi][ni][1] + bv.y + sa.y + oa.y, 0.f));
                    As[rb * PADK + (c >> 1)] =
                        pk2(fmaxf(acc[mi][ni][2] + bv.x + sb.x + ob.x, 0.f),
                            fmaxf(acc[mi][ni][3] + bv.y + sb.y + ob.y, 0.f));
                }
            }
            __syncthreads();
#pragma unroll
            for (int mi = 0; mi < 2; mi++)
#pragma unroll
                for (int ni = 0; ni < 4; ni++)
#pragma unroll
                    for (int q = 0; q < 4; q++) acc[mi][ni][q] = 0.f;
        } else if (i >= 3 && (i & 1)) {
            // GEMM2 epilogue for nc = (i-2)>>1
            const int nc = (i - 2) >> 1;
            const int boff = nc * 128;
#pragma unroll
            for (int mi = 0; mi < 2; mi++) {
                int ra = R0 + mi * 16 + g;
                int rb = ra + 8;
                int ta = t0 + ra, tb = t0 + rb;
                float* dA;
                float* dB;
                if (nc == 1) { dA = outP + (size_t)ta * 128; dB = outP + (size_t)tb * 128; }
                else {
                    const int* ridx = nc ? oIdx : sIdx;
                    dA = pooled + (size_t)ridx[ra] * 128;
                    dB = pooled + (size_t)ridx[rb] * 128;
                }
#pragma unroll
                for (int ni = 0; ni < 4; ni++) {
                    int cb = C0 + ni * 8;
                    float2 bv = *(const float2*)(b1b + boff + cb + 2 * tg);
                    float p0 = fmaxf(acc[mi][ni][0] + bv.x, 0.f);
                    float p1 = fmaxf(acc[mi][ni][1] + bv.y, 0.f);
                    float q0 = fmaxf(acc[mi][ni][2] + bv.x, 0.f);
                    float q1 = fmaxf(acc[mi][ni][3] + bv.y, 0.f);
                    float pp0 = __shfl_xor_sync(0xFFFFFFFF, p0, 1);
                    float pp1 = __shfl_xor_sync(0xFFFFFFFF, p1, 1);
                    float qq0 = __shfl_xor_sync(0xFFFFFFFF, q0, 1);
                    float qq1 = __shfl_xor_sync(0xFFFFFFFF, q1, 1);
                    if (nc == 1) {
                        if (!(tg & 1)) {
                            if (ta < T) *(float4*)(dA + cb + 2 * tg) = make_float4(p0, p1, pp0, pp1);
                        } else {
                            if (tb < T) *(float4*)(dB + cb + 2 * (tg - 1)) = make_float4(qq0, qq1, q0, q1);
                        }
                    } else {
                        if (!(tg & 1)) {
                            if (ta < T) red_add_v4(dA + cb + 2 * tg, p0, p1, pp0, pp1);
                        } else {
                            if (tb < T) red_add_v4(dB + cb + 2 * (tg - 1), qq0, qq1, q0, q1);
                        }
                    }
                }
            }
            if (i < 7) {
#pragma unroll
                for (int mi = 0; mi < 2; mi++)
#pragma unroll
                    for (int ni = 0; ni < 4; ni++)
#pragma unroll
                        for (int q = 0; q < 4; q++) acc[mi][ni][q] = 0.f;
            }
        }
    }
}

// ---------------- shared m32n64 mainloop for proj/obj (ldmatrix) ----------------
#define MMA_KLOOP(As, Wu, acc, R0, C0, arow, acol, brow, bcol)                  \
    do {                                                                        \
        _Pragma("unroll")                                                       \
        for (int ks = 0; ks < 8; ks++) {                                        \
            const int kw = ks * 8;                                              \
            unsigned a[2][4], bb[4][4];                                         \
            _Pragma("unroll")                                                   \
            for (int mi = 0; mi < 2; mi++)                                      \
                ldsm_x4(a[mi], (As) + ((R0) + mi * 16 + (arow)) * PADK + kw + (acol)); \
            _Pragma("unroll")                                                   \
            for (int j = 0; j < 4; j++)                                         \
                ldsm_x4(bb[j], (Wu) + ((C0) + j * 16 + (brow)) * PADK + kw + (bcol)); \
            _Pragma("unroll")                                                   \
            for (int mi = 0; mi < 2; mi++)                                      \
                _Pragma("unroll")                                               \
                for (int ni = 0; ni < 8; ni++)                                  \
                    mma_f16(acc[mi][ni], a[mi], &bb[ni >> 1][(ni & 1) * 2]);    \
        }                                                                       \
    } while (0)

#define ZERO_ACC8(acc)                                                          \
    do {                                                                        \
        _Pragma("unroll")                                                       \
        for (int mi = 0; mi < 2; mi++)                                          \
            _Pragma("unroll")                                                   \
            for (int ni = 0; ni < 8; ni++)                                      \
                _Pragma("unroll")                                               \
                for (int q = 0; q < 4; q++) acc[mi][ni][q] = 0.f;               \
    } while (0)

// ================= Kernel P: proj = half(obj @ {w1a_top^T, w1a_bot^T}) =================
__global__ __launch_bounds__(256, 2)
void proj_kernel(const float* __restrict__ obj, const __half* __restrict__ wt,
                 __half* __restrict__ proj, int O)
{
    extern __shared__ unsigned smu[];
    unsigned* As = smu;
    unsigned* Wb = smu + 128 * PADK;

    const int tid  = threadIdx.x;
    const int lane = tid & 31;
    const int g    = lane >> 2;
    const int tg   = lane & 3;
    const int w    = tid >> 5;
    const int R0   = (w >> 1) * 32;
    const int C0   = (w & 1) * 64;
    const int o0   = blockIdx.x * 128;

    const int rp   = lane & 7;
    const int sel  = lane >> 3;
    const int arow = ((sel & 1) << 3) + rp;
    const int acol = (sel >> 1) << 2;
    const int brow = ((sel >> 1) << 3) + rp;
    const int bcol = (sel & 1) << 2;

#pragma unroll
    for (int p = 0; p < 16; p++) {
        int idx = p * 256 + tid;
        int r = idx >> 5, c4 = idx & 31;
        int o = o0 + r;
        float4 v = make_float4(0.f, 0.f, 0.f, 0.f);
        if (o < O) v = *(const float4*)(obj + (size_t)o * 128 + c4 * 4);
        *(uint2*)(As + r * PADK + c4 * 2) = make_uint2(pk2(v.x, v.y), pk2(v.z, v.w));
    }

    auto stageW = [&](int buf, const __half* src) {
        unsigned* d = Wb + buf * 128 * PADK;
        const uint4* s = (const uint4*)src;
#pragma unroll
        for (int p = 0; p < 8; p++) {
            int idx = p * 256 + tid;
            int n = idx >> 4, c = idx & 15;
            *(uint4*)(d + n * PADK + c * 4) = s[idx];
        }
    };

    stageW(0, wt);                         // tile 0 = w1a_top^T
    __syncthreads();
    stageW(1, wt + 2 * 16384);             // tile 2 = w1a_bot^T

    float acc[2][8][4];
    for (int m = 0; m < 2; m++) {
        ZERO_ACC8(acc);
        const unsigned* Wu = Wb + m * 128 * PADK;
        MMA_KLOOP(As, Wu, acc, R0, C0, arow, acol, brow, bcol);
#pragma unroll
        for (int mi = 0; mi < 2; mi++) {
            int ra = R0 + mi * 16 + g;
            int rb = ra + 8;
            int oa = o0 + ra, ob = o0 + rb;
#pragma unroll
            for (int ni = 0; ni < 8; ni++) {
                int cb = C0 + ni * 8;
                float p0 = acc[mi][ni][0], p1 = acc[mi][ni][1];
                float q0 = acc[mi][ni][2], q1 = acc[mi][ni][3];
                float pp0 = __shfl_xor_sync(0xFFFFFFFF, p0, 1);
                float pp1 = __shfl_xor_sync(0xFFFFFFFF, p1, 1);
                float qq0 = __shfl_xor_sync(0xFFFFFFFF, q0, 1);
                float qq1 = __shfl_xor_sync(0xFFFFFFFF, q1, 1);
                if (!(tg & 1)) {
                    if (oa < O)
                        *(uint2*)(proj + (size_t)oa * 256 + m * 128 + cb + 2 * tg) =
                            make_uint2(pk2(p0, p1), pk2(pp0, pp1));
                } else {
                    if (ob < O)
                        *(uint2*)(proj + (size_t)ob * 256 + m * 128 + cb + 2 * (tg - 1)) =
                            make_uint2(pk2(qq0, qq1), pk2(q0, q1));
                }
            }
        }
        __syncthreads();
    }
}

// ================= Kernel B: object MLP (fp16 MMA) =================
__global__ __launch_bounds__(256, 2)
void obj_kernel(const __half* __restrict__ wt,
                const float* __restrict__ b2a, const float* __restrict__ b2b,
                const float* __restrict__ pooled, const float* __restrict__ counts,
                float* __restrict__ outO, int O)
{
    extern __shared__ unsigned smu[];
    unsigned* As = smu;
    unsigned* Wu = smu + 128 * PADK;
    float* invc = (float*)(smu + 2 * 128 * PADK);

    const int tid  = threadIdx.x;
    const int lane = tid & 31;
    const int g    = lane >> 2;
    const int tg   = lane & 3;
    const int w    = tid >> 5;
    const int R0   = (w >> 1) * 32;
    const int C0   = (w & 1) * 64;
    const int o0   = blockIdx.x * 128;

    const int rp   = lane & 7;
    const int sel  = lane >> 3;
    const int arow = ((sel & 1) << 3) + rp;
    const int acol = (sel >> 1) << 2;
    const int brow = ((sel >> 1) << 3) + rp;
    const int bcol = (sel & 1) << 2;

    if (tid < 128) {
        int o = o0 + tid;
        float c = (o < O) ? counts[o] : 1.f;
        c = fminf(fmaxf(c, 1.f), 1000.f);
        invc[tid] = 1.f / c;
    }

    auto stageW = [&](const __half* src) {
        const uint4* s = (const uint4*)src;
#pragma unroll
        for (int p = 0; p < 8; p++) {
            int idx = p * 256 + tid;
            int n = idx >> 4, c = idx & 15;
            *(uint4*)(Wu + n * PADK + c * 4) = s[idx];
        }
    };

    stageW(wt + 6 * 16384);                // w2a^T
    __syncthreads();

#pragma unroll
    for (int p = 0; p < 16; p++) {
        int idx = p * 256 + tid;
        int r = idx >> 5, c4 = idx & 31;
        int o = o0 + r;
        float4 v = make_float4(0.f, 0.f, 0.f, 0.f);
        if (o < O) v = *(const float4*)(pooled + (size_t)o * 128 + c4 * 4);
        float s = invc[r];
        *(uint2*)(As + r * PADK + c4 * 2) =
            make_uint2(pk2(v.x * s, v.y * s), pk2(v.z * s, v.w * s));
    }
    __syncthreads();

    float acc[2][8][4];
    ZERO_ACC8(acc);
    MMA_KLOOP(As, Wu, acc, R0, C0, arow, acol, brow, bcol);
    __syncthreads();

#pragma unroll
    for (int mi = 0; mi < 2; mi++) {
        int ra = R0 + mi * 16 + g;
        int rb = ra + 8;
#pragma unroll
        for (int ni = 0; ni < 8; ni++) {
            int c = C0 + ni * 8 + 2 * tg;
            float2 bv = *(const float2*)(b2a + c);
            As[ra * PADK + (c >> 1)] = pk2(fmaxf(acc[mi][ni][0] + bv.x, 0.f),
                                           fmaxf(acc[mi][ni][1] + bv.y, 0.f));
            As[rb * PADK + (c >> 1)] = pk2(fmaxf(acc[mi][ni][2] + bv.x, 0.f),
                                           fmaxf(acc[mi][ni][3] + bv.y, 0.f));
        }
    }
    stageW(wt + 7 * 16384);
    __syncthreads();

    ZERO_ACC8(acc);
    MMA_KLOOP(As, Wu, acc, R0, C0, arow, acol, brow, bcol);
#pragma unroll
    for (int mi = 0; mi < 2; mi++) {
        int ra = R0 + mi * 16 + g;
        int rb = ra + 8;
        int oa = o0 + ra, ob = o0 + rb;
#pragma unroll
        for (int ni = 0; ni < 8; ni++) {
            int cb = C0 + ni * 8;
            float2 bv = *(const float2*)(b2b + cb + 2 * tg);
            float p0 = fmaxf(acc[mi][ni][0] + bv.x, 0.f);
            float p1 = fmaxf(acc[mi][ni][1] + bv.y, 0.f);
            float q0 = fmaxf(acc[mi][ni][2] + bv.x, 0.f);
            float q1 = fmaxf(acc[mi][ni][3] + bv.y, 0.f);
            float pp0 = __shfl_xor_sync(0xFFFFFFFF, p0, 1);
            float pp1 = __shfl_xor_sync(0xFFFFFFFF, p1, 1);
            float qq0 = __shfl_xor_sync(0xFFFFFFFF, q0, 1);
            float qq1 = __shfl_xor_sync(0xFFFFFFFF, q1, 1);
            if (!(tg & 1)) {
                if (oa < O)
                    *(float4*)(outO + (size_t)oa * 128 + cb + 2 * tg) =
                        make_float4(p0, p1, pp0, pp1);
            } else {
                if (ob < O)
                    *(float4*)(outO + (size_t)ob * 128 + cb + 2 * (tg - 1)) =
                        make_float4(qq0, qq1, q0, q1);
            }
        }
    }
}

// ================= launch =================
extern "C" void kernel_launch(void* const* d_in, const int* in_sizes, int n_in,
                              void* d_out, int out_size)
{
    const float* obj   = (const float*)d_in[0];
    const float* predi = (const float*)d_in[1];
    const int*   edges = (const int*)d_in[2];
    const float* w1a   = (const float*)d_in[3];
    const float* b1a   = (const float*)d_in[4];
    const float* w1b   = (const float*)d_in[5];
    const float* b1b   = (const float*)d_in[6];
    const float* w2a   = (const float*)d_in[7];
    const float* b2a   = (const float*)d_in[8];
    const float* w2b   = (const float*)d_in[9];
    const float* b2b   = (const float*)d_in[10];

    const int O = in_sizes[0] / 128;
    const int T = in_sizes[1] / 128;

    float* outO = (float*)d_out;
    float* outP = outO + (size_t)O * 128;

    float *pooled = nullptr, *counts = nullptr;
    __half *proj = nullptr, *wt = nullptr;
    cudaGetSymbolAddress((void**)&pooled, g_pooled);
    cudaGetSymbolAddress((void**)&counts, g_counts);
    cudaGetSymbolAddress((void**)&proj,   g_proj);
    cudaGetSymbolAddress((void**)&wt,     g_wt);

    cudaMemsetAsync(pooled, 0, (size_t)O * 128 * sizeof(float));
    cudaMemsetAsync(counts, 0, (size_t)O * sizeof(float));

    const size_t smT = (size_t)(MT * PADK + 2 * 128 * PADW2) * 4 + MT * 2 * 4 + 256;
    const size_t smP = (size_t)(3 * 128 * PADK) * 4;
    const size_t smB = (size_t)(2 * 128 * PADK) * 4 + 512;

    cudaFuncSetAttribute(proj_kernel,   cudaFuncAttributeMaxDynamicSharedMemorySize, (int)smP);
    cudaFuncSetAttribute(triple_kernel, cudaFuncAttributeMaxDynamicSharedMemorySize, (int)smT);
    cudaFuncSetAttribute(obj_kernel,    cudaFuncAttributeMaxDynamicSharedMemorySize, (int)smB);

    prep_kernel<<<8, 256>>>(w1a, w1b, w2a, w2b, wt);
    proj_kernel<<<(O + 127) / 128, 256, smP>>>(obj, wt, proj, O);
    triple_kernel<<<(T + MT - 1) / MT, 256, smT>>>(predi, edges, wt, b1a, b1b, proj,
                                                   outP, pooled, counts, T);
    obj_kernel<<<(O + 127) / 128, 256, smB>>>(wt, b2a, b2b, pooled, counts, outO, O);
}

// round 12
// speedup vs baseline: 5.1982x; 1.0863x over previous
#include <cuda_runtime.h>
#include <cuda_fp16.h>
#include <cstdint>
#include <cstddef>

// ---------------- scratch (no allocs allowed) ----------------
#define O_CAP 100000
static __device__ float g_pooled[(size_t)O_CAP * 128];
static __device__ float g_counts[O_CAP];
static __device__ __half g_proj[(size_t)O_CAP * 256];   // half: 50MB -> L2-resident
// 8 pre-transposed half tiles [n=128][k=128]:
// 0,1,2: w1a k-rows [0:128),[128:256),[256:384);  3,4,5: w1b nc 0..2;  6: w2a; 7: w2b
static __device__ __half g_wt[8 * 128 * 128];

#define PADK  68   // As row stride (words): 64 data + 4 pad -> conflict-free, 272B = 17*16
#define PADW2 36   // half-K W row stride (words): 32 data + 4 pad -> conflict-free, 144B = 9*16
#define PADPR 68   // staged proj row stride (words): 64 data + 4 pad, 16B-aligned rows
#define MT    64   // triples per block in triple_kernel

// ---------------- helpers ----------------
__device__ __forceinline__ unsigned pk2(float x, float y) {
    __half2 h = __floats2half2_rn(x, y);
    return *reinterpret_cast<unsigned*>(&h);
}
__device__ __forceinline__ void mma_f16(float c[4], const unsigned a[4], const unsigned b[2]) {
    asm volatile(
        "mma.sync.aligned.m16n8k16.row.col.f32.f16.f16.f32 "
        "{%0,%1,%2,%3},{%4,%5,%6,%7},{%8,%9},{%0,%1,%2,%3};\n"
        : "+f"(c[0]), "+f"(c[1]), "+f"(c[2]), "+f"(c[3])
        : "r"(a[0]), "r"(a[1]), "r"(a[2]), "r"(a[3]), "r"(b[0]), "r"(b[1]));
}
__device__ __forceinline__ void ldsm_x4(unsigned r[4], const unsigned* p) {
    unsigned addr = (unsigned)__cvta_generic_to_shared(p);
    asm volatile("ldmatrix.sync.aligned.m8n8.x4.shared.b16 {%0,%1,%2,%3}, [%4];"
                 : "=r"(r[0]), "=r"(r[1]), "=r"(r[2]), "=r"(r[3]) : "r"(addr));
}
__device__ __forceinline__ void red_add_v4(float* p, float a, float b, float c, float d) {
    asm volatile("red.global.add.v4.f32 [%0], {%1,%2,%3,%4};"
                 :: "l"(p), "f"(a), "f"(b), "f"(c), "f"(d) : "memory");
}
__device__ __forceinline__ void cp16(void* dst, const void* src) {
    unsigned d = (unsigned)__cvta_generic_to_shared(dst);
    asm volatile("cp.async.cg.shared.global [%0], [%1], 16;" :: "r"(d), "l"(src) : "memory");
}
#define CP_COMMIT() asm volatile("cp.async.commit_group;" ::: "memory")
#define CP_WAIT0()  asm volatile("cp.async.wait_group 0;" ::: "memory")

// ================= prep: transpose+convert weights to half [n][k] =================
__global__ void prep_kernel(const float* __restrict__ w1a, const float* __restrict__ w1b,
                            const float* __restrict__ w2a, const float* __restrict__ w2b,
                            __half* __restrict__ wt)
{
    const int t = blockIdx.x;           // 0..7
    const int tid = threadIdx.x;
    for (int p = 0; p < 64; p++) {
        int idx = p * 256 + tid;        // 0..16383
        int n = idx >> 7, k = idx & 127;
        float v;
        if (t < 3)       v = w1a[(size_t)(t * 128 + k) * 128 + n];
        else if (t < 6)  v = w1b[(size_t)k * 384 + (t - 3) * 128 + n];
        else if (t == 6) v = w2a[(size_t)k * 128 + n];
        else             v = w2b[(size_t)k * 128 + n];
        wt[((size_t)t * 128 + n) * 128 + k] = __float2half_rn(v);
    }
}

// ================= Kernel A: triple MLP, 64-row tiles, smem-staged proj =================
__global__ __launch_bounds__(256, 3)
void triple_kernel(const float* __restrict__ predi, const int* __restrict__ edges,
                   const __half* __restrict__ wt,
                   const float* __restrict__ b1a, const float* __restrict__ b1b,
                   const __half* __restrict__ proj,
                   float* __restrict__ outP, float* __restrict__ pooled,
                   float* __restrict__ counts, int T)
{
    extern __shared__ unsigned smu[];
    unsigned* As = smu;                            // MT*PADK
    unsigned* Wb = smu + MT * PADK;                // 2 * 128*PADW2 ; buf0 also stages 64 proj rows (64*PADPR=4352 <= 4608)
    int* sIdx = (int*)(smu + MT * PADK + 2 * 128 * PADW2);
    int* oIdx = sIdx + MT;

    const int tid  = threadIdx.x;
    const int lane = tid & 31;
    const int g    = lane >> 2;
    const int tg   = lane & 3;
    const int w    = tid >> 5;
    const int R0   = (w >> 2) * 32;                // 2 row groups x 32 = 64 rows
    const int C0   = (w & 3) * 32;                 // 4 col groups x 32 = 128 cols
    const int t0   = blockIdx.x * MT;

    // ldmatrix lane addressing
    const int rp   = lane & 7;
    const int sel  = lane >> 3;
    const int arow = ((sel & 1) << 3) + rp;
    const int acol = (sel >> 1) << 2;
    const int brow = ((sel >> 1) << 3) + rp;
    const int bcol = (sel & 1) << 2;

    // cp.async stage: one half-K chunk [128n][32 words] of a weight tile
    auto stageW = [&](int buf, const __half* tile, int half) {
        unsigned* dstBase = Wb + buf * 128 * PADW2;
#pragma unroll
        for (int p = 0; p < 4; p++) {
            int idx = p * 256 + tid;               // 0..1023
            int n = idx >> 3, c8 = idx & 7;
            cp16(dstBase + n * PADW2 + c8 * 4, tile + n * 128 + half * 64 + c8 * 8);
        }
        CP_COMMIT();
    };

    // cp.async stage: 64 proj rows (256B each, coalesced) into Wb buf0 region
    auto stageProj = [&](const int* ridx, int off) {
#pragma unroll
        for (int p = 0; p < 4; p++) {
            int idx = p * 256 + tid;               // 0..1023
            int row = idx >> 4, seg = idx & 15;
            cp16(Wb + row * PADPR + seg * 4,
                 proj + (size_t)ridx[row] * 256 + off + seg * 8);
        }
        CP_COMMIT();
    };

    stageW(0, wt + 1 * 16384, 0);                  // chunk0: GEMM1 half0

    if (tid < MT) {
        int t = t0 + tid;
        int s = 0, o = 0;
        if (t < T) {
            s = edges[2 * t];
            o = edges[2 * t + 1];
            atomicAdd(&counts[s], 1.0f);
            atomicAdd(&counts[o], 1.0f);
        }
        sIdx[tid] = s; oIdx[tid] = o;
    }

    // stage A = half(predi tile): MT rows x 32 float4 = 2048 items
#pragma unroll
    for (int p = 0; p < 8; p++) {
        int idx = p * 256 + tid;
        int r = idx >> 5, c4 = idx & 31;
        int t = t0 + r;
        float4 v = make_float4(0.f, 0.f, 0.f, 0.f);
        if (t < T) v = *(const float4*)(predi + (size_t)t * 128 + c4 * 4);
        *(uint2*)(As + r * PADK + c4 * 2) = make_uint2(pk2(v.x, v.y), pk2(v.z, v.w));
    }
    CP_WAIT0();
    __syncthreads();

    float acc[2][4][4];
#pragma unroll
    for (int mi = 0; mi < 2; mi++)
#pragma unroll
        for (int ni = 0; ni < 4; ni++)
#pragma unroll
            for (int q = 0; q < 4; q++) acc[mi][ni][q] = 0.f;

    // mainloop body for one 32-wide K chunk from buffer b
    auto mmaChunk = [&](int b, int kwA0) {
        const unsigned* Wu = Wb + b * 128 * PADW2;
#pragma unroll
        for (int ks = 0; ks < 4; ks++) {
            const int kwA = kwA0 + ks * 8;
            const int kwB = ks * 8;
            unsigned a[2][4], bb[2][4];
#pragma unroll
            for (int mi = 0; mi < 2; mi++)
                ldsm_x4(a[mi], As + (R0 + mi * 16 + arow) * PADK + kwA + acol);
#pragma unroll
            for (int j = 0; j < 2; j++)
                ldsm_x4(bb[j], Wu + (C0 + j * 16 + brow) * PADW2 + kwB + bcol);
#pragma unroll
            for (int mi = 0; mi < 2; mi++)
#pragma unroll
                for (int ni = 0; ni < 4; ni++)
                    mma_f16(acc[mi][ni], a[mi], &bb[ni >> 1][(ni & 1) * 2]);
        }
    };

    // ---------------- GEMM1 ----------------
    // i=0: MMA chunk0 (buf0); prefetch chunk1 (buf1)
    stageW(1, wt + 1 * 16384, 1);
    mmaChunk(0, 0);
    CP_WAIT0();
    __syncthreads();

    // i=1: MMA chunk1 (buf1); stage proj_s rows into buf0 (chunk0 dead)
    stageProj(sIdx, 0);
    mmaChunk(1, 32);
    CP_WAIT0();
    __syncthreads();

    // phase A: acc += bias + proj_s (smem); overlap chunk2 prefetch into buf1
    stageW(1, wt + 3 * 16384, 0);                  // chunk2 = w1b nc0 half0
#pragma unroll
    for (int mi = 0; mi < 2; mi++) {
        int ra = R0 + mi * 16 + g;
        int rb = ra + 8;
#pragma unroll
        for (int ni = 0; ni < 4; ni++) {
            int c = C0 + ni * 8 + 2 * tg;
            float2 bv = *(const float2*)(b1a + c);
            float2 sa = __half22float2(*(const __half2*)(Wb + ra * PADPR + (c >> 1)));
            float2 sb = __half22float2(*(const __half2*)(Wb + rb * PADPR + (c >> 1)));
            acc[mi][ni][0] += bv.x + sa.x;
            acc[mi][ni][1] += bv.y + sa.y;
            acc[mi][ni][2] += bv.x + sb.x;
            acc[mi][ni][3] += bv.y + sb.y;
        }
    }
    __syncthreads();                               // all warps done reading s-rows
    stageProj(oIdx, 128);                          // o-rows into buf0
    CP_WAIT0();
    __syncthreads();                               // o-rows + chunk2 ready

    // phase B: acc += proj_o; relu; -> As (half)
#pragma unroll
    for (int mi = 0; mi < 2; mi++) {
        int ra = R0 + mi * 16 + g;
        int rb = ra + 8;
#pragma unroll
        for (int ni = 0; ni < 4; ni++) {
            int c = C0 + ni * 8 + 2 * tg;
            float2 oa = __half22float2(*(const __half2*)(Wb + ra * PADPR + (c >> 1)));
            float2 ob = __half22float2(*(const __half2*)(Wb + rb * PADPR + (c >> 1)));
            As[ra * PADK + (c >> 1)] = pk2(fmaxf(acc[mi][ni][0] + oa.x, 0.f),
                                           fmaxf(acc[mi][ni][1] + oa.y, 0.f));
            As[rb * PADK + (c >> 1)] = pk2(fmaxf(acc[mi][ni][2] + ob.x, 0.f),
                                           fmaxf(acc[mi][ni][3] + ob.y, 0.f));
        }
    }
    __syncthreads();                               // As (H) visible to all warps
#pragma unroll
    for (int mi = 0; mi < 2; mi++)
#pragma unroll
        for (int ni = 0; ni < 4; ni++)
#pragma unroll
            for (int q = 0; q < 4; q++) acc[mi][ni][q] = 0.f;

    // ---------------- GEMM2: chunks 2..7 (3 nc x 2 K-halves) ----------------
    for (int i = 2; i < 8; i++) {
        const int b = (i & 1) ^ 1;                 // chunk2->buf1, chunk3->buf0, ...
        if (i < 7)
            stageW(b ^ 1, wt + (size_t)(3 + ((i - 1) >> 1)) * 16384, (i + 1) & 1);
        mmaChunk(b, (i & 1) * 32);
        CP_WAIT0();
        __syncthreads();

        if (i & 1) {
            const int nc = (i - 2) >> 1;
            const int boff = nc * 128;
#pragma unroll
            for (int mi = 0; mi < 2; mi++) {
                int ra = R0 + mi * 16 + g;
                int rb = ra + 8;
                int ta = t0 + ra, tb = t0 + rb;
                float* dA;
                float* dB;
                if (nc == 1) { dA = outP + (size_t)ta * 128; dB = outP + (size_t)tb * 128; }
                else {
                    const int* ridx = nc ? oIdx : sIdx;
                    dA = pooled + (size_t)ridx[ra] * 128;
                    dB = pooled + (size_t)ridx[rb] * 128;
                }
#pragma unroll
                for (int ni = 0; ni < 4; ni++) {
                    int cb = C0 + ni * 8;
                    float2 bv = *(const float2*)(b1b + boff + cb + 2 * tg);
                    float p0 = fmaxf(acc[mi][ni][0] + bv.x, 0.f);
                    float p1 = fmaxf(acc[mi][ni][1] + bv.y, 0.f);
                    float q0 = fmaxf(acc[mi][ni][2] + bv.x, 0.f);
                    float q1 = fmaxf(acc[mi][ni][3] + bv.y, 0.f);
                    float pp0 = __shfl_xor_sync(0xFFFFFFFF, p0, 1);
                    float pp1 = __shfl_xor_sync(0xFFFFFFFF, p1, 1);
                    float qq0 = __shfl_xor_sync(0xFFFFFFFF, q0, 1);
                    float qq1 = __shfl_xor_sync(0xFFFFFFFF, q1, 1);
                    if (nc == 1) {
                        if (!(tg & 1)) {
                            if (ta < T) *(float4*)(dA + cb + 2 * tg) = make_float4(p0, p1, pp0, pp1);
                        } else {
                            if (tb < T) *(float4*)(dB + cb + 2 * (tg - 1)) = make_float4(qq0, qq1, q0, q1);
                        }
                    } else {
                        if (!(tg & 1)) {
                            if (ta < T) red_add_v4(dA + cb + 2 * tg, p0, p1, pp0, pp1);
                        } else {
                            if (tb < T) red_add_v4(dB + cb + 2 * (tg - 1), qq0, qq1, q0, q1);
                        }
                    }
                }
            }
            if (i < 7) {
#pragma unroll
                for (int mi = 0; mi < 2; mi++)
#pragma unroll
                    for (int ni = 0; ni < 4; ni++)
#pragma unroll
                        for (int q = 0; q < 4; q++) acc[mi][ni][q] = 0.f;
            }
        }
    }
}

// ---------------- shared m32n64 mainloop for proj/obj (ldmatrix) ----------------
#define MMA_KLOOP(As, Wu, acc, R0, C0, arow, acol, brow, bcol)                  \
    do {                                                                        \
        _Pragma("unroll")                                                       \
        for (int ks = 0; ks < 8; ks++) {                                        \
            const int kw = ks * 8;                                              \
            unsigned a[2][4], bb[4][4];                                         \
            _Pragma("unroll")                                                   \
            for (int mi = 0; mi < 2; mi++)                                      \
                ldsm_x4(a[mi], (As) + ((R0) + mi * 16 + (arow)) * PADK + kw + (acol)); \
            _Pragma("unroll")                                                   \
            for (int j = 0; j < 4; j++)                                         \
                ldsm_x4(bb[j], (Wu) + ((C0) + j * 16 + (brow)) * PADK + kw + (bcol)); \
            _Pragma("unroll")                                                   \
            for (int mi = 0; mi < 2; mi++)                                      \
                _Pragma("unroll")                                               \
                for (int ni = 0; ni < 8; ni++)                                  \
                    mma_f16(acc[mi][ni], a[mi], &bb[ni >> 1][(ni & 1) * 2]);    \
        }                                                                       \
    } while (0)

#define ZERO_ACC8(acc)                                                          \
    do {                                                                        \
        _Pragma("unroll")                                                       \
        for (int mi = 0; mi < 2; mi++)                                          \
            _Pragma("unroll")                                                   \
            for (int ni = 0; ni < 8; ni++)                                      \
                _Pragma("unroll")                                               \
                for (int q = 0; q < 4; q++) acc[mi][ni][q] = 0.f;               \
    } while (0)

// ================= Kernel P: proj = half(obj @ {w1a_top^T, w1a_bot^T}) =================
__global__ __launch_bounds__(256, 2)
void proj_kernel(const float* __restrict__ obj, const __half* __restrict__ wt,
                 __half* __restrict__ proj, int O)
{
    extern __shared__ unsigned smu[];
    unsigned* As = smu;
    unsigned* Wb = smu + 128 * PADK;

    const int tid  = threadIdx.x;
    const int lane = tid & 31;
    const int g    = lane >> 2;
    const int tg   = lane & 3;
    const int w    = tid >> 5;
    const int R0   = (w >> 1) * 32;
    const int C0   = (w & 1) * 64;
    const int o0   = blockIdx.x * 128;

    const int rp   = lane & 7;
    const int sel  = lane >> 3;
    const int arow = ((sel & 1) << 3) + rp;
    const int acol = (sel >> 1) << 2;
    const int brow = ((sel >> 1) << 3) + rp;
    const int bcol = (sel & 1) << 2;

#pragma unroll
    for (int p = 0; p < 16; p++) {
        int idx = p * 256 + tid;
        int r = idx >> 5, c4 = idx & 31;
        int o = o0 + r;
        float4 v = make_float4(0.f, 0.f, 0.f, 0.f);
        if (o < O) v = *(const float4*)(obj + (size_t)o * 128 + c4 * 4);
        *(uint2*)(As + r * PADK + c4 * 2) = make_uint2(pk2(v.x, v.y), pk2(v.z, v.w));
    }

    auto stageW = [&](int buf, const __half* src) {
        unsigned* d = Wb + buf * 128 * PADK;
        const uint4* s = (const uint4*)src;
#pragma unroll
        for (int p = 0; p < 8; p++) {
            int idx = p * 256 + tid;
            int n = idx >> 4, c = idx & 15;
            *(uint4*)(d + n * PADK + c * 4) = s[idx];
        }
    };

    stageW(0, wt);                         // tile 0 = w1a_top^T
    __syncthreads();
    stageW(1, wt + 2 * 16384);             // tile 2 = w1a_bot^T

    float acc[2][8][4];
    for (int m = 0; m < 2; m++) {
        ZERO_ACC8(acc);
        const unsigned* Wu = Wb + m * 128 * PADK;
        MMA_KLOOP(As, Wu, acc, R0, C0, arow, acol, brow, bcol);
#pragma unroll
        for (int mi = 0; mi < 2; mi++) {
            int ra = R0 + mi * 16 + g;
            int rb = ra + 8;
            int oa = o0 + ra, ob = o0 + rb;
#pragma unroll
            for (int ni = 0; ni < 8; ni++) {
                int cb = C0 + ni * 8;
                float p0 = acc[mi][ni][0], p1 = acc[mi][ni][1];
                float q0 = acc[mi][ni][2], q1 = acc[mi][ni][3];
                float pp0 = __shfl_xor_sync(0xFFFFFFFF, p0, 1);
                float pp1 = __shfl_xor_sync(0xFFFFFFFF, p1, 1);
                float qq0 = __shfl_xor_sync(0xFFFFFFFF, q0, 1);
                float qq1 = __shfl_xor_sync(0xFFFFFFFF, q1, 1);
                if (!(tg & 1)) {
                    if (oa < O)
                        *(uint2*)(proj + (size_t)oa * 256 + m * 128 + cb + 2 * tg) =
                            make_uint2(pk2(p0, p1), pk2(pp0, pp1));
                } else {
                    if (ob < O)
                        *(uint2*)(proj + (size_t)ob * 256 + m * 128 + cb + 2 * (tg - 1)) =
                            make_uint2(pk2(qq0, qq1), pk2(q0, q1));
                }
            }
        }
        __syncthreads();
    }
}

// ================= Kernel B: object MLP (fp16 MMA) =================
__global__ __launch_bounds__(256, 2)
void obj_kernel(const __half* __restrict__ wt,
                const float* __restrict__ b2a, const float* __restrict__ b2b,
                const float* __restrict__ pooled, const float* __restrict__ counts,
                float* __restrict__ outO, int O)
{
    extern __shared__ unsigned smu[];
    unsigned* As = smu;
    unsigned* Wu = smu + 128 * PADK;
    float* invc = (float*)(smu + 2 * 128 * PADK);

    const int tid  = threadIdx.x;
    const int lane = tid & 31;
    const int g    = lane >> 2;
    const int tg   = lane & 3;
    const int w    = tid >> 5;
    const int R0   = (w >> 1) * 32;
    const int C0   = (w & 1) * 64;
    const int o0   = blockIdx.x * 128;

    const int rp   = lane & 7;
    const int sel  = lane >> 3;
    const int arow = ((sel & 1) << 3) + rp;
    const int acol = (sel >> 1) << 2;
    const int brow = ((sel >> 1) << 3) + rp;
    const int bcol = (sel & 1) << 2;

    if (tid < 128) {
        int o = o0 + tid;
        float c = (o < O) ? counts[o] : 1.f;
        c = fminf(fmaxf(c, 1.f), 1000.f);
        invc[tid] = 1.f / c;
    }

    auto stageW = [&](const __half* src) {
        const uint4* s = (const uint4*)src;
#pragma unroll
        for (int p = 0; p < 8; p++) {
            int idx = p * 256 + tid;
            int n = idx >> 4, c = idx & 15;
            *(uint4*)(Wu + n * PADK + c * 4) = s[idx];
        }
    };

    stageW(wt + 6 * 16384);                // w2a^T
    __syncthreads();

#pragma unroll
    for (int p = 0; p < 16; p++) {
        int idx = p * 256 + tid;
        int r = idx >> 5, c4 = idx & 31;
        int o = o0 + r;
        float4 v = make_float4(0.f, 0.f, 0.f, 0.f);
        if (o < O) v = *(const float4*)(pooled + (size_t)o * 128 + c4 * 4);
        float s = invc[r];
        *(uint2*)(As + r * PADK + c4 * 2) =
            make_uint2(pk2(v.x * s, v.y * s), pk2(v.z * s, v.w * s));
    }
    __syncthreads();

    float acc[2][8][4];
    ZERO_ACC8(acc);
    MMA_KLOOP(As, Wu, acc, R0, C0, arow, acol, brow, bcol);
    __syncthreads();

#pragma unroll
    for (int mi = 0; mi < 2; mi++) {
        int ra = R0 + mi * 16 + g;
        int rb = ra + 8;
#pragma unroll
        for (int ni = 0; ni < 8; ni++) {
            int c = C0 + ni * 8 + 2 * tg;
            float2 bv = *(const float2*)(b2a + c);
            As[ra * PADK + (c >> 1)] = pk2(fmaxf(acc[mi][ni][0] + bv.x, 0.f),
                                           fmaxf(acc[mi][ni][1] + bv.y, 0.f));
            As[rb * PADK + (c >> 1)] = pk2(fmaxf(acc[mi][ni][2] + bv.x, 0.f),
                                           fmaxf(acc[mi][ni][3] + bv.y, 0.f));
        }
    }
    stageW(wt + 7 * 16384);
    __syncthreads();

    ZERO_ACC8(acc);
    MMA_KLOOP(As, Wu, acc, R0, C0, arow, acol, brow, bcol);
#pragma unroll
    for (int mi = 0; mi < 2; mi++) {
        int ra = R0 + mi * 16 + g;
        int rb = ra + 8;
        int oa = o0 + ra, ob = o0 + rb;
#pragma unroll
        for (int ni = 0; ni < 8; ni++) {
            int cb = C0 + ni * 8;
            float2 bv = *(const float2*)(b2b + cb + 2 * tg);
            float p0 = fmaxf(acc[mi][ni][0] + bv.x, 0.f);
            float p1 = fmaxf(acc[mi][ni][1] + bv.y, 0.f);
            float q0 = fmaxf(acc[mi][ni][2] + bv.x, 0.f);
            float q1 = fmaxf(acc[mi][ni][3] + bv.y, 0.f);
            float pp0 = __shfl_xor_sync(0xFFFFFFFF, p0, 1);
            float pp1 = __shfl_xor_sync(0xFFFFFFFF, p1, 1);
            float qq0 = __shfl_xor_sync(0xFFFFFFFF, q0, 1);
            float qq1 = __shfl_xor_sync(0xFFFFFFFF, q1, 1);
            if (!(tg & 1)) {
                if (oa < O)
                    *(float4*)(outO + (size_t)oa * 128 + cb + 2 * tg) =
                        make_float4(p0, p1, pp0, pp1);
            } else {
                if (ob < O)
                    *(float4*)(outO + (size_t)ob * 128 + cb + 2 * (tg - 1)) =
                        make_float4(qq0, qq1, q0, q1);
            }
        }
    }
}

// ================= launch =================
extern "C" void kernel_launch(void* const* d_in, const int* in_sizes, int n_in,
                              void* d_out, int out_size)
{
    const float* obj   = (const float*)d_in[0];
    const float* predi = (const float*)d_in[1];
    const int*   edges = (const int*)d_in[2];
    const float* w1a   = (const float*)d_in[3];
    const float* b1a   = (const float*)d_in[4];
    const float* w1b   = (const float*)d_in[5];
    const float* b1b   = (const float*)d_in[6];
    const float* w2a   = (const float*)d_in[7];
    const float* b2a   = (const float*)d_in[8];
    const float* w2b   = (const float*)d_in[9];
    const float* b2b   = (const float*)d_in[10];

    const int O = in_sizes[0] / 128;
    const int T = in_sizes[1] / 128;

    float* outO = (float*)d_out;
    float* outP = outO + (size_t)O * 128;

    float *pooled = nullptr, *counts = nullptr;
    __half *proj = nullptr, *wt = nullptr;
    cudaGetSymbolAddress((void**)&pooled, g_pooled);
    cudaGetSymbolAddress((void**)&counts, g_counts);
    cudaGetSymbolAddress((void**)&proj,   g_proj);
    cudaGetSymbolAddress((void**)&wt,     g_wt);

    cudaMemsetAsync(pooled, 0, (size_t)O * 128 * sizeof(float));
    cudaMemsetAsync(counts, 0, (size_t)O * sizeof(float));

    const size_t smT = (size_t)(MT * PADK + 2 * 128 * PADW2) * 4 + MT * 2 * 4 + 256;
    const size_t smP = (size_t)(3 * 128 * PADK) * 4;
    const size_t smB = (size_t)(2 * 128 * PADK) * 4 + 512;

    cudaFuncSetAttribute(proj_kernel,   cudaFuncAttributeMaxDynamicSharedMemorySize, (int)smP);
    cudaFuncSetAttribute(triple_kernel, cudaFuncAttributeMaxDynamicSharedMemorySize, (int)smT);
    cudaFuncSetAttribute(obj_kernel,    cudaFuncAttributeMaxDynamicSharedMemorySize, (int)smB);

    prep_kernel<<<8, 256>>>(w1a, w1b, w2a, w2b, wt);
    proj_kernel<<<(O + 127) / 128, 256, smP>>>(obj, wt, proj, O);
    triple_kernel<<<(T + MT - 1) / MT, 256, smT>>>(predi, edges, wt, b1a, b1b, proj,
                                                   outP, pooled, counts, T);
    obj_kernel<<<(O + 127) / 128, 256, smB>>>(wt, b2a, b2b, pooled, counts, outO, O);
}